// round 1
// baseline (speedup 1.0000x reference)
#include <cuda_runtime.h>
#include <math.h>

// Problem constants
#define BATCH   2
#define SEQ     2048
#define DMODEL  2048
#define NH      32
#define NKV     8
#define HD      64
#define QPOS    (NH * HD)            // 2048
#define KVPOS   (NKV * HD)           // 512
#define OPS     (QPOS + 2 * KVPOS)   // 3072
#define ATTN_SCALE 0.125f            // 64^-0.5

// Scratch (device globals: allocation-guard safe)
__device__ float g_qkv[BATCH * SEQ * OPS];      // [B*L, 3072]
__device__ float g_att[BATCH * SEQ * QPOS];     // [B*L, 2048]

// ---------------------------------------------------------------------------
// GEMM: C[M,N] = A[M,K] * B[N,K]^T   (both A and B are K-contiguous row-major)
// Tiles: BM=64, BN=64, BK=32. 256 threads, each computes a 4x4 microtile.
// ---------------------------------------------------------------------------
__global__ void __launch_bounds__(256)
gemm_abt_kernel(const float* __restrict__ A, const float* __restrict__ B,
                float* __restrict__ C, int M, int N, int K)
{
    const int BM = 64, BN = 64, BK = 32;
    __shared__ float As[BK][BM + 4];   // row stride 68 floats = 272B (16B aligned)
    __shared__ float Bs[BK][BN + 4];

    const int tid = threadIdx.x;
    const int tx  = tid & 15;          // 0..15 -> n microtile
    const int ty  = tid >> 4;          // 0..15 -> m microtile
    const int bm  = blockIdx.y * BM;
    const int bn  = blockIdx.x * BN;

    const int lk = tid & 31;           // k index within tile (coalesced gmem)
    const int lr = tid >> 5;           // row group 0..7

    float acc[4][4];
#pragma unroll
    for (int i = 0; i < 4; i++)
#pragma unroll
        for (int j = 0; j < 4; j++) acc[i][j] = 0.f;

    for (int k0 = 0; k0 < K; k0 += BK) {
        // Load A tile (64x32) and B tile (64x32), transposed into smem
#pragma unroll
        for (int r = 0; r < BM; r += 8) {
            As[lk][r + lr] = A[(size_t)(bm + r + lr) * K + k0 + lk];
            Bs[lk][r + lr] = B[(size_t)(bn + r + lr) * K + k0 + lk];
        }
        __syncthreads();

#pragma unroll
        for (int k = 0; k < BK; k++) {
            float4 a = *(const float4*)&As[k][ty * 4];
            float4 b = *(const float4*)&Bs[k][tx * 4];
            acc[0][0] += a.x * b.x; acc[0][1] += a.x * b.y; acc[0][2] += a.x * b.z; acc[0][3] += a.x * b.w;
            acc[1][0] += a.y * b.x; acc[1][1] += a.y * b.y; acc[1][2] += a.y * b.z; acc[1][3] += a.y * b.w;
            acc[2][0] += a.z * b.x; acc[2][1] += a.z * b.y; acc[2][2] += a.z * b.z; acc[2][3] += a.z * b.w;
            acc[3][0] += a.w * b.x; acc[3][1] += a.w * b.y; acc[3][2] += a.w * b.z; acc[3][3] += a.w * b.w;
        }
        __syncthreads();
    }

#pragma unroll
    for (int i = 0; i < 4; i++) {
        float4 v = make_float4(acc[i][0], acc[i][1], acc[i][2], acc[i][3]);
        *(float4*)&C[(size_t)(bm + ty * 4 + i) * N + bn + tx * 4] = v;
    }
}

// ---------------------------------------------------------------------------
// RoPE in-place on g_qkv for Q heads (32) and K heads (8).
// One thread per (b, l, head, pair-index i<32).
// ---------------------------------------------------------------------------
__global__ void rope_kernel()
{
    const int total = BATCH * SEQ * (NH + NKV) * (HD / 2);
    int idx = blockIdx.x * blockDim.x + threadIdx.x;
    if (idx >= total) return;

    int i    = idx & 31;
    int rest = idx >> 5;
    int h    = rest % (NH + NKV);
    int bl   = rest / (NH + NKV);
    int l    = bl % SEQ;

    int off = (h < NH) ? h * HD : QPOS + (h - NH) * HD;

    float inv_freq = powf(10000.0f, -(float)(2 * i) / (float)HD);
    float ang = (float)l * inv_freq;
    float s, c;
    sincosf(ang, &s, &c);   // accurate range reduction

    float* p = g_qkv + (size_t)bl * OPS + off;
    float t1 = p[i];
    float t2 = p[i + 32];
    p[i]      = t1 * c - t2 * s;
    p[i + 32] = t2 * c + t1 * s;
}

// ---------------------------------------------------------------------------
// Causal GQA flash attention, fp32.
// grid = (SEQ/BQ, NH, BATCH), block = 128 threads.
// Each thread owns one query row: q[64] + o[64] accumulators in registers.
// Keys/values staged 32 rows at a time in shared memory.
// ---------------------------------------------------------------------------
__global__ void __launch_bounds__(128)
attn_kernel()
{
    const int BQ = 128, BK = 32;
    __shared__ float Ks[BK][HD + 4];   // pad to 68 floats: 16B-aligned rows
    __shared__ float Vs[BK][HD + 4];

    const int tid  = threadIdx.x;
    const int q0   = blockIdx.x * BQ;
    const int h    = blockIdx.y;
    const int b    = blockIdx.z;
    const int kvh  = h / (NH / NKV);
    const int qrow = q0 + tid;

    // Load my query row into registers
    const float* qptr = g_qkv + (size_t)(b * SEQ + qrow) * OPS + h * HD;
    float4 q[16];
#pragma unroll
    for (int i = 0; i < 16; i++) q[i] = *(const float4*)(qptr + 4 * i);

    float4 o[16];
#pragma unroll
    for (int i = 0; i < 16; i++) o[i] = make_float4(0.f, 0.f, 0.f, 0.f);

    float m = -1e30f, lsum = 0.f;

    const float* kbase = g_qkv + (size_t)(b * SEQ) * OPS + QPOS + kvh * HD;
    const float* vbase = kbase + KVPOS;

    const int kend = q0 + BQ;   // causal bound for this block

    for (int kt = 0; kt < kend; kt += BK) {
        __syncthreads();
        // Load K/V tile: 32 rows x 64 floats each; 4 threads per row
        {
            int row = tid >> 2;
            int seg = (tid & 3) * 16;
            const float* kr = kbase + (size_t)(kt + row) * OPS + seg;
            const float* vr = vbase + (size_t)(kt + row) * OPS + seg;
#pragma unroll
            for (int i = 0; i < 4; i++) {
                *(float4*)&Ks[row][seg + 4 * i] = *(const float4*)(kr + 4 * i);
                *(float4*)&Vs[row][seg + 4 * i] = *(const float4*)(vr + 4 * i);
            }
        }
        __syncthreads();

        // Scores for 32 keys
        float s[BK];
        float tmax = -1e30f;
#pragma unroll
        for (int j = 0; j < BK; j++) {
            const float4* kj = (const float4*)&Ks[j][0];
            float4 a = make_float4(0.f, 0.f, 0.f, 0.f);
#pragma unroll
            for (int d = 0; d < 16; d++) {
                float4 kv = kj[d];
                a.x += q[d].x * kv.x; a.y += q[d].y * kv.y;
                a.z += q[d].z * kv.z; a.w += q[d].w * kv.w;
            }
            float sj = ((a.x + a.y) + (a.z + a.w)) * ATTN_SCALE;
            if (kt + j > qrow) sj = -1e30f;   // causal mask
            s[j] = sj;
            tmax = fmaxf(tmax, sj);
        }

        // Online softmax update
        float mnew = fmaxf(m, tmax);
        float corr = __expf(m - mnew);
        lsum *= corr;
#pragma unroll
        for (int d = 0; d < 16; d++) {
            o[d].x *= corr; o[d].y *= corr; o[d].z *= corr; o[d].w *= corr;
        }
#pragma unroll
        for (int j = 0; j < BK; j++) {
            float p = __expf(s[j] - mnew);
            lsum += p;
            const float4* vj = (const float4*)&Vs[j][0];
#pragma unroll
            for (int d = 0; d < 16; d++) {
                float4 vv = vj[d];
                o[d].x += p * vv.x; o[d].y += p * vv.y;
                o[d].z += p * vv.z; o[d].w += p * vv.w;
            }
        }
        m = mnew;
    }

    // Normalize and write out in [b, l, h*64+d] layout
    float inv = 1.f / lsum;
    float* op = g_att + (size_t)(b * SEQ + qrow) * QPOS + h * HD;
#pragma unroll
    for (int d = 0; d < 16; d++) {
        float4 r = o[d];
        r.x *= inv; r.y *= inv; r.z *= inv; r.w *= inv;
        *(float4*)(op + 4 * d) = r;
    }
}

// ---------------------------------------------------------------------------
// kernel_launch: x -> qkv GEMM -> RoPE -> attention -> out GEMM
// Inputs: d_in[0]=x [B,L,D], d_in[1]=Wqkv [3072,2048], d_in[2]=Wo [2048,2048]
// Output: [B,L,D] fp32
// ---------------------------------------------------------------------------
extern "C" void kernel_launch(void* const* d_in, const int* in_sizes, int n_in,
                              void* d_out, int out_size)
{
    const float* x    = (const float*)d_in[0];
    const float* Wqkv = (const float*)d_in[1];
    const float* Wo   = (const float*)d_in[2];
    float* out        = (float*)d_out;

    float* qkv;
    float* att;
    cudaGetSymbolAddress((void**)&qkv, g_qkv);
    cudaGetSymbolAddress((void**)&att, g_att);

    const int M = BATCH * SEQ;   // 4096

    // 1) QKV projection: [4096,2048] x [3072,2048]^T -> [4096,3072]
    {
        dim3 grid(OPS / 64, M / 64);
        gemm_abt_kernel<<<grid, 256>>>(x, Wqkv, qkv, M, OPS, DMODEL);
    }

    // 2) RoPE on q and k
    {
        int total = BATCH * SEQ * (NH + NKV) * (HD / 2);
        rope_kernel<<<(total + 255) / 256, 256>>>();
    }

    // 3) Causal GQA attention
    {
        dim3 grid(SEQ / 128, NH, BATCH);
        attn_kernel<<<grid, 128>>>();
    }

    // 4) Output projection: [4096,2048] x [2048,2048]^T -> [4096,2048]
    {
        dim3 grid(DMODEL / 64, M / 64);
        gemm_abt_kernel<<<grid, 256>>>(att, Wo, out, M, DMODEL, DMODEL);
    }
}

// round 2
// speedup vs baseline: 1.0055x; 1.0055x over previous
#include <cuda_runtime.h>
#include <math.h>

// Problem constants
#define BATCH   2
#define SEQ     2048
#define DMODEL  2048
#define NH      32
#define NKV     8
#define HD      64
#define QPOS    (NH * HD)            // 2048
#define KVPOS   (NKV * HD)           // 512
#define OPS     (QPOS + 2 * KVPOS)   // 3072
#define ATTN_SCALE 0.125f            // 64^-0.5

// Scratch (device globals: allocation-guard safe)
__device__ float g_qkv[BATCH * SEQ * OPS];      // [B*L, 3072]
__device__ float g_att[BATCH * SEQ * QPOS];     // [B*L, 2048]

// ---------------------------------------------------------------------------
// GEMM: C[M,N] = A[M,K] * B[N,K]^T   (both A and B are K-contiguous row-major)
// Tiles: BM=64, BN=64, BK=32. 256 threads, each computes a 4x4 microtile.
// ---------------------------------------------------------------------------
__global__ void __launch_bounds__(256)
gemm_abt_kernel(const float* __restrict__ A, const float* __restrict__ B,
                float* __restrict__ C, int M, int N, int K)
{
    const int BM = 64, BN = 64, BK = 32;
    __shared__ float As[BK][BM + 4];   // row stride 68 floats = 272B (16B aligned)
    __shared__ float Bs[BK][BN + 4];

    const int tid = threadIdx.x;
    const int tx  = tid & 15;          // 0..15 -> n microtile
    const int ty  = tid >> 4;          // 0..15 -> m microtile
    const int bm  = blockIdx.y * BM;
    const int bn  = blockIdx.x * BN;

    const int lk = tid & 31;           // k index within tile (coalesced gmem)
    const int lr = tid >> 5;           // row group 0..7

    float acc[4][4];
#pragma unroll
    for (int i = 0; i < 4; i++)
#pragma unroll
        for (int j = 0; j < 4; j++) acc[i][j] = 0.f;

    for (int k0 = 0; k0 < K; k0 += BK) {
        // Load A tile (64x32) and B tile (64x32), transposed into smem
#pragma unroll
        for (int r = 0; r < BM; r += 8) {
            As[lk][r + lr] = A[(size_t)(bm + r + lr) * K + k0 + lk];
            Bs[lk][r + lr] = B[(size_t)(bn + r + lr) * K + k0 + lk];
        }
        __syncthreads();

#pragma unroll
        for (int k = 0; k < BK; k++) {
            float4 a = *(const float4*)&As[k][ty * 4];
            float4 b = *(const float4*)&Bs[k][tx * 4];
            acc[0][0] += a.x * b.x; acc[0][1] += a.x * b.y; acc[0][2] += a.x * b.z; acc[0][3] += a.x * b.w;
            acc[1][0] += a.y * b.x; acc[1][1] += a.y * b.y; acc[1][2] += a.y * b.z; acc[1][3] += a.y * b.w;
            acc[2][0] += a.z * b.x; acc[2][1] += a.z * b.y; acc[2][2] += a.z * b.z; acc[2][3] += a.z * b.w;
            acc[3][0] += a.w * b.x; acc[3][1] += a.w * b.y; acc[3][2] += a.w * b.z; acc[3][3] += a.w * b.w;
        }
        __syncthreads();
    }

#pragma unroll
    for (int i = 0; i < 4; i++) {
        float4 v = make_float4(acc[i][0], acc[i][1], acc[i][2], acc[i][3]);
        *(float4*)&C[(size_t)(bm + ty * 4 + i) * N + bn + tx * 4] = v;
    }
}

// ---------------------------------------------------------------------------
// RoPE in-place on g_qkv for Q heads (32) and K heads (8).
// One thread per (b, l, head, pair-index i<32).
// ---------------------------------------------------------------------------
__global__ void rope_kernel()
{
    const int total = BATCH * SEQ * (NH + NKV) * (HD / 2);
    int idx = blockIdx.x * blockDim.x + threadIdx.x;
    if (idx >= total) return;

    int i    = idx & 31;
    int rest = idx >> 5;
    int h    = rest % (NH + NKV);
    int bl   = rest / (NH + NKV);
    int l    = bl % SEQ;

    int off = (h < NH) ? h * HD : QPOS + (h - NH) * HD;

    float inv_freq = powf(10000.0f, -(float)(2 * i) / (float)HD);
    float ang = (float)l * inv_freq;
    float s, c;
    sincosf(ang, &s, &c);   // accurate range reduction

    float* p = g_qkv + (size_t)bl * OPS + off;
    float t1 = p[i];
    float t2 = p[i + 32];
    p[i]      = t1 * c - t2 * s;
    p[i + 32] = t2 * c + t1 * s;
}

// ---------------------------------------------------------------------------
// Causal GQA flash attention, fp32.
// grid = (SEQ/BQ, NH, BATCH), block = 128 threads.
// Each thread owns one query row: q[64] + o[64] accumulators in registers.
// Keys/values staged 32 rows at a time in shared memory.
// ---------------------------------------------------------------------------
__global__ void __launch_bounds__(128)
attn_kernel()
{
    const int BQ = 128, BK = 32;
    __shared__ float Ks[BK][HD + 4];   // pad to 68 floats: 16B-aligned rows
    __shared__ float Vs[BK][HD + 4];

    const int tid  = threadIdx.x;
    const int q0   = blockIdx.x * BQ;
    const int h    = blockIdx.y;
    const int b    = blockIdx.z;
    const int kvh  = h / (NH / NKV);
    const int qrow = q0 + tid;

    // Load my query row into registers
    const float* qptr = g_qkv + (size_t)(b * SEQ + qrow) * OPS + h * HD;
    float4 q[16];
#pragma unroll
    for (int i = 0; i < 16; i++) q[i] = *(const float4*)(qptr + 4 * i);

    float4 o[16];
#pragma unroll
    for (int i = 0; i < 16; i++) o[i] = make_float4(0.f, 0.f, 0.f, 0.f);

    float m = -1e30f, lsum = 0.f;

    const float* kbase = g_qkv + (size_t)(b * SEQ) * OPS + QPOS + kvh * HD;
    const float* vbase = kbase + KVPOS;

    const int kend = q0 + BQ;   // causal bound for this block

    for (int kt = 0; kt < kend; kt += BK) {
        __syncthreads();
        // Load K/V tile: 32 rows x 64 floats each; 4 threads per row
        {
            int row = tid >> 2;
            int seg = (tid & 3) * 16;
            const float* kr = kbase + (size_t)(kt + row) * OPS + seg;
            const float* vr = vbase + (size_t)(kt + row) * OPS + seg;
#pragma unroll
            for (int i = 0; i < 4; i++) {
                *(float4*)&Ks[row][seg + 4 * i] = *(const float4*)(kr + 4 * i);
                *(float4*)&Vs[row][seg + 4 * i] = *(const float4*)(vr + 4 * i);
            }
        }
        __syncthreads();

        // Scores for 32 keys
        float s[BK];
        float tmax = -1e30f;
#pragma unroll
        for (int j = 0; j < BK; j++) {
            const float4* kj = (const float4*)&Ks[j][0];
            float4 a = make_float4(0.f, 0.f, 0.f, 0.f);
#pragma unroll
            for (int d = 0; d < 16; d++) {
                float4 kv = kj[d];
                a.x += q[d].x * kv.x; a.y += q[d].y * kv.y;
                a.z += q[d].z * kv.z; a.w += q[d].w * kv.w;
            }
            float sj = ((a.x + a.y) + (a.z + a.w)) * ATTN_SCALE;
            if (kt + j > qrow) sj = -1e30f;   // causal mask
            s[j] = sj;
            tmax = fmaxf(tmax, sj);
        }

        // Online softmax update
        float mnew = fmaxf(m, tmax);
        float corr = __expf(m - mnew);
        lsum *= corr;
#pragma unroll
        for (int d = 0; d < 16; d++) {
            o[d].x *= corr; o[d].y *= corr; o[d].z *= corr; o[d].w *= corr;
        }
#pragma unroll
        for (int j = 0; j < BK; j++) {
            float p = __expf(s[j] - mnew);
            lsum += p;
            const float4* vj = (const float4*)&Vs[j][0];
#pragma unroll
            for (int d = 0; d < 16; d++) {
                float4 vv = vj[d];
                o[d].x += p * vv.x; o[d].y += p * vv.y;
                o[d].z += p * vv.z; o[d].w += p * vv.w;
            }
        }
        m = mnew;
    }

    // Normalize and write out in [b, l, h*64+d] layout
    float inv = 1.f / lsum;
    float* op = g_att + (size_t)(b * SEQ + qrow) * QPOS + h * HD;
#pragma unroll
    for (int d = 0; d < 16; d++) {
        float4 r = o[d];
        r.x *= inv; r.y *= inv; r.z *= inv; r.w *= inv;
        *(float4*)(op + 4 * d) = r;
    }
}

// ---------------------------------------------------------------------------
// kernel_launch: x -> qkv GEMM -> RoPE -> attention -> out GEMM
// Inputs: d_in[0]=x [B,L,D], d_in[1]=Wqkv [3072,2048], d_in[2]=Wo [2048,2048]
// Output: [B,L,D] fp32
// ---------------------------------------------------------------------------
extern "C" void kernel_launch(void* const* d_in, const int* in_sizes, int n_in,
                              void* d_out, int out_size)
{
    const float* x    = (const float*)d_in[0];
    const float* Wqkv = (const float*)d_in[1];
    const float* Wo   = (const float*)d_in[2];
    float* out        = (float*)d_out;

    float* qkv;
    float* att;
    cudaGetSymbolAddress((void**)&qkv, g_qkv);
    cudaGetSymbolAddress((void**)&att, g_att);

    const int M = BATCH * SEQ;   // 4096

    // 1) QKV projection: [4096,2048] x [3072,2048]^T -> [4096,3072]
    {
        dim3 grid(OPS / 64, M / 64);
        gemm_abt_kernel<<<grid, 256>>>(x, Wqkv, qkv, M, OPS, DMODEL);
    }

    // 2) RoPE on q and k
    {
        int total = BATCH * SEQ * (NH + NKV) * (HD / 2);
        rope_kernel<<<(total + 255) / 256, 256>>>();
    }

    // 3) Causal GQA attention
    {
        dim3 grid(SEQ / 128, NH, BATCH);
        attn_kernel<<<grid, 128>>>();
    }

    // 4) Output projection: [4096,2048] x [2048,2048]^T -> [4096,2048]
    {
        dim3 grid(DMODEL / 64, M / 64);
        gemm_abt_kernel<<<grid, 256>>>(att, Wo, out, M, DMODEL, DMODEL);
    }
}

// round 4
// speedup vs baseline: 1.5585x; 1.5501x over previous
#include <cuda_runtime.h>
#include <cuda_bf16.h>
#include <math.h>
#include <stdint.h>

// Problem constants
#define BATCH   2
#define SEQ     2048
#define DMODEL  2048
#define NH      32
#define NKV     8
#define HD      64
#define QPOS    (NH * HD)            // 2048
#define KVPOS   (NKV * HD)           // 512
#define OPS     (QPOS + 2 * KVPOS)   // 3072
#define MTOT    (BATCH * SEQ)        // 4096
#define ATTN_SCALE 0.125f

// ---------------------------------------------------------------------------
// Scratch (device globals: allocation-guard safe)
// ---------------------------------------------------------------------------
__device__ float g_qkv[MTOT * OPS];       // [4096, 3072] fp32
__device__ float g_att[MTOT * QPOS];      // [4096, 2048] fp32
__device__ __nv_bfloat16 g_x_hi[MTOT * DMODEL];
__device__ __nv_bfloat16 g_x_lo[MTOT * DMODEL];
__device__ __nv_bfloat16 g_wq_hi[OPS * DMODEL];
__device__ __nv_bfloat16 g_wq_lo[OPS * DMODEL];
__device__ __nv_bfloat16 g_wo_hi[DMODEL * DMODEL];
__device__ __nv_bfloat16 g_wo_lo[DMODEL * DMODEL];
__device__ __nv_bfloat16 g_a_hi[MTOT * QPOS];
__device__ __nv_bfloat16 g_a_lo[MTOT * QPOS];

// ---------------------------------------------------------------------------
// helpers
// ---------------------------------------------------------------------------
__device__ __forceinline__ uint32_t smem_to_u32(const void* p) {
    uint32_t a;
    asm("{ .reg .u64 t; cvta.to.shared.u64 t, %1; cvt.u32.u64 %0, t; }"
        : "=r"(a) : "l"(p));
    return a;
}

__device__ __forceinline__ void cp_async16(uint32_t smem_dst, const void* gmem_src) {
    asm volatile("cp.async.cg.shared.global [%0], [%1], 16;"
                 :: "r"(smem_dst), "l"(gmem_src) : "memory");
}
__device__ __forceinline__ void cp_commit() {
    asm volatile("cp.async.commit_group;" ::: "memory");
}
__device__ __forceinline__ void cp_wait1() {
    asm volatile("cp.async.wait_group 1;" ::: "memory");
}
__device__ __forceinline__ void cp_wait0() {
    asm volatile("cp.async.wait_group 0;" ::: "memory");
}

__device__ __forceinline__ void ldsm_x4(uint32_t& r0, uint32_t& r1,
                                        uint32_t& r2, uint32_t& r3, uint32_t addr) {
    asm volatile("ldmatrix.sync.aligned.m8n8.x4.shared.b16 {%0,%1,%2,%3}, [%4];"
                 : "=r"(r0), "=r"(r1), "=r"(r2), "=r"(r3) : "r"(addr));
}

__device__ __forceinline__ void mma16816(float& d0, float& d1, float& d2, float& d3,
                                         uint32_t a0, uint32_t a1, uint32_t a2, uint32_t a3,
                                         uint32_t b0, uint32_t b1) {
    asm volatile(
        "mma.sync.aligned.m16n8k16.row.col.f32.bf16.bf16.f32 "
        "{%0,%1,%2,%3}, {%4,%5,%6,%7}, {%8,%9}, {%0,%1,%2,%3};"
        : "+f"(d0), "+f"(d1), "+f"(d2), "+f"(d3)
        : "r"(a0), "r"(a1), "r"(a2), "r"(a3), "r"(b0), "r"(b1));
}

// ---------------------------------------------------------------------------
// Split fp32 -> bf16 hi + bf16 lo (residual), vectorized x4
// ---------------------------------------------------------------------------
__global__ void split_bf16_kernel(const float* __restrict__ src,
                                  __nv_bfloat16* __restrict__ hi,
                                  __nv_bfloat16* __restrict__ lo, int n4)
{
    int i = blockIdx.x * blockDim.x + threadIdx.x;
    if (i >= n4) return;
    float4 v = ((const float4*)src)[i];
    __nv_bfloat16 h0 = __float2bfloat16(v.x);
    __nv_bfloat16 h1 = __float2bfloat16(v.y);
    __nv_bfloat16 h2 = __float2bfloat16(v.z);
    __nv_bfloat16 h3 = __float2bfloat16(v.w);
    __nv_bfloat16 l0 = __float2bfloat16(v.x - __bfloat162float(h0));
    __nv_bfloat16 l1 = __float2bfloat16(v.y - __bfloat162float(h1));
    __nv_bfloat16 l2 = __float2bfloat16(v.z - __bfloat162float(h2));
    __nv_bfloat16 l3 = __float2bfloat16(v.w - __bfloat162float(h3));
    __nv_bfloat162* hp = (__nv_bfloat162*)hi;
    __nv_bfloat162* lp = (__nv_bfloat162*)lo;
    hp[2 * i]     = __nv_bfloat162(h0, h1);
    hp[2 * i + 1] = __nv_bfloat162(h2, h3);
    lp[2 * i]     = __nv_bfloat162(l0, l1);
    lp[2 * i + 1] = __nv_bfloat162(l2, l3);
}

// ---------------------------------------------------------------------------
// mma.sync bf16-split GEMM: C[M,N] = (Ahi+Alo)[M,K] * (Bhi+Blo)[N,K]^T, fp32 C.
// Block tile 128x128, K-chunk 32, double-buffered cp.async.
// 256 threads = 8 warps in 4(m) x 2(n); warp tile 32x64.
// 3 combos per k-step: hi*hi + hi*lo + lo*hi.
// ---------------------------------------------------------------------------
#define BKC   32
#define LDSE  40                      // padded row length (elements)
#define LDSB  (LDSE * 2)              // 80 bytes row stride
#define TILE_B (128 * LDSB)           // 10240 bytes per operand tile
#define STAGE_B (4 * TILE_B)          // 40960 bytes per stage
#define GEMM_SMEM (2 * STAGE_B)       // 81920 bytes

__global__ void __launch_bounds__(256)
gemm_mma_split_kernel(const __nv_bfloat16* __restrict__ Ahi,
                      const __nv_bfloat16* __restrict__ Alo,
                      const __nv_bfloat16* __restrict__ Bhi,
                      const __nv_bfloat16* __restrict__ Blo,
                      float* __restrict__ C, int N, int K)
{
    extern __shared__ char smem[];
    const uint32_t sb = smem_to_u32(smem);

    const int tid  = threadIdx.x;
    const int lane = tid & 31;
    const int wid  = tid >> 5;
    const int wm   = wid >> 1;          // 0..3
    const int wn   = wid & 1;           // 0..1
    const int bm   = blockIdx.y * 128;
    const int bn   = blockIdx.x * 128;

    const __nv_bfloat16* aH = Ahi + (size_t)bm * K;
    const __nv_bfloat16* aL = Alo + (size_t)bm * K;
    const __nv_bfloat16* bH = Bhi + (size_t)bn * K;
    const __nv_bfloat16* bL = Blo + (size_t)bn * K;

    // per-thread load mapping: 2 x (row = lin>>2, 16B-chunk c = lin&3)
    const int r0 = tid >> 2;            // rows 0..63
    const int c0 = tid & 3;

    float acc[2][8][4];
#pragma unroll
    for (int i = 0; i < 2; i++)
#pragma unroll
        for (int j = 0; j < 8; j++)
#pragma unroll
            for (int t = 0; t < 4; t++) acc[i][j][t] = 0.f;

    const int iters = K / BKC;

    // ldmatrix base addresses (within a stage, operand-relative)
    const uint32_t a_ld_off =
        (uint32_t)((wm * 32 + (lane & 15)) * LDSB + (lane >> 4) * 16);
    const uint32_t b_ld_off =
        (uint32_t)((wn * 64 + (lane & 7) + ((lane >> 4) << 3)) * LDSB
                   + ((lane >> 3) & 1) * 16);

    auto load_stage = [&](int stage, int k0) {
        uint32_t base = sb + stage * STAGE_B;
#pragma unroll
        for (int i = 0; i < 2; i++) {
            int row = r0 + i * 64;
            int c   = c0;
            uint32_t sofs = (uint32_t)(row * LDSB + c * 16);
            size_t gofs   = (size_t)row * K + k0 + c * 8;
            cp_async16(base + 0 * TILE_B + sofs, aH + gofs);
            cp_async16(base + 1 * TILE_B + sofs, aL + gofs);
            cp_async16(base + 2 * TILE_B + sofs, bH + gofs);
            cp_async16(base + 3 * TILE_B + sofs, bL + gofs);
        }
        cp_commit();
    };

    load_stage(0, 0);

    for (int it = 0; it < iters; ++it) {
        if (it + 1 < iters) {
            load_stage((it + 1) & 1, (it + 1) * BKC);
            cp_wait1();
        } else {
            cp_wait0();
        }
        __syncthreads();

        const uint32_t base = sb + (it & 1) * STAGE_B;
        const uint32_t sAH = base + 0 * TILE_B + a_ld_off;
        const uint32_t sAL = base + 1 * TILE_B + a_ld_off;
        const uint32_t sBH = base + 2 * TILE_B + b_ld_off;
        const uint32_t sBL = base + 3 * TILE_B + b_ld_off;

#pragma unroll
        for (int ks = 0; ks < 2; ks++) {
            const uint32_t kofs = ks * 32;   // 16 bf16 = 32 bytes
            uint32_t ah[2][4], al[2][4], bh[4][4], bl[4][4];
#pragma unroll
            for (int mt = 0; mt < 2; mt++) {
                ldsm_x4(ah[mt][0], ah[mt][1], ah[mt][2], ah[mt][3],
                        sAH + mt * 16 * LDSB + kofs);
                ldsm_x4(al[mt][0], al[mt][1], al[mt][2], al[mt][3],
                        sAL + mt * 16 * LDSB + kofs);
            }
#pragma unroll
            for (int np = 0; np < 4; np++) {
                ldsm_x4(bh[np][0], bh[np][1], bh[np][2], bh[np][3],
                        sBH + np * 16 * LDSB + kofs);
                ldsm_x4(bl[np][0], bl[np][1], bl[np][2], bl[np][3],
                        sBL + np * 16 * LDSB + kofs);
            }
#pragma unroll
            for (int mt = 0; mt < 2; mt++) {
#pragma unroll
                for (int np = 0; np < 4; np++) {
                    // hi * hi
                    mma16816(acc[mt][2*np][0], acc[mt][2*np][1], acc[mt][2*np][2], acc[mt][2*np][3],
                             ah[mt][0], ah[mt][1], ah[mt][2], ah[mt][3], bh[np][0], bh[np][1]);
                    mma16816(acc[mt][2*np+1][0], acc[mt][2*np+1][1], acc[mt][2*np+1][2], acc[mt][2*np+1][3],
                             ah[mt][0], ah[mt][1], ah[mt][2], ah[mt][3], bh[np][2], bh[np][3]);
                    // hi * lo
                    mma16816(acc[mt][2*np][0], acc[mt][2*np][1], acc[mt][2*np][2], acc[mt][2*np][3],
                             ah[mt][0], ah[mt][1], ah[mt][2], ah[mt][3], bl[np][0], bl[np][1]);
                    mma16816(acc[mt][2*np+1][0], acc[mt][2*np+1][1], acc[mt][2*np+1][2], acc[mt][2*np+1][3],
                             ah[mt][0], ah[mt][1], ah[mt][2], ah[mt][3], bl[np][2], bl[np][3]);
                    // lo * hi
                    mma16816(acc[mt][2*np][0], acc[mt][2*np][1], acc[mt][2*np][2], acc[mt][2*np][3],
                             al[mt][0], al[mt][1], al[mt][2], al[mt][3], bh[np][0], bh[np][1]);
                    mma16816(acc[mt][2*np+1][0], acc[mt][2*np+1][1], acc[mt][2*np+1][2], acc[mt][2*np+1][3],
                             al[mt][0], al[mt][1], al[mt][2], al[mt][3], bh[np][2], bh[np][3]);
                }
            }
        }
        __syncthreads();
    }

    // Epilogue: acc -> C
#pragma unroll
    for (int mt = 0; mt < 2; mt++) {
        int row = bm + wm * 32 + mt * 16 + (lane >> 2);
#pragma unroll
        for (int nt = 0; nt < 8; nt++) {
            int col = bn + wn * 64 + nt * 8 + (lane & 3) * 2;
            *(float2*)&C[(size_t)row * N + col] =
                make_float2(acc[mt][nt][0], acc[mt][nt][1]);
            *(float2*)&C[(size_t)(row + 8) * N + col] =
                make_float2(acc[mt][nt][2], acc[mt][nt][3]);
        }
    }
}

// ---------------------------------------------------------------------------
// RoPE in-place on g_qkv for Q heads (32) and K heads (8)
// ---------------------------------------------------------------------------
__global__ void rope_kernel()
{
    const int total = MTOT * (NH + NKV) * (HD / 2);
    int idx = blockIdx.x * blockDim.x + threadIdx.x;
    if (idx >= total) return;

    int i    = idx & 31;
    int rest = idx >> 5;
    int h    = rest % (NH + NKV);
    int bl   = rest / (NH + NKV);
    int l    = bl % SEQ;

    int off = (h < NH) ? h * HD : QPOS + (h - NH) * HD;

    float inv_freq = powf(10000.0f, -(float)(2 * i) / (float)HD);
    float ang = (float)l * inv_freq;
    float s, c;
    sincosf(ang, &s, &c);

    float* p = g_qkv + (size_t)bl * OPS + off;
    float t1 = p[i];
    float t2 = p[i + 32];
    p[i]      = t1 * c - t2 * s;
    p[i + 32] = t2 * c + t1 * s;
}

// ---------------------------------------------------------------------------
// Causal GQA flash attention, fp32 (known-good)
// ---------------------------------------------------------------------------
__global__ void __launch_bounds__(128)
attn_kernel()
{
    const int BQ = 128, BK = 32;
    __shared__ float Ks[BK][HD + 4];
    __shared__ float Vs[BK][HD + 4];

    const int tid  = threadIdx.x;
    const int q0   = blockIdx.x * BQ;
    const int h    = blockIdx.y;
    const int b    = blockIdx.z;
    const int kvh  = h / (NH / NKV);
    const int qrow = q0 + tid;

    const float* qptr = g_qkv + (size_t)(b * SEQ + qrow) * OPS + h * HD;
    float4 q[16];
#pragma unroll
    for (int i = 0; i < 16; i++) q[i] = *(const float4*)(qptr + 4 * i);

    float4 o[16];
#pragma unroll
    for (int i = 0; i < 16; i++) o[i] = make_float4(0.f, 0.f, 0.f, 0.f);

    float m = -1e30f, lsum = 0.f;

    const float* kbase = g_qkv + (size_t)(b * SEQ) * OPS + QPOS + kvh * HD;
    const float* vbase = kbase + KVPOS;

    const int kend = q0 + BQ;

    for (int kt = 0; kt < kend; kt += BK) {
        __syncthreads();
        {
            int row = tid >> 2;
            int seg = (tid & 3) * 16;
            const float* kr = kbase + (size_t)(kt + row) * OPS + seg;
            const float* vr = vbase + (size_t)(kt + row) * OPS + seg;
#pragma unroll
            for (int i = 0; i < 4; i++) {
                *(float4*)&Ks[row][seg + 4 * i] = *(const float4*)(kr + 4 * i);
                *(float4*)&Vs[row][seg + 4 * i] = *(const float4*)(vr + 4 * i);
            }
        }
        __syncthreads();

        float s[BK];
        float tmax = -1e30f;
#pragma unroll
        for (int j = 0; j < BK; j++) {
            const float4* kj = (const float4*)&Ks[j][0];
            float4 a = make_float4(0.f, 0.f, 0.f, 0.f);
#pragma unroll
            for (int d = 0; d < 16; d++) {
                float4 kv = kj[d];
                a.x += q[d].x * kv.x; a.y += q[d].y * kv.y;
                a.z += q[d].z * kv.z; a.w += q[d].w * kv.w;
            }
            float sj = ((a.x + a.y) + (a.z + a.w)) * ATTN_SCALE;
            if (kt + j > qrow) sj = -1e30f;
            s[j] = sj;
            tmax = fmaxf(tmax, sj);
        }

        float mnew = fmaxf(m, tmax);
        float corr = __expf(m - mnew);
        lsum *= corr;
#pragma unroll
        for (int d = 0; d < 16; d++) {
            o[d].x *= corr; o[d].y *= corr; o[d].z *= corr; o[d].w *= corr;
        }
#pragma unroll
        for (int j = 0; j < BK; j++) {
            float p = __expf(s[j] - mnew);
            lsum += p;
            const float4* vj = (const float4*)&Vs[j][0];
#pragma unroll
            for (int d = 0; d < 16; d++) {
                float4 vv = vj[d];
                o[d].x += p * vv.x; o[d].y += p * vv.y;
                o[d].z += p * vv.z; o[d].w += p * vv.w;
            }
        }
        m = mnew;
    }

    float inv = 1.f / lsum;
    float* op = g_att + (size_t)(b * SEQ + qrow) * QPOS + h * HD;
#pragma unroll
    for (int d = 0; d < 16; d++) {
        float4 r = o[d];
        r.x *= inv; r.y *= inv; r.z *= inv; r.w *= inv;
        *(float4*)(op + 4 * d) = r;
    }
}

// ---------------------------------------------------------------------------
// kernel_launch
// ---------------------------------------------------------------------------
extern "C" void kernel_launch(void* const* d_in, const int* in_sizes, int n_in,
                              void* d_out, int out_size)
{
    const float* x    = (const float*)d_in[0];
    const float* Wqkv = (const float*)d_in[1];
    const float* Wo   = (const float*)d_in[2];
    float* out        = (float*)d_out;

    float *qkv, *att;
    __nv_bfloat16 *xh, *xl, *wqh, *wql, *woh, *wol, *ah, *al;
    cudaGetSymbolAddress((void**)&qkv, g_qkv);
    cudaGetSymbolAddress((void**)&att, g_att);
    cudaGetSymbolAddress((void**)&xh,  g_x_hi);
    cudaGetSymbolAddress((void**)&xl,  g_x_lo);
    cudaGetSymbolAddress((void**)&wqh, g_wq_hi);
    cudaGetSymbolAddress((void**)&wql, g_wq_lo);
    cudaGetSymbolAddress((void**)&woh, g_wo_hi);
    cudaGetSymbolAddress((void**)&wol, g_wo_lo);
    cudaGetSymbolAddress((void**)&ah,  g_a_hi);
    cudaGetSymbolAddress((void**)&al,  g_a_lo);

    cudaFuncSetAttribute(gemm_mma_split_kernel,
                         cudaFuncAttributeMaxDynamicSharedMemorySize, GEMM_SMEM);

    // 1) Split inputs to bf16 hi/lo
    {
        int n4 = (MTOT * DMODEL) / 4;
        split_bf16_kernel<<<(n4 + 255) / 256, 256>>>(x, xh, xl, n4);
    }
    {
        int n4 = (OPS * DMODEL) / 4;
        split_bf16_kernel<<<(n4 + 255) / 256, 256>>>(Wqkv, wqh, wql, n4);
    }
    {
        int n4 = (DMODEL * DMODEL) / 4;
        split_bf16_kernel<<<(n4 + 255) / 256, 256>>>(Wo, woh, wol, n4);
    }

    // 2) QKV projection: [4096,2048] x [3072,2048]^T -> [4096,3072]
    {
        dim3 grid(OPS / 128, MTOT / 128);
        gemm_mma_split_kernel<<<grid, 256, GEMM_SMEM>>>(xh, xl, wqh, wql, qkv, OPS, DMODEL);
    }

    // 3) RoPE
    {
        int total = MTOT * (NH + NKV) * (HD / 2);
        rope_kernel<<<(total + 255) / 256, 256>>>();
    }

    // 4) Attention
    {
        dim3 grid(SEQ / 128, NH, BATCH);
        attn_kernel<<<grid, 128>>>();
    }

    // 5) Split attention output, then O-projection
    {
        int n4 = (MTOT * QPOS) / 4;
        split_bf16_kernel<<<(n4 + 255) / 256, 256>>>(att, ah, al, n4);
    }
    {
        dim3 grid(DMODEL / 128, MTOT / 128);
        gemm_mma_split_kernel<<<grid, 256, GEMM_SMEM>>>(ah, al, woh, wol, out, DMODEL, DMODEL);
    }
}

// round 5
// speedup vs baseline: 3.2804x; 2.1048x over previous
#include <cuda_runtime.h>
#include <cuda_bf16.h>
#include <math.h>
#include <stdint.h>

// Problem constants
#define BATCH   2
#define SEQ     2048
#define DMODEL  2048
#define NH      32
#define NKV     8
#define HD      64
#define QPOS    (NH * HD)            // 2048
#define KVPOS   (NKV * HD)           // 512
#define OPS     (QPOS + 2 * KVPOS)   // 3072
#define MTOT    (BATCH * SEQ)        // 4096
#define ATTN_SCALE 0.125f

// ---------------------------------------------------------------------------
// Scratch (device globals: allocation-guard safe)
// ---------------------------------------------------------------------------
__device__ float g_qkv[MTOT * OPS];       // [4096, 3072] fp32
__device__ __nv_bfloat16 g_x_hi[MTOT * DMODEL];
__device__ __nv_bfloat16 g_x_lo[MTOT * DMODEL];
__device__ __nv_bfloat16 g_wq_hi[OPS * DMODEL];
__device__ __nv_bfloat16 g_wq_lo[OPS * DMODEL];
__device__ __nv_bfloat16 g_wo_hi[DMODEL * DMODEL];
__device__ __nv_bfloat16 g_wo_lo[DMODEL * DMODEL];
// per-head-contiguous roped q/k and v, bf16 hi/lo
__device__ __nv_bfloat16 g_qh[BATCH * NH  * SEQ * HD];
__device__ __nv_bfloat16 g_ql[BATCH * NH  * SEQ * HD];
__device__ __nv_bfloat16 g_kh[BATCH * NKV * SEQ * HD];
__device__ __nv_bfloat16 g_kl[BATCH * NKV * SEQ * HD];
__device__ __nv_bfloat16 g_vh[BATCH * NKV * SEQ * HD];
__device__ __nv_bfloat16 g_vl[BATCH * NKV * SEQ * HD];
// attention output, bf16 hi/lo (input to O-proj)
__device__ __nv_bfloat16 g_a_hi[MTOT * QPOS];
__device__ __nv_bfloat16 g_a_lo[MTOT * QPOS];

// ---------------------------------------------------------------------------
// helpers
// ---------------------------------------------------------------------------
__device__ __forceinline__ uint32_t smem_to_u32(const void* p) {
    uint32_t a;
    asm("{ .reg .u64 t; cvta.to.shared.u64 t, %1; cvt.u32.u64 %0, t; }"
        : "=r"(a) : "l"(p));
    return a;
}

__device__ __forceinline__ void cp_async16(uint32_t smem_dst, const void* gmem_src) {
    asm volatile("cp.async.cg.shared.global [%0], [%1], 16;"
                 :: "r"(smem_dst), "l"(gmem_src) : "memory");
}
__device__ __forceinline__ void cp_commit() {
    asm volatile("cp.async.commit_group;" ::: "memory");
}
__device__ __forceinline__ void cp_wait1() {
    asm volatile("cp.async.wait_group 1;" ::: "memory");
}
__device__ __forceinline__ void cp_wait0() {
    asm volatile("cp.async.wait_group 0;" ::: "memory");
}

__device__ __forceinline__ void ldsm_x4(uint32_t& r0, uint32_t& r1,
                                        uint32_t& r2, uint32_t& r3, uint32_t addr) {
    asm volatile("ldmatrix.sync.aligned.m8n8.x4.shared.b16 {%0,%1,%2,%3}, [%4];"
                 : "=r"(r0), "=r"(r1), "=r"(r2), "=r"(r3) : "r"(addr));
}
__device__ __forceinline__ void ldsm_x4_trans(uint32_t& r0, uint32_t& r1,
                                              uint32_t& r2, uint32_t& r3, uint32_t addr) {
    asm volatile("ldmatrix.sync.aligned.m8n8.x4.trans.shared.b16 {%0,%1,%2,%3}, [%4];"
                 : "=r"(r0), "=r"(r1), "=r"(r2), "=r"(r3) : "r"(addr));
}

__device__ __forceinline__ void mma16816(float& d0, float& d1, float& d2, float& d3,
                                         uint32_t a0, uint32_t a1, uint32_t a2, uint32_t a3,
                                         uint32_t b0, uint32_t b1) {
    asm volatile(
        "mma.sync.aligned.m16n8k16.row.col.f32.bf16.bf16.f32 "
        "{%0,%1,%2,%3}, {%4,%5,%6,%7}, {%8,%9}, {%0,%1,%2,%3};"
        : "+f"(d0), "+f"(d1), "+f"(d2), "+f"(d3)
        : "r"(a0), "r"(a1), "r"(a2), "r"(a3), "r"(b0), "r"(b1));
}

__device__ __forceinline__ uint32_t pack_bf16x2(float x, float y) {
    __nv_bfloat162 t = __floats2bfloat162_rn(x, y);
    return *(uint32_t*)&t;
}

// ---------------------------------------------------------------------------
// Split fp32 -> bf16 hi + bf16 lo (residual), vectorized x4
// ---------------------------------------------------------------------------
__global__ void split_bf16_kernel(const float* __restrict__ src,
                                  __nv_bfloat16* __restrict__ hi,
                                  __nv_bfloat16* __restrict__ lo, int n4)
{
    int i = blockIdx.x * blockDim.x + threadIdx.x;
    if (i >= n4) return;
    float4 v = ((const float4*)src)[i];
    __nv_bfloat16 h0 = __float2bfloat16(v.x);
    __nv_bfloat16 h1 = __float2bfloat16(v.y);
    __nv_bfloat16 h2 = __float2bfloat16(v.z);
    __nv_bfloat16 h3 = __float2bfloat16(v.w);
    __nv_bfloat16 l0 = __float2bfloat16(v.x - __bfloat162float(h0));
    __nv_bfloat16 l1 = __float2bfloat16(v.y - __bfloat162float(h1));
    __nv_bfloat16 l2 = __float2bfloat16(v.z - __bfloat162float(h2));
    __nv_bfloat16 l3 = __float2bfloat16(v.w - __bfloat162float(h3));
    __nv_bfloat162* hp = (__nv_bfloat162*)hi;
    __nv_bfloat162* lp = (__nv_bfloat162*)lo;
    hp[2 * i]     = __nv_bfloat162(h0, h1);
    hp[2 * i + 1] = __nv_bfloat162(h2, h3);
    lp[2 * i]     = __nv_bfloat162(l0, l1);
    lp[2 * i + 1] = __nv_bfloat162(l2, l3);
}

// ---------------------------------------------------------------------------
// mma.sync bf16-split GEMM (unchanged from R4)
// ---------------------------------------------------------------------------
#define BKC   32
#define LDSE  40
#define LDSB  (LDSE * 2)
#define TILE_B (128 * LDSB)
#define STAGE_B (4 * TILE_B)
#define GEMM_SMEM (2 * STAGE_B)

__global__ void __launch_bounds__(256)
gemm_mma_split_kernel(const __nv_bfloat16* __restrict__ Ahi,
                      const __nv_bfloat16* __restrict__ Alo,
                      const __nv_bfloat16* __restrict__ Bhi,
                      const __nv_bfloat16* __restrict__ Blo,
                      float* __restrict__ C, int N, int K)
{
    extern __shared__ char smem[];
    const uint32_t sb = smem_to_u32(smem);

    const int tid  = threadIdx.x;
    const int lane = tid & 31;
    const int wid  = tid >> 5;
    const int wm   = wid >> 1;
    const int wn   = wid & 1;
    const int bm   = blockIdx.y * 128;
    const int bn   = blockIdx.x * 128;

    const __nv_bfloat16* aH = Ahi + (size_t)bm * K;
    const __nv_bfloat16* aL = Alo + (size_t)bm * K;
    const __nv_bfloat16* bH = Bhi + (size_t)bn * K;
    const __nv_bfloat16* bL = Blo + (size_t)bn * K;

    const int r0 = tid >> 2;
    const int c0 = tid & 3;

    float acc[2][8][4];
#pragma unroll
    for (int i = 0; i < 2; i++)
#pragma unroll
        for (int j = 0; j < 8; j++)
#pragma unroll
            for (int t = 0; t < 4; t++) acc[i][j][t] = 0.f;

    const int iters = K / BKC;

    const uint32_t a_ld_off =
        (uint32_t)((wm * 32 + (lane & 15)) * LDSB + (lane >> 4) * 16);
    const uint32_t b_ld_off =
        (uint32_t)((wn * 64 + (lane & 7) + ((lane >> 4) << 3)) * LDSB
                   + ((lane >> 3) & 1) * 16);

    auto load_stage = [&](int stage, int k0) {
        uint32_t base = sb + stage * STAGE_B;
#pragma unroll
        for (int i = 0; i < 2; i++) {
            int row = r0 + i * 64;
            int c   = c0;
            uint32_t sofs = (uint32_t)(row * LDSB + c * 16);
            size_t gofs   = (size_t)row * K + k0 + c * 8;
            cp_async16(base + 0 * TILE_B + sofs, aH + gofs);
            cp_async16(base + 1 * TILE_B + sofs, aL + gofs);
            cp_async16(base + 2 * TILE_B + sofs, bH + gofs);
            cp_async16(base + 3 * TILE_B + sofs, bL + gofs);
        }
        cp_commit();
    };

    load_stage(0, 0);

    for (int it = 0; it < iters; ++it) {
        if (it + 1 < iters) {
            load_stage((it + 1) & 1, (it + 1) * BKC);
            cp_wait1();
        } else {
            cp_wait0();
        }
        __syncthreads();

        const uint32_t base = sb + (it & 1) * STAGE_B;
        const uint32_t sAH = base + 0 * TILE_B + a_ld_off;
        const uint32_t sAL = base + 1 * TILE_B + a_ld_off;
        const uint32_t sBH = base + 2 * TILE_B + b_ld_off;
        const uint32_t sBL = base + 3 * TILE_B + b_ld_off;

#pragma unroll
        for (int ks = 0; ks < 2; ks++) {
            const uint32_t kofs = ks * 32;
            uint32_t ah[2][4], al[2][4], bh[4][4], bl[4][4];
#pragma unroll
            for (int mt = 0; mt < 2; mt++) {
                ldsm_x4(ah[mt][0], ah[mt][1], ah[mt][2], ah[mt][3],
                        sAH + mt * 16 * LDSB + kofs);
                ldsm_x4(al[mt][0], al[mt][1], al[mt][2], al[mt][3],
                        sAL + mt * 16 * LDSB + kofs);
            }
#pragma unroll
            for (int np = 0; np < 4; np++) {
                ldsm_x4(bh[np][0], bh[np][1], bh[np][2], bh[np][3],
                        sBH + np * 16 * LDSB + kofs);
                ldsm_x4(bl[np][0], bl[np][1], bl[np][2], bl[np][3],
                        sBL + np * 16 * LDSB + kofs);
            }
#pragma unroll
            for (int mt = 0; mt < 2; mt++) {
#pragma unroll
                for (int np = 0; np < 4; np++) {
                    mma16816(acc[mt][2*np][0], acc[mt][2*np][1], acc[mt][2*np][2], acc[mt][2*np][3],
                             ah[mt][0], ah[mt][1], ah[mt][2], ah[mt][3], bh[np][0], bh[np][1]);
                    mma16816(acc[mt][2*np+1][0], acc[mt][2*np+1][1], acc[mt][2*np+1][2], acc[mt][2*np+1][3],
                             ah[mt][0], ah[mt][1], ah[mt][2], ah[mt][3], bh[np][2], bh[np][3]);
                    mma16816(acc[mt][2*np][0], acc[mt][2*np][1], acc[mt][2*np][2], acc[mt][2*np][3],
                             ah[mt][0], ah[mt][1], ah[mt][2], ah[mt][3], bl[np][0], bl[np][1]);
                    mma16816(acc[mt][2*np+1][0], acc[mt][2*np+1][1], acc[mt][2*np+1][2], acc[mt][2*np+1][3],
                             ah[mt][0], ah[mt][1], ah[mt][2], ah[mt][3], bl[np][2], bl[np][3]);
                    mma16816(acc[mt][2*np][0], acc[mt][2*np][1], acc[mt][2*np][2], acc[mt][2*np][3],
                             al[mt][0], al[mt][1], al[mt][2], al[mt][3], bh[np][0], bh[np][1]);
                    mma16816(acc[mt][2*np+1][0], acc[mt][2*np+1][1], acc[mt][2*np+1][2], acc[mt][2*np+1][3],
                             al[mt][0], al[mt][1], al[mt][2], al[mt][3], bh[np][2], bh[np][3]);
                }
            }
        }
        __syncthreads();
    }

#pragma unroll
    for (int mt = 0; mt < 2; mt++) {
        int row = bm + wm * 32 + mt * 16 + (lane >> 2);
#pragma unroll
        for (int nt = 0; nt < 8; nt++) {
            int col = bn + wn * 64 + nt * 8 + (lane & 3) * 2;
            *(float2*)&C[(size_t)row * N + col] =
                make_float2(acc[mt][nt][0], acc[mt][nt][1]);
            *(float2*)&C[(size_t)(row + 8) * N + col] =
                make_float2(acc[mt][nt][2], acc[mt][nt][3]);
        }
    }
}

// ---------------------------------------------------------------------------
// Fused RoPE + split + per-head relayout.
// One thread per (b,l,head) row of 64: q heads (rope), k heads (rope), v (copy).
// ---------------------------------------------------------------------------
__global__ void rope_split_kernel()
{
    const int NROW = MTOT * (NH + 2 * NKV);   // 4096 * 48
    int rowid = blockIdx.x * blockDim.x + threadIdx.x;
    if (rowid >= NROW) return;

    int hh = rowid % (NH + 2 * NKV);
    int bl = rowid / (NH + 2 * NKV);
    int b  = bl / SEQ;
    int l  = bl % SEQ;

    const float* src;
    __nv_bfloat16 *dh, *dl;
    bool do_rope;
    if (hh < NH) {
        src = g_qkv + (size_t)bl * OPS + hh * HD;
        size_t o = ((size_t)(b * NH + hh) * SEQ + l) * HD;
        dh = g_qh + o; dl = g_ql + o; do_rope = true;
    } else if (hh < NH + NKV) {
        int h2 = hh - NH;
        src = g_qkv + (size_t)bl * OPS + QPOS + h2 * HD;
        size_t o = ((size_t)(b * NKV + h2) * SEQ + l) * HD;
        dh = g_kh + o; dl = g_kl + o; do_rope = true;
    } else {
        int h2 = hh - NH - NKV;
        src = g_qkv + (size_t)bl * OPS + QPOS + KVPOS + h2 * HD;
        size_t o = ((size_t)(b * NKV + h2) * SEQ + l) * HD;
        dh = g_vh + o; dl = g_vl + o; do_rope = false;
    }

    float v[64];
#pragma unroll
    for (int i = 0; i < 16; i++)
        *(float4*)&v[4 * i] = *(const float4*)(src + 4 * i);

    if (do_rope) {
#pragma unroll 8
        for (int i = 0; i < 32; i++) {
            float inv_freq = powf(10000.0f, -(float)(2 * i) / (float)HD);
            float ang = (float)l * inv_freq;
            float s, c;
            sincosf(ang, &s, &c);
            float t1 = v[i], t2 = v[i + 32];
            v[i]      = t1 * c - t2 * s;
            v[i + 32] = t2 * c + t1 * s;
        }
    }

#pragma unroll
    for (int j = 0; j < 32; j++) {
        float x = v[2 * j], y = v[2 * j + 1];
        __nv_bfloat16 hx = __float2bfloat16(x);
        __nv_bfloat16 hy = __float2bfloat16(y);
        ((__nv_bfloat162*)dh)[j] = __nv_bfloat162(hx, hy);
        ((__nv_bfloat162*)dl)[j] = __nv_bfloat162(
            __float2bfloat16(x - __bfloat162float(hx)),
            __float2bfloat16(y - __bfloat162float(hy)));
    }
}

// ---------------------------------------------------------------------------
// Flash attention with bf16-split mma.sync.
// CTA: 64 q-rows, 4 warps (m16 each). KV tiles of 64 keys, double-buffered.
// ---------------------------------------------------------------------------
#define A_LDSB  144                       // 72 elems * 2B (conflict-free)
#define A_TILE  (64 * A_LDSB)             // 9216 B
#define A_STAGE (4 * A_TILE)              // KH, KL, VH, VL
#define ATTN_SMEM (2 * A_STAGE)           // 73728 B
#define AT_KH 0
#define AT_KL A_TILE
#define AT_VH (2 * A_TILE)
#define AT_VL (3 * A_TILE)

__global__ void __launch_bounds__(128)
attn_mma_kernel()
{
    extern __shared__ char smem[];
    const uint32_t sb = smem_to_u32(smem);

    const int tid  = threadIdx.x;
    const int lane = tid & 31;
    const int wid  = tid >> 5;
    const int q0   = blockIdx.x * 64;
    const int hq   = blockIdx.y;
    const int b    = blockIdx.z;
    const int kvh  = hq >> 2;              // NH/NKV = 4
    const int r    = lane >> 2;
    const int c2   = (lane & 3) * 2;

    // ---- Q fragments, loaded directly from gmem (hi + lo)
    const size_t qoff = ((size_t)(b * NH + hq) * SEQ + q0 + wid * 16 + r) * HD;
    const __nv_bfloat16* qh0 = g_qh + qoff;
    const __nv_bfloat16* qh1 = qh0 + 8 * HD;
    const __nv_bfloat16* ql0 = g_ql + qoff;
    const __nv_bfloat16* ql1 = ql0 + 8 * HD;
    uint32_t qfh[4][4], qfl[4][4];
#pragma unroll
    for (int ks = 0; ks < 4; ks++) {
        qfh[ks][0] = *(const uint32_t*)(qh0 + ks * 16 + c2);
        qfh[ks][1] = *(const uint32_t*)(qh1 + ks * 16 + c2);
        qfh[ks][2] = *(const uint32_t*)(qh0 + ks * 16 + c2 + 8);
        qfh[ks][3] = *(const uint32_t*)(qh1 + ks * 16 + c2 + 8);
        qfl[ks][0] = *(const uint32_t*)(ql0 + ks * 16 + c2);
        qfl[ks][1] = *(const uint32_t*)(ql1 + ks * 16 + c2);
        qfl[ks][2] = *(const uint32_t*)(ql0 + ks * 16 + c2 + 8);
        qfl[ks][3] = *(const uint32_t*)(ql1 + ks * 16 + c2 + 8);
    }

    const __nv_bfloat16* kh_g = g_kh + (size_t)(b * NKV + kvh) * SEQ * HD;
    const __nv_bfloat16* kl_g = g_kl + (size_t)(b * NKV + kvh) * SEQ * HD;
    const __nv_bfloat16* vh_g = g_vh + (size_t)(b * NKV + kvh) * SEQ * HD;
    const __nv_bfloat16* vl_g = g_vl + (size_t)(b * NKV + kvh) * SEQ * HD;

    auto load_stage = [&](int st, int kt) {
        uint32_t base = sb + st * A_STAGE;
#pragma unroll
        for (int i = 0; i < 4; i++) {
            int lin = tid + i * 128;
            int row = lin >> 3;
            int c   = lin & 7;
            uint32_t sofs = (uint32_t)(row * A_LDSB + c * 16);
            size_t gofs   = (size_t)(kt + row) * HD + c * 8;
            cp_async16(base + AT_KH + sofs, kh_g + gofs);
            cp_async16(base + AT_KL + sofs, kl_g + gofs);
            cp_async16(base + AT_VH + sofs, vh_g + gofs);
            cp_async16(base + AT_VL + sofs, vl_g + gofs);
        }
        cp_commit();
    };

    const int iters = blockIdx.x + 1;
    load_stage(0, 0);

    float o[8][4];
#pragma unroll
    for (int j = 0; j < 8; j++)
#pragma unroll
        for (int t = 0; t < 4; t++) o[j][t] = 0.f;
    float m0 = -1e30f, m1 = -1e30f, l0 = 0.f, l1 = 0.f;

    // ldmatrix lane cores
    const uint32_t kcore = (uint32_t)(((lane & 7) + ((lane >> 4) << 3)) * A_LDSB
                                      + ((lane >> 3) & 1) * 16);
    const uint32_t vcore = (uint32_t)((lane & 15) * A_LDSB + ((lane >> 4) << 4));

    for (int it = 0; it < iters; ++it) {
        const int kt = it * 64;
        if (it + 1 < iters) {
            load_stage((it + 1) & 1, (it + 1) * 64);
            cp_wait1();
        } else {
            cp_wait0();
        }
        __syncthreads();

        const uint32_t base = sb + (it & 1) * A_STAGE;

        // ---- S = Q K^T  (3 split combos)
        float s[8][4];
#pragma unroll
        for (int j = 0; j < 8; j++)
#pragma unroll
            for (int t = 0; t < 4; t++) s[j][t] = 0.f;

#pragma unroll
        for (int kk = 0; kk < 4; kk++) {
#pragma unroll
            for (int np = 0; np < 4; np++) {
                uint32_t addr = base + AT_KH + kcore + np * 16 * A_LDSB + kk * 32;
                uint32_t kb[4], kbl[4];
                ldsm_x4(kb[0], kb[1], kb[2], kb[3], addr);
                ldsm_x4(kbl[0], kbl[1], kbl[2], kbl[3], addr + (AT_KL - AT_KH));
                int j0 = 2 * np, j1 = 2 * np + 1;
                mma16816(s[j0][0], s[j0][1], s[j0][2], s[j0][3],
                         qfh[kk][0], qfh[kk][1], qfh[kk][2], qfh[kk][3], kb[0], kb[1]);
                mma16816(s[j1][0], s[j1][1], s[j1][2], s[j1][3],
                         qfh[kk][0], qfh[kk][1], qfh[kk][2], qfh[kk][3], kb[2], kb[3]);
                mma16816(s[j0][0], s[j0][1], s[j0][2], s[j0][3],
                         qfh[kk][0], qfh[kk][1], qfh[kk][2], qfh[kk][3], kbl[0], kbl[1]);
                mma16816(s[j1][0], s[j1][1], s[j1][2], s[j1][3],
                         qfh[kk][0], qfh[kk][1], qfh[kk][2], qfh[kk][3], kbl[2], kbl[3]);
                mma16816(s[j0][0], s[j0][1], s[j0][2], s[j0][3],
                         qfl[kk][0], qfl[kk][1], qfl[kk][2], qfl[kk][3], kb[0], kb[1]);
                mma16816(s[j1][0], s[j1][1], s[j1][2], s[j1][3],
                         qfl[kk][0], qfl[kk][1], qfl[kk][2], qfl[kk][3], kb[2], kb[3]);
            }
        }

        // ---- scale + causal mask (diagonal block only)
#pragma unroll
        for (int j = 0; j < 8; j++)
#pragma unroll
            for (int t = 0; t < 4; t++) s[j][t] *= ATTN_SCALE;

        if (kt == q0) {
            int row0 = q0 + wid * 16 + r;
#pragma unroll
            for (int j = 0; j < 8; j++) {
                int col = kt + j * 8 + c2;
                if (col > row0)     s[j][0] = -1e30f;
                if (col + 1 > row0) s[j][1] = -1e30f;
                if (col > row0 + 8)     s[j][2] = -1e30f;
                if (col + 1 > row0 + 8) s[j][3] = -1e30f;
            }
        }

        // ---- online softmax
        float mx0 = -1e30f, mx1 = -1e30f;
#pragma unroll
        for (int j = 0; j < 8; j++) {
            mx0 = fmaxf(mx0, fmaxf(s[j][0], s[j][1]));
            mx1 = fmaxf(mx1, fmaxf(s[j][2], s[j][3]));
        }
        mx0 = fmaxf(mx0, __shfl_xor_sync(0xffffffffu, mx0, 1));
        mx0 = fmaxf(mx0, __shfl_xor_sync(0xffffffffu, mx0, 2));
        mx1 = fmaxf(mx1, __shfl_xor_sync(0xffffffffu, mx1, 1));
        mx1 = fmaxf(mx1, __shfl_xor_sync(0xffffffffu, mx1, 2));

        float mn0 = fmaxf(m0, mx0), mn1 = fmaxf(m1, mx1);
        float corr0 = __expf(m0 - mn0), corr1 = __expf(m1 - mn1);
        l0 *= corr0; l1 *= corr1;
#pragma unroll
        for (int j = 0; j < 8; j++) {
            o[j][0] *= corr0; o[j][1] *= corr0;
            o[j][2] *= corr1; o[j][3] *= corr1;
        }
#pragma unroll
        for (int j = 0; j < 8; j++) {
            float p0 = __expf(s[j][0] - mn0);
            float p1 = __expf(s[j][1] - mn0);
            float p2 = __expf(s[j][2] - mn1);
            float p3 = __expf(s[j][3] - mn1);
            l0 += p0 + p1; l1 += p2 + p3;
            s[j][0] = p0; s[j][1] = p1; s[j][2] = p2; s[j][3] = p3;
        }
        m0 = mn0; m1 = mn1;

        // ---- O += P V  (3 split combos); P frags from S registers
#pragma unroll
        for (int kk = 0; kk < 4; kk++) {
            uint32_t pah[4], pal[4];
            {
                float x, y;
                __nv_bfloat16 hx, hy;
                // a0: rows r, keys 16kk + c2,c2+1  -> s[2kk][0..1]
                x = s[2*kk][0]; y = s[2*kk][1];
                hx = __float2bfloat16(x); hy = __float2bfloat16(y);
                pah[0] = pack_bf16x2(__bfloat162float(hx), __bfloat162float(hy));
                pal[0] = pack_bf16x2(x - __bfloat162float(hx), y - __bfloat162float(hy));
                x = s[2*kk][2]; y = s[2*kk][3];
                hx = __float2bfloat16(x); hy = __float2bfloat16(y);
                pah[1] = pack_bf16x2(__bfloat162float(hx), __bfloat162float(hy));
                pal[1] = pack_bf16x2(x - __bfloat162float(hx), y - __bfloat162float(hy));
                x = s[2*kk+1][0]; y = s[2*kk+1][1];
                hx = __float2bfloat16(x); hy = __float2bfloat16(y);
                pah[2] = pack_bf16x2(__bfloat162float(hx), __bfloat162float(hy));
                pal[2] = pack_bf16x2(x - __bfloat162float(hx), y - __bfloat162float(hy));
                x = s[2*kk+1][2]; y = s[2*kk+1][3];
                hx = __float2bfloat16(x); hy = __float2bfloat16(y);
                pah[3] = pack_bf16x2(__bfloat162float(hx), __bfloat162float(hy));
                pal[3] = pack_bf16x2(x - __bfloat162float(hx), y - __bfloat162float(hy));
            }
#pragma unroll
            for (int np = 0; np < 4; np++) {
                uint32_t addr = base + AT_VH + vcore + kk * 16 * A_LDSB + np * 32;
                uint32_t vb[4], vbl[4];
                ldsm_x4_trans(vb[0], vb[1], vb[2], vb[3], addr);
                ldsm_x4_trans(vbl[0], vbl[1], vbl[2], vbl[3], addr + (AT_VL - AT_VH));
                int j0 = 2 * np, j1 = 2 * np + 1;
                mma16816(o[j0][0], o[j0][1], o[j0][2], o[j0][3],
                         pah[0], pah[1], pah[2], pah[3], vb[0], vb[1]);
                mma16816(o[j1][0], o[j1][1], o[j1][2], o[j1][3],
                         pah[0], pah[1], pah[2], pah[3], vb[2], vb[3]);
                mma16816(o[j0][0], o[j0][1], o[j0][2], o[j0][3],
                         pah[0], pah[1], pah[2], pah[3], vbl[0], vbl[1]);
                mma16816(o[j1][0], o[j1][1], o[j1][2], o[j1][3],
                         pah[0], pah[1], pah[2], pah[3], vbl[2], vbl[3]);
                mma16816(o[j0][0], o[j0][1], o[j0][2], o[j0][3],
                         pal[0], pal[1], pal[2], pal[3], vb[0], vb[1]);
                mma16816(o[j1][0], o[j1][1], o[j1][2], o[j1][3],
                         pal[0], pal[1], pal[2], pal[3], vb[2], vb[3]);
            }
        }
        __syncthreads();
    }

    // ---- finalize: reduce l across the 4 lanes of each row, normalize, store
    l0 += __shfl_xor_sync(0xffffffffu, l0, 1);
    l0 += __shfl_xor_sync(0xffffffffu, l0, 2);
    l1 += __shfl_xor_sync(0xffffffffu, l1, 1);
    l1 += __shfl_xor_sync(0xffffffffu, l1, 2);
    float inv0 = 1.f / l0, inv1 = 1.f / l1;

    size_t row0 = (size_t)(b * SEQ + q0 + wid * 16 + r);
    size_t row1 = row0 + 8;
#pragma unroll
    for (int j = 0; j < 8; j++) {
        int col = hq * HD + j * 8 + c2;
        float x = o[j][0] * inv0, y = o[j][1] * inv0;
        __nv_bfloat16 hx = __float2bfloat16(x), hy = __float2bfloat16(y);
        *(uint32_t*)&g_a_hi[row0 * QPOS + col] =
            pack_bf16x2(__bfloat162float(hx), __bfloat162float(hy));
        *(uint32_t*)&g_a_lo[row0 * QPOS + col] =
            pack_bf16x2(x - __bfloat162float(hx), y - __bfloat162float(hy));
        x = o[j][2] * inv1; y = o[j][3] * inv1;
        hx = __float2bfloat16(x); hy = __float2bfloat16(y);
        *(uint32_t*)&g_a_hi[row1 * QPOS + col] =
            pack_bf16x2(__bfloat162float(hx), __bfloat162float(hy));
        *(uint32_t*)&g_a_lo[row1 * QPOS + col] =
            pack_bf16x2(x - __bfloat162float(hx), y - __bfloat162float(hy));
    }
}

// ---------------------------------------------------------------------------
// kernel_launch
// ---------------------------------------------------------------------------
extern "C" void kernel_launch(void* const* d_in, const int* in_sizes, int n_in,
                              void* d_out, int out_size)
{
    const float* x    = (const float*)d_in[0];
    const float* Wqkv = (const float*)d_in[1];
    const float* Wo   = (const float*)d_in[2];
    float* out        = (float*)d_out;

    float* qkv;
    __nv_bfloat16 *xh, *xl, *wqh, *wql, *woh, *wol, *ah, *al;
    cudaGetSymbolAddress((void**)&qkv, g_qkv);
    cudaGetSymbolAddress((void**)&xh,  g_x_hi);
    cudaGetSymbolAddress((void**)&xl,  g_x_lo);
    cudaGetSymbolAddress((void**)&wqh, g_wq_hi);
    cudaGetSymbolAddress((void**)&wql, g_wq_lo);
    cudaGetSymbolAddress((void**)&woh, g_wo_hi);
    cudaGetSymbolAddress((void**)&wol, g_wo_lo);
    cudaGetSymbolAddress((void**)&ah,  g_a_hi);
    cudaGetSymbolAddress((void**)&al,  g_a_lo);

    cudaFuncSetAttribute(gemm_mma_split_kernel,
                         cudaFuncAttributeMaxDynamicSharedMemorySize, GEMM_SMEM);
    cudaFuncSetAttribute(attn_mma_kernel,
                         cudaFuncAttributeMaxDynamicSharedMemorySize, ATTN_SMEM);

    // 1) Split inputs to bf16 hi/lo
    {
        int n4 = (MTOT * DMODEL) / 4;
        split_bf16_kernel<<<(n4 + 255) / 256, 256>>>(x, xh, xl, n4);
    }
    {
        int n4 = (OPS * DMODEL) / 4;
        split_bf16_kernel<<<(n4 + 255) / 256, 256>>>(Wqkv, wqh, wql, n4);
    }
    {
        int n4 = (DMODEL * DMODEL) / 4;
        split_bf16_kernel<<<(n4 + 255) / 256, 256>>>(Wo, woh, wol, n4);
    }

    // 2) QKV projection
    {
        dim3 grid(OPS / 128, MTOT / 128);
        gemm_mma_split_kernel<<<grid, 256, GEMM_SMEM>>>(xh, xl, wqh, wql, qkv, OPS, DMODEL);
    }

    // 3) RoPE + split + per-head relayout
    {
        int nrow = MTOT * (NH + 2 * NKV);
        rope_split_kernel<<<(nrow + 255) / 256, 256>>>();
    }

    // 4) Flash attention (tensor cores), writes bf16 hi/lo directly
    {
        dim3 grid(SEQ / 64, NH, BATCH);
        attn_mma_kernel<<<grid, 128, ATTN_SMEM>>>();
    }

    // 5) O-projection
    {
        dim3 grid(DMODEL / 128, MTOT / 128);
        gemm_mma_split_kernel<<<grid, 256, GEMM_SMEM>>>(ah, al, woh, wol, out, DMODEL, DMODEL);
    }
}

// round 6
// speedup vs baseline: 3.6239x; 1.1047x over previous
#include <cuda_runtime.h>
#include <cuda_bf16.h>
#include <math.h>
#include <stdint.h>

// Problem constants
#define BATCH   2
#define SEQ     2048
#define DMODEL  2048
#define NH      32
#define NKV     8
#define HD      64
#define QPOS    (NH * HD)            // 2048
#define KVPOS   (NKV * HD)           // 512
#define OPS     (QPOS + 2 * KVPOS)   // 3072
#define MTOT    (BATCH * SEQ)        // 4096
#define ATTN_SCALE 0.125f

// ---------------------------------------------------------------------------
// Scratch (device globals: allocation-guard safe)
// ---------------------------------------------------------------------------
__device__ float g_qkv[MTOT * OPS];       // [4096, 3072] fp32
__device__ __nv_bfloat16 g_x_hi[MTOT * DMODEL];
__device__ __nv_bfloat16 g_x_lo[MTOT * DMODEL];
__device__ __nv_bfloat16 g_wq_hi[OPS * DMODEL];
__device__ __nv_bfloat16 g_wq_lo[OPS * DMODEL];
__device__ __nv_bfloat16 g_wo_hi[DMODEL * DMODEL];
__device__ __nv_bfloat16 g_wo_lo[DMODEL * DMODEL];
// per-head-contiguous roped q/k and v, bf16 hi/lo
__device__ __nv_bfloat16 g_qh[BATCH * NH  * SEQ * HD];
__device__ __nv_bfloat16 g_ql[BATCH * NH  * SEQ * HD];
__device__ __nv_bfloat16 g_kh[BATCH * NKV * SEQ * HD];
__device__ __nv_bfloat16 g_kl[BATCH * NKV * SEQ * HD];
__device__ __nv_bfloat16 g_vh[BATCH * NKV * SEQ * HD];
__device__ __nv_bfloat16 g_vl[BATCH * NKV * SEQ * HD];
// attention output, bf16 hi/lo (input to O-proj)
__device__ __nv_bfloat16 g_a_hi[MTOT * QPOS];
__device__ __nv_bfloat16 g_a_lo[MTOT * QPOS];

// ---------------------------------------------------------------------------
// helpers
// ---------------------------------------------------------------------------
__device__ __forceinline__ uint32_t smem_to_u32(const void* p) {
    uint32_t a;
    asm("{ .reg .u64 t; cvta.to.shared.u64 t, %1; cvt.u32.u64 %0, t; }"
        : "=r"(a) : "l"(p));
    return a;
}

__device__ __forceinline__ void cp_async16(uint32_t smem_dst, const void* gmem_src) {
    asm volatile("cp.async.cg.shared.global [%0], [%1], 16;"
                 :: "r"(smem_dst), "l"(gmem_src) : "memory");
}
__device__ __forceinline__ void cp_commit() {
    asm volatile("cp.async.commit_group;" ::: "memory");
}
__device__ __forceinline__ void cp_wait1() {
    asm volatile("cp.async.wait_group 1;" ::: "memory");
}
__device__ __forceinline__ void cp_wait0() {
    asm volatile("cp.async.wait_group 0;" ::: "memory");
}

__device__ __forceinline__ void ldsm_x4(uint32_t& r0, uint32_t& r1,
                                        uint32_t& r2, uint32_t& r3, uint32_t addr) {
    asm volatile("ldmatrix.sync.aligned.m8n8.x4.shared.b16 {%0,%1,%2,%3}, [%4];"
                 : "=r"(r0), "=r"(r1), "=r"(r2), "=r"(r3) : "r"(addr));
}
__device__ __forceinline__ void ldsm_x4_trans(uint32_t& r0, uint32_t& r1,
                                              uint32_t& r2, uint32_t& r3, uint32_t addr) {
    asm volatile("ldmatrix.sync.aligned.m8n8.x4.trans.shared.b16 {%0,%1,%2,%3}, [%4];"
                 : "=r"(r0), "=r"(r1), "=r"(r2), "=r"(r3) : "r"(addr));
}

__device__ __forceinline__ void mma16816(float& d0, float& d1, float& d2, float& d3,
                                         uint32_t a0, uint32_t a1, uint32_t a2, uint32_t a3,
                                         uint32_t b0, uint32_t b1) {
    asm volatile(
        "mma.sync.aligned.m16n8k16.row.col.f32.bf16.bf16.f32 "
        "{%0,%1,%2,%3}, {%4,%5,%6,%7}, {%8,%9}, {%0,%1,%2,%3};"
        : "+f"(d0), "+f"(d1), "+f"(d2), "+f"(d3)
        : "r"(a0), "r"(a1), "r"(a2), "r"(a3), "r"(b0), "r"(b1));
}

__device__ __forceinline__ uint32_t pack_bf16x2(float x, float y) {
    __nv_bfloat162 t = __floats2bfloat162_rn(x, y);
    return *(uint32_t*)&t;
}

// ---------------------------------------------------------------------------
// Split fp32 -> bf16 hi + bf16 lo (residual), vectorized x4
// ---------------------------------------------------------------------------
__global__ void split_bf16_kernel(const float* __restrict__ src,
                                  __nv_bfloat16* __restrict__ hi,
                                  __nv_bfloat16* __restrict__ lo, int n4)
{
    int i = blockIdx.x * blockDim.x + threadIdx.x;
    if (i >= n4) return;
    float4 v = ((const float4*)src)[i];
    __nv_bfloat16 h0 = __float2bfloat16(v.x);
    __nv_bfloat16 h1 = __float2bfloat16(v.y);
    __nv_bfloat16 h2 = __float2bfloat16(v.z);
    __nv_bfloat16 h3 = __float2bfloat16(v.w);
    __nv_bfloat16 l0 = __float2bfloat16(v.x - __bfloat162float(h0));
    __nv_bfloat16 l1 = __float2bfloat16(v.y - __bfloat162float(h1));
    __nv_bfloat16 l2 = __float2bfloat16(v.z - __bfloat162float(h2));
    __nv_bfloat16 l3 = __float2bfloat16(v.w - __bfloat162float(h3));
    __nv_bfloat162* hp = (__nv_bfloat162*)hi;
    __nv_bfloat162* lp = (__nv_bfloat162*)lo;
    hp[2 * i]     = __nv_bfloat162(h0, h1);
    hp[2 * i + 1] = __nv_bfloat162(h2, h3);
    lp[2 * i]     = __nv_bfloat162(l0, l1);
    lp[2 * i + 1] = __nv_bfloat162(l2, l3);
}

// ---------------------------------------------------------------------------
// mma.sync bf16-split GEMM: C[M,N] = (Ahi+Alo)[M,K] * (Bhi+Blo)[N,K]^T, fp32 C.
// Block tile 128x128, K-chunk 32, double-buffered cp.async.
// 256 threads = 8 warps (4m x 2n); warp tile 32x64.
// __launch_bounds__(256, 2): cap regs at 128 so 2 CTAs co-reside per SM.
// B-fragments are loaded per-n-panel to keep peak register pressure low.
// ---------------------------------------------------------------------------
#define BKC   32
#define LDSE  40
#define LDSB  (LDSE * 2)
#define TILE_B (128 * LDSB)
#define STAGE_B (4 * TILE_B)
#define GEMM_SMEM (2 * STAGE_B)       // 81920 B; x2 CTAs = 160 KB < 228 KB

__global__ void __launch_bounds__(256, 2)
gemm_mma_split_kernel(const __nv_bfloat16* __restrict__ Ahi,
                      const __nv_bfloat16* __restrict__ Alo,
                      const __nv_bfloat16* __restrict__ Bhi,
                      const __nv_bfloat16* __restrict__ Blo,
                      float* __restrict__ C, int N, int K)
{
    extern __shared__ char smem[];
    const uint32_t sb = smem_to_u32(smem);

    const int tid  = threadIdx.x;
    const int lane = tid & 31;
    const int wid  = tid >> 5;
    const int wm   = wid >> 1;
    const int wn   = wid & 1;
    const int bm   = blockIdx.y * 128;
    const int bn   = blockIdx.x * 128;

    const __nv_bfloat16* aH = Ahi + (size_t)bm * K;
    const __nv_bfloat16* aL = Alo + (size_t)bm * K;
    const __nv_bfloat16* bH = Bhi + (size_t)bn * K;
    const __nv_bfloat16* bL = Blo + (size_t)bn * K;

    const int r0 = tid >> 2;
    const int c0 = tid & 3;

    float acc[2][8][4];
#pragma unroll
    for (int i = 0; i < 2; i++)
#pragma unroll
        for (int j = 0; j < 8; j++)
#pragma unroll
            for (int t = 0; t < 4; t++) acc[i][j][t] = 0.f;

    const int iters = K / BKC;

    const uint32_t a_ld_off =
        (uint32_t)((wm * 32 + (lane & 15)) * LDSB + (lane >> 4) * 16);
    const uint32_t b_ld_off =
        (uint32_t)((wn * 64 + (lane & 7) + ((lane >> 4) << 3)) * LDSB
                   + ((lane >> 3) & 1) * 16);

    auto load_stage = [&](int stage, int k0) {
        uint32_t base = sb + stage * STAGE_B;
#pragma unroll
        for (int i = 0; i < 2; i++) {
            int row = r0 + i * 64;
            int c   = c0;
            uint32_t sofs = (uint32_t)(row * LDSB + c * 16);
            size_t gofs   = (size_t)row * K + k0 + c * 8;
            cp_async16(base + 0 * TILE_B + sofs, aH + gofs);
            cp_async16(base + 1 * TILE_B + sofs, aL + gofs);
            cp_async16(base + 2 * TILE_B + sofs, bH + gofs);
            cp_async16(base + 3 * TILE_B + sofs, bL + gofs);
        }
        cp_commit();
    };

    load_stage(0, 0);

    for (int it = 0; it < iters; ++it) {
        if (it + 1 < iters) {
            load_stage((it + 1) & 1, (it + 1) * BKC);
            cp_wait1();
        } else {
            cp_wait0();
        }
        __syncthreads();

        const uint32_t base = sb + (it & 1) * STAGE_B;
        const uint32_t sAH = base + 0 * TILE_B + a_ld_off;
        const uint32_t sAL = base + 1 * TILE_B + a_ld_off;
        const uint32_t sBH = base + 2 * TILE_B + b_ld_off;
        const uint32_t sBL = base + 3 * TILE_B + b_ld_off;

#pragma unroll
        for (int ks = 0; ks < 2; ks++) {
            const uint32_t kofs = ks * 32;
            uint32_t ah[2][4], al[2][4];
#pragma unroll
            for (int mt = 0; mt < 2; mt++) {
                ldsm_x4(ah[mt][0], ah[mt][1], ah[mt][2], ah[mt][3],
                        sAH + mt * 16 * LDSB + kofs);
                ldsm_x4(al[mt][0], al[mt][1], al[mt][2], al[mt][3],
                        sAL + mt * 16 * LDSB + kofs);
            }
#pragma unroll
            for (int np = 0; np < 4; np++) {
                uint32_t bh[4], bl[4];
                ldsm_x4(bh[0], bh[1], bh[2], bh[3],
                        sBH + np * 16 * LDSB + kofs);
                ldsm_x4(bl[0], bl[1], bl[2], bl[3],
                        sBL + np * 16 * LDSB + kofs);
#pragma unroll
                for (int mt = 0; mt < 2; mt++) {
                    mma16816(acc[mt][2*np][0], acc[mt][2*np][1], acc[mt][2*np][2], acc[mt][2*np][3],
                             ah[mt][0], ah[mt][1], ah[mt][2], ah[mt][3], bh[0], bh[1]);
                    mma16816(acc[mt][2*np+1][0], acc[mt][2*np+1][1], acc[mt][2*np+1][2], acc[mt][2*np+1][3],
                             ah[mt][0], ah[mt][1], ah[mt][2], ah[mt][3], bh[2], bh[3]);
                    mma16816(acc[mt][2*np][0], acc[mt][2*np][1], acc[mt][2*np][2], acc[mt][2*np][3],
                             ah[mt][0], ah[mt][1], ah[mt][2], ah[mt][3], bl[0], bl[1]);
                    mma16816(acc[mt][2*np+1][0], acc[mt][2*np+1][1], acc[mt][2*np+1][2], acc[mt][2*np+1][3],
                             ah[mt][0], ah[mt][1], ah[mt][2], ah[mt][3], bl[2], bl[3]);
                    mma16816(acc[mt][2*np][0], acc[mt][2*np][1], acc[mt][2*np][2], acc[mt][2*np][3],
                             al[mt][0], al[mt][1], al[mt][2], al[mt][3], bh[0], bh[1]);
                    mma16816(acc[mt][2*np+1][0], acc[mt][2*np+1][1], acc[mt][2*np+1][2], acc[mt][2*np+1][3],
                             al[mt][0], al[mt][1], al[mt][2], al[mt][3], bh[2], bh[3]);
                }
            }
        }
        __syncthreads();
    }

#pragma unroll
    for (int mt = 0; mt < 2; mt++) {
        int row = bm + wm * 32 + mt * 16 + (lane >> 2);
#pragma unroll
        for (int nt = 0; nt < 8; nt++) {
            int col = bn + wn * 64 + nt * 8 + (lane & 3) * 2;
            *(float2*)&C[(size_t)row * N + col] =
                make_float2(acc[mt][nt][0], acc[mt][nt][1]);
            *(float2*)&C[(size_t)(row + 8) * N + col] =
                make_float2(acc[mt][nt][2], acc[mt][nt][3]);
        }
    }
}

// ---------------------------------------------------------------------------
// Fused RoPE + split + per-head relayout.
// ---------------------------------------------------------------------------
__global__ void rope_split_kernel()
{
    const int NROW = MTOT * (NH + 2 * NKV);   // 4096 * 48
    int rowid = blockIdx.x * blockDim.x + threadIdx.x;
    if (rowid >= NROW) return;

    int hh = rowid % (NH + 2 * NKV);
    int bl = rowid / (NH + 2 * NKV);
    int b  = bl / SEQ;
    int l  = bl % SEQ;

    const float* src;
    __nv_bfloat16 *dh, *dl;
    bool do_rope;
    if (hh < NH) {
        src = g_qkv + (size_t)bl * OPS + hh * HD;
        size_t o = ((size_t)(b * NH + hh) * SEQ + l) * HD;
        dh = g_qh + o; dl = g_ql + o; do_rope = true;
    } else if (hh < NH + NKV) {
        int h2 = hh - NH;
        src = g_qkv + (size_t)bl * OPS + QPOS + h2 * HD;
        size_t o = ((size_t)(b * NKV + h2) * SEQ + l) * HD;
        dh = g_kh + o; dl = g_kl + o; do_rope = true;
    } else {
        int h2 = hh - NH - NKV;
        src = g_qkv + (size_t)bl * OPS + QPOS + KVPOS + h2 * HD;
        size_t o = ((size_t)(b * NKV + h2) * SEQ + l) * HD;
        dh = g_vh + o; dl = g_vl + o; do_rope = false;
    }

    float v[64];
#pragma unroll
    for (int i = 0; i < 16; i++)
        *(float4*)&v[4 * i] = *(const float4*)(src + 4 * i);

    if (do_rope) {
#pragma unroll 8
        for (int i = 0; i < 32; i++) {
            float inv_freq = powf(10000.0f, -(float)(2 * i) / (float)HD);
            float ang = (float)l * inv_freq;
            float s, c;
            sincosf(ang, &s, &c);
            float t1 = v[i], t2 = v[i + 32];
            v[i]      = t1 * c - t2 * s;
            v[i + 32] = t2 * c + t1 * s;
        }
    }

#pragma unroll
    for (int j = 0; j < 32; j++) {
        float x = v[2 * j], y = v[2 * j + 1];
        __nv_bfloat16 hx = __float2bfloat16(x);
        __nv_bfloat16 hy = __float2bfloat16(y);
        ((__nv_bfloat162*)dh)[j] = __nv_bfloat162(hx, hy);
        ((__nv_bfloat162*)dl)[j] = __nv_bfloat162(
            __float2bfloat16(x - __bfloat162float(hx)),
            __float2bfloat16(y - __bfloat162float(hy)));
    }
}

// ---------------------------------------------------------------------------
// Flash attention with bf16-split mma.sync (unchanged from R5).
// ---------------------------------------------------------------------------
#define A_LDSB  144
#define A_TILE  (64 * A_LDSB)
#define A_STAGE (4 * A_TILE)
#define ATTN_SMEM (2 * A_STAGE)
#define AT_KH 0
#define AT_KL A_TILE
#define AT_VH (2 * A_TILE)
#define AT_VL (3 * A_TILE)

__global__ void __launch_bounds__(128)
attn_mma_kernel()
{
    extern __shared__ char smem[];
    const uint32_t sb = smem_to_u32(smem);

    const int tid  = threadIdx.x;
    const int lane = tid & 31;
    const int wid  = tid >> 5;
    const int q0   = blockIdx.x * 64;
    const int hq   = blockIdx.y;
    const int b    = blockIdx.z;
    const int kvh  = hq >> 2;
    const int r    = lane >> 2;
    const int c2   = (lane & 3) * 2;

    const size_t qoff = ((size_t)(b * NH + hq) * SEQ + q0 + wid * 16 + r) * HD;
    const __nv_bfloat16* qh0 = g_qh + qoff;
    const __nv_bfloat16* qh1 = qh0 + 8 * HD;
    const __nv_bfloat16* ql0 = g_ql + qoff;
    const __nv_bfloat16* ql1 = ql0 + 8 * HD;
    uint32_t qfh[4][4], qfl[4][4];
#pragma unroll
    for (int ks = 0; ks < 4; ks++) {
        qfh[ks][0] = *(const uint32_t*)(qh0 + ks * 16 + c2);
        qfh[ks][1] = *(const uint32_t*)(qh1 + ks * 16 + c2);
        qfh[ks][2] = *(const uint32_t*)(qh0 + ks * 16 + c2 + 8);
        qfh[ks][3] = *(const uint32_t*)(qh1 + ks * 16 + c2 + 8);
        qfl[ks][0] = *(const uint32_t*)(ql0 + ks * 16 + c2);
        qfl[ks][1] = *(const uint32_t*)(ql1 + ks * 16 + c2);
        qfl[ks][2] = *(const uint32_t*)(ql0 + ks * 16 + c2 + 8);
        qfl[ks][3] = *(const uint32_t*)(ql1 + ks * 16 + c2 + 8);
    }

    const __nv_bfloat16* kh_g = g_kh + (size_t)(b * NKV + kvh) * SEQ * HD;
    const __nv_bfloat16* kl_g = g_kl + (size_t)(b * NKV + kvh) * SEQ * HD;
    const __nv_bfloat16* vh_g = g_vh + (size_t)(b * NKV + kvh) * SEQ * HD;
    const __nv_bfloat16* vl_g = g_vl + (size_t)(b * NKV + kvh) * SEQ * HD;

    auto load_stage = [&](int st, int kt) {
        uint32_t base = sb + st * A_STAGE;
#pragma unroll
        for (int i = 0; i < 4; i++) {
            int lin = tid + i * 128;
            int row = lin >> 3;
            int c   = lin & 7;
            uint32_t sofs = (uint32_t)(row * A_LDSB + c * 16);
            size_t gofs   = (size_t)(kt + row) * HD + c * 8;
            cp_async16(base + AT_KH + sofs, kh_g + gofs);
            cp_async16(base + AT_KL + sofs, kl_g + gofs);
            cp_async16(base + AT_VH + sofs, vh_g + gofs);
            cp_async16(base + AT_VL + sofs, vl_g + gofs);
        }
        cp_commit();
    };

    const int iters = blockIdx.x + 1;
    load_stage(0, 0);

    float o[8][4];
#pragma unroll
    for (int j = 0; j < 8; j++)
#pragma unroll
        for (int t = 0; t < 4; t++) o[j][t] = 0.f;
    float m0 = -1e30f, m1 = -1e30f, l0 = 0.f, l1 = 0.f;

    const uint32_t kcore = (uint32_t)(((lane & 7) + ((lane >> 4) << 3)) * A_LDSB
                                      + ((lane >> 3) & 1) * 16);
    const uint32_t vcore = (uint32_t)((lane & 15) * A_LDSB + ((lane >> 4) << 4));

    for (int it = 0; it < iters; ++it) {
        const int kt = it * 64;
        if (it + 1 < iters) {
            load_stage((it + 1) & 1, (it + 1) * 64);
            cp_wait1();
        } else {
            cp_wait0();
        }
        __syncthreads();

        const uint32_t base = sb + (it & 1) * A_STAGE;

        float s[8][4];
#pragma unroll
        for (int j = 0; j < 8; j++)
#pragma unroll
            for (int t = 0; t < 4; t++) s[j][t] = 0.f;

#pragma unroll
        for (int kk = 0; kk < 4; kk++) {
#pragma unroll
            for (int np = 0; np < 4; np++) {
                uint32_t addr = base + AT_KH + kcore + np * 16 * A_LDSB + kk * 32;
                uint32_t kb[4], kbl[4];
                ldsm_x4(kb[0], kb[1], kb[2], kb[3], addr);
                ldsm_x4(kbl[0], kbl[1], kbl[2], kbl[3], addr + (AT_KL - AT_KH));
                int j0 = 2 * np, j1 = 2 * np + 1;
                mma16816(s[j0][0], s[j0][1], s[j0][2], s[j0][3],
                         qfh[kk][0], qfh[kk][1], qfh[kk][2], qfh[kk][3], kb[0], kb[1]);
                mma16816(s[j1][0], s[j1][1], s[j1][2], s[j1][3],
                         qfh[kk][0], qfh[kk][1], qfh[kk][2], qfh[kk][3], kb[2], kb[3]);
                mma16816(s[j0][0], s[j0][1], s[j0][2], s[j0][3],
                         qfh[kk][0], qfh[kk][1], qfh[kk][2], qfh[kk][3], kbl[0], kbl[1]);
                mma16816(s[j1][0], s[j1][1], s[j1][2], s[j1][3],
                         qfh[kk][0], qfh[kk][1], qfh[kk][2], qfh[kk][3], kbl[2], kbl[3]);
                mma16816(s[j0][0], s[j0][1], s[j0][2], s[j0][3],
                         qfl[kk][0], qfl[kk][1], qfl[kk][2], qfl[kk][3], kb[0], kb[1]);
                mma16816(s[j1][0], s[j1][1], s[j1][2], s[j1][3],
                         qfl[kk][0], qfl[kk][1], qfl[kk][2], qfl[kk][3], kb[2], kb[3]);
            }
        }

#pragma unroll
        for (int j = 0; j < 8; j++)
#pragma unroll
            for (int t = 0; t < 4; t++) s[j][t] *= ATTN_SCALE;

        if (kt == q0) {
            int row0 = q0 + wid * 16 + r;
#pragma unroll
            for (int j = 0; j < 8; j++) {
                int col = kt + j * 8 + c2;
                if (col > row0)     s[j][0] = -1e30f;
                if (col + 1 > row0) s[j][1] = -1e30f;
                if (col > row0 + 8)     s[j][2] = -1e30f;
                if (col + 1 > row0 + 8) s[j][3] = -1e30f;
            }
        }

        float mx0 = -1e30f, mx1 = -1e30f;
#pragma unroll
        for (int j = 0; j < 8; j++) {
            mx0 = fmaxf(mx0, fmaxf(s[j][0], s[j][1]));
            mx1 = fmaxf(mx1, fmaxf(s[j][2], s[j][3]));
        }
        mx0 = fmaxf(mx0, __shfl_xor_sync(0xffffffffu, mx0, 1));
        mx0 = fmaxf(mx0, __shfl_xor_sync(0xffffffffu, mx0, 2));
        mx1 = fmaxf(mx1, __shfl_xor_sync(0xffffffffu, mx1, 1));
        mx1 = fmaxf(mx1, __shfl_xor_sync(0xffffffffu, mx1, 2));

        float mn0 = fmaxf(m0, mx0), mn1 = fmaxf(m1, mx1);
        float corr0 = __expf(m0 - mn0), corr1 = __expf(m1 - mn1);
        l0 *= corr0; l1 *= corr1;
#pragma unroll
        for (int j = 0; j < 8; j++) {
            o[j][0] *= corr0; o[j][1] *= corr0;
            o[j][2] *= corr1; o[j][3] *= corr1;
        }
#pragma unroll
        for (int j = 0; j < 8; j++) {
            float p0 = __expf(s[j][0] - mn0);
            float p1 = __expf(s[j][1] - mn0);
            float p2 = __expf(s[j][2] - mn1);
            float p3 = __expf(s[j][3] - mn1);
            l0 += p0 + p1; l1 += p2 + p3;
            s[j][0] = p0; s[j][1] = p1; s[j][2] = p2; s[j][3] = p3;
        }
        m0 = mn0; m1 = mn1;

#pragma unroll
        for (int kk = 0; kk < 4; kk++) {
            uint32_t pah[4], pal[4];
            {
                float x, y;
                __nv_bfloat16 hx, hy;
                x = s[2*kk][0]; y = s[2*kk][1];
                hx = __float2bfloat16(x); hy = __float2bfloat16(y);
                pah[0] = pack_bf16x2(__bfloat162float(hx), __bfloat162float(hy));
                pal[0] = pack_bf16x2(x - __bfloat162float(hx), y - __bfloat162float(hy));
                x = s[2*kk][2]; y = s[2*kk][3];
                hx = __float2bfloat16(x); hy = __float2bfloat16(y);
                pah[1] = pack_bf16x2(__bfloat162float(hx), __bfloat162float(hy));
                pal[1] = pack_bf16x2(x - __bfloat162float(hx), y - __bfloat162float(hy));
                x = s[2*kk+1][0]; y = s[2*kk+1][1];
                hx = __float2bfloat16(x); hy = __float2bfloat16(y);
                pah[2] = pack_bf16x2(__bfloat162float(hx), __bfloat162float(hy));
                pal[2] = pack_bf16x2(x - __bfloat162float(hx), y - __bfloat162float(hy));
                x = s[2*kk+1][2]; y = s[2*kk+1][3];
                hx = __float2bfloat16(x); hy = __float2bfloat16(y);
                pah[3] = pack_bf16x2(__bfloat162float(hx), __bfloat162float(hy));
                pal[3] = pack_bf16x2(x - __bfloat162float(hx), y - __bfloat162float(hy));
            }
#pragma unroll
            for (int np = 0; np < 4; np++) {
                uint32_t addr = base + AT_VH + vcore + kk * 16 * A_LDSB + np * 32;
                uint32_t vb[4], vbl[4];
                ldsm_x4_trans(vb[0], vb[1], vb[2], vb[3], addr);
                ldsm_x4_trans(vbl[0], vbl[1], vbl[2], vbl[3], addr + (AT_VL - AT_VH));
                int j0 = 2 * np, j1 = 2 * np + 1;
                mma16816(o[j0][0], o[j0][1], o[j0][2], o[j0][3],
                         pah[0], pah[1], pah[2], pah[3], vb[0], vb[1]);
                mma16816(o[j1][0], o[j1][1], o[j1][2], o[j1][3],
                         pah[0], pah[1], pah[2], pah[3], vb[2], vb[3]);
                mma16816(o[j0][0], o[j0][1], o[j0][2], o[j0][3],
                         pah[0], pah[1], pah[2], pah[3], vbl[0], vbl[1]);
                mma16816(o[j1][0], o[j1][1], o[j1][2], o[j1][3],
                         pah[0], pah[1], pah[2], pah[3], vbl[2], vbl[3]);
                mma16816(o[j0][0], o[j0][1], o[j0][2], o[j0][3],
                         pal[0], pal[1], pal[2], pal[3], vb[0], vb[1]);
                mma16816(o[j1][0], o[j1][1], o[j1][2], o[j1][3],
                         pal[0], pal[1], pal[2], pal[3], vb[2], vb[3]);
            }
        }
        __syncthreads();
    }

    l0 += __shfl_xor_sync(0xffffffffu, l0, 1);
    l0 += __shfl_xor_sync(0xffffffffu, l0, 2);
    l1 += __shfl_xor_sync(0xffffffffu, l1, 1);
    l1 += __shfl_xor_sync(0xffffffffu, l1, 2);
    float inv0 = 1.f / l0, inv1 = 1.f / l1;

    size_t row0 = (size_t)(b * SEQ + q0 + wid * 16 + r);
    size_t row1 = row0 + 8;
#pragma unroll
    for (int j = 0; j < 8; j++) {
        int col = hq * HD + j * 8 + c2;
        float x = o[j][0] * inv0, y = o[j][1] * inv0;
        __nv_bfloat16 hx = __float2bfloat16(x), hy = __float2bfloat16(y);
        *(uint32_t*)&g_a_hi[row0 * QPOS + col] =
            pack_bf16x2(__bfloat162float(hx), __bfloat162float(hy));
        *(uint32_t*)&g_a_lo[row0 * QPOS + col] =
            pack_bf16x2(x - __bfloat162float(hx), y - __bfloat162float(hy));
        x = o[j][2] * inv1; y = o[j][3] * inv1;
        hx = __float2bfloat16(x); hy = __float2bfloat16(y);
        *(uint32_t*)&g_a_hi[row1 * QPOS + col] =
            pack_bf16x2(__bfloat162float(hx), __bfloat162float(hy));
        *(uint32_t*)&g_a_lo[row1 * QPOS + col] =
            pack_bf16x2(x - __bfloat162float(hx), y - __bfloat162float(hy));
    }
}

// ---------------------------------------------------------------------------
// kernel_launch
// ---------------------------------------------------------------------------
extern "C" void kernel_launch(void* const* d_in, const int* in_sizes, int n_in,
                              void* d_out, int out_size)
{
    const float* x    = (const float*)d_in[0];
    const float* Wqkv = (const float*)d_in[1];
    const float* Wo   = (const float*)d_in[2];
    float* out        = (float*)d_out;

    float* qkv;
    __nv_bfloat16 *xh, *xl, *wqh, *wql, *woh, *wol, *ah, *al;
    cudaGetSymbolAddress((void**)&qkv, g_qkv);
    cudaGetSymbolAddress((void**)&xh,  g_x_hi);
    cudaGetSymbolAddress((void**)&xl,  g_x_lo);
    cudaGetSymbolAddress((void**)&wqh, g_wq_hi);
    cudaGetSymbolAddress((void**)&wql, g_wq_lo);
    cudaGetSymbolAddress((void**)&woh, g_wo_hi);
    cudaGetSymbolAddress((void**)&wol, g_wo_lo);
    cudaGetSymbolAddress((void**)&ah,  g_a_hi);
    cudaGetSymbolAddress((void**)&al,  g_a_lo);

    cudaFuncSetAttribute(gemm_mma_split_kernel,
                         cudaFuncAttributeMaxDynamicSharedMemorySize, GEMM_SMEM);
    cudaFuncSetAttribute(attn_mma_kernel,
                         cudaFuncAttributeMaxDynamicSharedMemorySize, ATTN_SMEM);

    // 1) Split inputs to bf16 hi/lo
    {
        int n4 = (MTOT * DMODEL) / 4;
        split_bf16_kernel<<<(n4 + 255) / 256, 256>>>(x, xh, xl, n4);
    }
    {
        int n4 = (OPS * DMODEL) / 4;
        split_bf16_kernel<<<(n4 + 255) / 256, 256>>>(Wqkv, wqh, wql, n4);
    }
    {
        int n4 = (DMODEL * DMODEL) / 4;
        split_bf16_kernel<<<(n4 + 255) / 256, 256>>>(Wo, woh, wol, n4);
    }

    // 2) QKV projection
    {
        dim3 grid(OPS / 128, MTOT / 128);
        gemm_mma_split_kernel<<<grid, 256, GEMM_SMEM>>>(xh, xl, wqh, wql, qkv, OPS, DMODEL);
    }

    // 3) RoPE + split + per-head relayout
    {
        int nrow = MTOT * (NH + 2 * NKV);
        rope_split_kernel<<<(nrow + 255) / 256, 256>>>();
    }

    // 4) Flash attention (tensor cores), writes bf16 hi/lo directly
    {
        dim3 grid(SEQ / 64, NH, BATCH);
        attn_mma_kernel<<<grid, 128, ATTN_SMEM>>>();
    }

    // 5) O-projection
    {
        dim3 grid(DMODEL / 128, MTOT / 128);
        gemm_mma_split_kernel<<<grid, 256, GEMM_SMEM>>>(ah, al, woh, wol, out, DMODEL, DMODEL);
    }
}

// round 7
// speedup vs baseline: 3.9109x; 1.0792x over previous
#include <cuda_runtime.h>
#include <cuda_bf16.h>
#include <math.h>
#include <stdint.h>

// Problem constants
#define BATCH   2
#define SEQ     2048
#define DMODEL  2048
#define NH      32
#define NKV     8
#define HD      64
#define QPOS    (NH * HD)            // 2048
#define KVPOS   (NKV * HD)           // 512
#define OPS     (QPOS + 2 * KVPOS)   // 3072
#define MTOT    (BATCH * SEQ)        // 4096
#define ATTN_SCALE 0.125f

// ---------------------------------------------------------------------------
// Scratch (device globals: allocation-guard safe)
// ---------------------------------------------------------------------------
__device__ __nv_bfloat16 g_x_hi[MTOT * DMODEL];
__device__ __nv_bfloat16 g_x_lo[MTOT * DMODEL];
__device__ __nv_bfloat16 g_wq_hi[OPS * DMODEL];
__device__ __nv_bfloat16 g_wq_lo[OPS * DMODEL];
__device__ __nv_bfloat16 g_wo_hi[DMODEL * DMODEL];
__device__ __nv_bfloat16 g_wo_lo[DMODEL * DMODEL];
// per-head-contiguous roped q/k and v, bf16 hi/lo
__device__ __nv_bfloat16 g_qh[BATCH * NH  * SEQ * HD];
__device__ __nv_bfloat16 g_ql[BATCH * NH  * SEQ * HD];
__device__ __nv_bfloat16 g_kh[BATCH * NKV * SEQ * HD];
__device__ __nv_bfloat16 g_kl[BATCH * NKV * SEQ * HD];
__device__ __nv_bfloat16 g_vh[BATCH * NKV * SEQ * HD];
__device__ __nv_bfloat16 g_vl[BATCH * NKV * SEQ * HD];
// attention output, bf16 hi/lo (input to O-proj)
__device__ __nv_bfloat16 g_a_hi[MTOT * QPOS];
__device__ __nv_bfloat16 g_a_lo[MTOT * QPOS];
// rope cos/sin table: [l][i] -> (cos, sin)
__device__ float2 g_rope[SEQ * 32];

// ---------------------------------------------------------------------------
// helpers
// ---------------------------------------------------------------------------
__device__ __forceinline__ uint32_t smem_to_u32(const void* p) {
    uint32_t a;
    asm("{ .reg .u64 t; cvta.to.shared.u64 t, %1; cvt.u32.u64 %0, t; }"
        : "=r"(a) : "l"(p));
    return a;
}

__device__ __forceinline__ void cp_async16(uint32_t smem_dst, const void* gmem_src) {
    asm volatile("cp.async.cg.shared.global [%0], [%1], 16;"
                 :: "r"(smem_dst), "l"(gmem_src) : "memory");
}
__device__ __forceinline__ void cp_commit() {
    asm volatile("cp.async.commit_group;" ::: "memory");
}
__device__ __forceinline__ void cp_wait0() {
    asm volatile("cp.async.wait_group 0;" ::: "memory");
}

__device__ __forceinline__ void ldsm_x4(uint32_t& r0, uint32_t& r1,
                                        uint32_t& r2, uint32_t& r3, uint32_t addr) {
    asm volatile("ldmatrix.sync.aligned.m8n8.x4.shared.b16 {%0,%1,%2,%3}, [%4];"
                 : "=r"(r0), "=r"(r1), "=r"(r2), "=r"(r3) : "r"(addr));
}
__device__ __forceinline__ void ldsm_x4_trans(uint32_t& r0, uint32_t& r1,
                                              uint32_t& r2, uint32_t& r3, uint32_t addr) {
    asm volatile("ldmatrix.sync.aligned.m8n8.x4.trans.shared.b16 {%0,%1,%2,%3}, [%4];"
                 : "=r"(r0), "=r"(r1), "=r"(r2), "=r"(r3) : "r"(addr));
}

__device__ __forceinline__ void mma16816(float& d0, float& d1, float& d2, float& d3,
                                         uint32_t a0, uint32_t a1, uint32_t a2, uint32_t a3,
                                         uint32_t b0, uint32_t b1) {
    asm volatile(
        "mma.sync.aligned.m16n8k16.row.col.f32.bf16.bf16.f32 "
        "{%0,%1,%2,%3}, {%4,%5,%6,%7}, {%8,%9}, {%0,%1,%2,%3};"
        : "+f"(d0), "+f"(d1), "+f"(d2), "+f"(d3)
        : "r"(a0), "r"(a1), "r"(a2), "r"(a3), "r"(b0), "r"(b1));
}

__device__ __forceinline__ uint32_t pack_bf16x2(float x, float y) {
    __nv_bfloat162 t = __floats2bfloat162_rn(x, y);
    return *(uint32_t*)&t;
}

// write pair (x,y) as bf16 hi to ph and bf16 residual to pl (4B stores)
__device__ __forceinline__ void store_split(__nv_bfloat16* ph, __nv_bfloat16* pl,
                                            float x, float y) {
    __nv_bfloat16 hx = __float2bfloat16(x);
    __nv_bfloat16 hy = __float2bfloat16(y);
    __nv_bfloat162 h2(hx, hy);
    *(uint32_t*)ph = *(uint32_t*)&h2;
    *(uint32_t*)pl = pack_bf16x2(x - __bfloat162float(hx), y - __bfloat162float(hy));
}

// ---------------------------------------------------------------------------
// Split fp32 -> bf16 hi + bf16 lo (residual), vectorized x4
// ---------------------------------------------------------------------------
__global__ void split_bf16_kernel(const float* __restrict__ src,
                                  __nv_bfloat16* __restrict__ hi,
                                  __nv_bfloat16* __restrict__ lo, int n4)
{
    int i = blockIdx.x * blockDim.x + threadIdx.x;
    if (i >= n4) return;
    float4 v = ((const float4*)src)[i];
    __nv_bfloat16 h0 = __float2bfloat16(v.x);
    __nv_bfloat16 h1 = __float2bfloat16(v.y);
    __nv_bfloat16 h2 = __float2bfloat16(v.z);
    __nv_bfloat16 h3 = __float2bfloat16(v.w);
    __nv_bfloat16 l0 = __float2bfloat16(v.x - __bfloat162float(h0));
    __nv_bfloat16 l1 = __float2bfloat16(v.y - __bfloat162float(h1));
    __nv_bfloat16 l2 = __float2bfloat16(v.z - __bfloat162float(h2));
    __nv_bfloat16 l3 = __float2bfloat16(v.w - __bfloat162float(h3));
    __nv_bfloat162* hp = (__nv_bfloat162*)hi;
    __nv_bfloat162* lp = (__nv_bfloat162*)lo;
    hp[2 * i]     = __nv_bfloat162(h0, h1);
    hp[2 * i + 1] = __nv_bfloat162(h2, h3);
    lp[2 * i]     = __nv_bfloat162(l0, l1);
    lp[2 * i + 1] = __nv_bfloat162(l2, l3);
}

// ---------------------------------------------------------------------------
// RoPE cos/sin table
// ---------------------------------------------------------------------------
__global__ void rope_table_kernel()
{
    int idx = blockIdx.x * blockDim.x + threadIdx.x;
    if (idx >= SEQ * 32) return;
    int l = idx >> 5, i = idx & 31;
    float ang = (float)l * powf(10000.0f, -(float)(2 * i) / (float)HD);
    float s, c;
    sincosf(ang, &s, &c);
    g_rope[idx] = make_float2(c, s);
}

// ---------------------------------------------------------------------------
// mma.sync bf16-split GEMM. Block 128x128, K-chunk 32, double-buffered,
// 8 warps (4m x 2n), warp tile 32x64, 2 CTAs/SM.
// MODE 0: C = fp32 output (O-projection).
// MODE 1: QKV epilogue — apply RoPE (table), split to bf16 hi/lo, and
//         scatter per-head into g_q*/g_k*/g_v* (no fp32 C written).
// ---------------------------------------------------------------------------
#define BKC   32
#define LDSE  40
#define LDSB  (LDSE * 2)
#define TILE_B (128 * LDSB)
#define STAGE_B (4 * TILE_B)
#define GEMM_SMEM (2 * STAGE_B)       // 81920 B; x2 CTAs = 160 KB

template <int MODE>
__global__ void __launch_bounds__(256, 2)
gemm_mma_split_kernel(const __nv_bfloat16* __restrict__ Ahi,
                      const __nv_bfloat16* __restrict__ Alo,
                      const __nv_bfloat16* __restrict__ Bhi,
                      const __nv_bfloat16* __restrict__ Blo,
                      float* __restrict__ C, int N, int K)
{
    extern __shared__ char smem[];
    const uint32_t sb = smem_to_u32(smem);

    const int tid  = threadIdx.x;
    const int lane = tid & 31;
    const int wid  = tid >> 5;
    const int wm   = wid >> 1;
    const int wn   = wid & 1;
    const int bm   = blockIdx.y * 128;
    const int bn   = blockIdx.x * 128;

    const __nv_bfloat16* aH = Ahi + (size_t)bm * K;
    const __nv_bfloat16* aL = Alo + (size_t)bm * K;
    const __nv_bfloat16* bH = Bhi + (size_t)bn * K;
    const __nv_bfloat16* bL = Blo + (size_t)bn * K;

    const int r0 = tid >> 2;
    const int c0 = tid & 3;

    float acc[2][8][4];
#pragma unroll
    for (int i = 0; i < 2; i++)
#pragma unroll
        for (int j = 0; j < 8; j++)
#pragma unroll
            for (int t = 0; t < 4; t++) acc[i][j][t] = 0.f;

    const int iters = K / BKC;

    const uint32_t a_ld_off =
        (uint32_t)((wm * 32 + (lane & 15)) * LDSB + (lane >> 4) * 16);
    const uint32_t b_ld_off =
        (uint32_t)((wn * 64 + (lane & 7) + ((lane >> 4) << 3)) * LDSB
                   + ((lane >> 3) & 1) * 16);

    auto load_stage = [&](int stage, int k0) {
        uint32_t base = sb + stage * STAGE_B;
#pragma unroll
        for (int i = 0; i < 2; i++) {
            int row = r0 + i * 64;
            int c   = c0;
            uint32_t sofs = (uint32_t)(row * LDSB + c * 16);
            size_t gofs   = (size_t)row * K + k0 + c * 8;
            cp_async16(base + 0 * TILE_B + sofs, aH + gofs);
            cp_async16(base + 1 * TILE_B + sofs, aL + gofs);
            cp_async16(base + 2 * TILE_B + sofs, bH + gofs);
            cp_async16(base + 3 * TILE_B + sofs, bL + gofs);
        }
        cp_commit();
    };

    load_stage(0, 0);

    for (int it = 0; it < iters; ++it) {
        cp_wait0();
        __syncthreads();
        if (it + 1 < iters) load_stage((it + 1) & 1, (it + 1) * BKC);

        const uint32_t base = sb + (it & 1) * STAGE_B;
        const uint32_t sAH = base + 0 * TILE_B + a_ld_off;
        const uint32_t sAL = base + 1 * TILE_B + a_ld_off;
        const uint32_t sBH = base + 2 * TILE_B + b_ld_off;
        const uint32_t sBL = base + 3 * TILE_B + b_ld_off;

#pragma unroll
        for (int ks = 0; ks < 2; ks++) {
            const uint32_t kofs = ks * 32;
            uint32_t ah[2][4], al[2][4];
#pragma unroll
            for (int mt = 0; mt < 2; mt++) {
                ldsm_x4(ah[mt][0], ah[mt][1], ah[mt][2], ah[mt][3],
                        sAH + mt * 16 * LDSB + kofs);
                ldsm_x4(al[mt][0], al[mt][1], al[mt][2], al[mt][3],
                        sAL + mt * 16 * LDSB + kofs);
            }
#pragma unroll
            for (int np = 0; np < 4; np++) {
                uint32_t bh[4], bl[4];
                ldsm_x4(bh[0], bh[1], bh[2], bh[3], sBH + np * 16 * LDSB + kofs);
                ldsm_x4(bl[0], bl[1], bl[2], bl[3], sBL + np * 16 * LDSB + kofs);
                const int j0 = 2 * np, j1 = 2 * np + 1;
                // combo-outer ordering: same accumulator repeats every 4 MMAs
                // hi * hi
                mma16816(acc[0][j0][0], acc[0][j0][1], acc[0][j0][2], acc[0][j0][3],
                         ah[0][0], ah[0][1], ah[0][2], ah[0][3], bh[0], bh[1]);
                mma16816(acc[0][j1][0], acc[0][j1][1], acc[0][j1][2], acc[0][j1][3],
                         ah[0][0], ah[0][1], ah[0][2], ah[0][3], bh[2], bh[3]);
                mma16816(acc[1][j0][0], acc[1][j0][1], acc[1][j0][2], acc[1][j0][3],
                         ah[1][0], ah[1][1], ah[1][2], ah[1][3], bh[0], bh[1]);
                mma16816(acc[1][j1][0], acc[1][j1][1], acc[1][j1][2], acc[1][j1][3],
                         ah[1][0], ah[1][1], ah[1][2], ah[1][3], bh[2], bh[3]);
                // hi * lo
                mma16816(acc[0][j0][0], acc[0][j0][1], acc[0][j0][2], acc[0][j0][3],
                         ah[0][0], ah[0][1], ah[0][2], ah[0][3], bl[0], bl[1]);
                mma16816(acc[0][j1][0], acc[0][j1][1], acc[0][j1][2], acc[0][j1][3],
                         ah[0][0], ah[0][1], ah[0][2], ah[0][3], bl[2], bl[3]);
                mma16816(acc[1][j0][0], acc[1][j0][1], acc[1][j0][2], acc[1][j0][3],
                         ah[1][0], ah[1][1], ah[1][2], ah[1][3], bl[0], bl[1]);
                mma16816(acc[1][j1][0], acc[1][j1][1], acc[1][j1][2], acc[1][j1][3],
                         ah[1][0], ah[1][1], ah[1][2], ah[1][3], bl[2], bl[3]);
                // lo * hi
                mma16816(acc[0][j0][0], acc[0][j0][1], acc[0][j0][2], acc[0][j0][3],
                         al[0][0], al[0][1], al[0][2], al[0][3], bh[0], bh[1]);
                mma16816(acc[0][j1][0], acc[0][j1][1], acc[0][j1][2], acc[0][j1][3],
                         al[0][0], al[0][1], al[0][2], al[0][3], bh[2], bh[3]);
                mma16816(acc[1][j0][0], acc[1][j0][1], acc[1][j0][2], acc[1][j0][3],
                         al[1][0], al[1][1], al[1][2], al[1][3], bh[0], bh[1]);
                mma16816(acc[1][j1][0], acc[1][j1][1], acc[1][j1][2], acc[1][j1][3],
                         al[1][0], al[1][1], al[1][2], al[1][3], bh[2], bh[3]);
            }
        }
        __syncthreads();
    }

    const int c2v = (lane & 3) * 2;

    if (MODE == 0) {
        // plain fp32 store
#pragma unroll
        for (int mt = 0; mt < 2; mt++) {
            int row = bm + wm * 32 + mt * 16 + (lane >> 2);
#pragma unroll
            for (int nt = 0; nt < 8; nt++) {
                int col = bn + wn * 64 + nt * 8 + c2v;
                *(float2*)&C[(size_t)row * N + col] =
                    make_float2(acc[mt][nt][0], acc[mt][nt][1]);
                *(float2*)&C[(size_t)(row + 8) * N + col] =
                    make_float2(acc[mt][nt][2], acc[mt][nt][3]);
            }
        }
    } else {
        // QKV epilogue: rope + split + per-head scatter.
        // Warp's 64-col panel is exactly one head.
        const int head = (bn + wn * 64) >> 6;   // 0..47
#pragma unroll
        for (int mt = 0; mt < 2; mt++) {
            int grow = bm + wm * 32 + mt * 16 + (lane >> 2);
            int b = grow >> 11;          // / SEQ
            int l = grow & (SEQ - 1);
            __nv_bfloat16 *dh, *dl;
            bool rope;
            if (head < NH) {
                size_t o = ((size_t)(b * NH + head) * SEQ + l) * HD;
                dh = g_qh + o; dl = g_ql + o; rope = true;
            } else if (head < NH + NKV) {
                size_t o = ((size_t)(b * NKV + (head - NH)) * SEQ + l) * HD;
                dh = g_kh + o; dl = g_kl + o; rope = true;
            } else {
                size_t o = ((size_t)(b * NKV + (head - NH - NKV)) * SEQ + l) * HD;
                dh = g_vh + o; dl = g_vl + o; rope = false;
            }
#pragma unroll
            for (int nt = 0; nt < 4; nt++) {
                int i0 = nt * 8 + c2v;                // 0..31 (even)
                float x0 = acc[mt][nt][0],     x1 = acc[mt][nt][1];      // (l,   i0/i0+1)
                float y0 = acc[mt][nt + 4][0], y1 = acc[mt][nt + 4][1];  // (l,   i0+32/33)
                float x2 = acc[mt][nt][2],     x3 = acc[mt][nt][3];      // (l+8, i0/i0+1)
                float y2 = acc[mt][nt + 4][2], y3 = acc[mt][nt + 4][3];  // (l+8, i0+32/33)
                if (rope) {
                    float2 cs0 = g_rope[l * 32 + i0];
                    float2 cs1 = g_rope[l * 32 + i0 + 1];
                    float2 cs2 = g_rope[(l + 8) * 32 + i0];
                    float2 cs3 = g_rope[(l + 8) * 32 + i0 + 1];
                    float nx;
                    nx = x0 * cs0.x - y0 * cs0.y; y0 = y0 * cs0.x + x0 * cs0.y; x0 = nx;
                    nx = x1 * cs1.x - y1 * cs1.y; y1 = y1 * cs1.x + x1 * cs1.y; x1 = nx;
                    nx = x2 * cs2.x - y2 * cs2.y; y2 = y2 * cs2.x + x2 * cs2.y; x2 = nx;
                    nx = x3 * cs3.x - y3 * cs3.y; y3 = y3 * cs3.x + x3 * cs3.y; x3 = nx;
                }
                store_split(dh + i0,               dl + i0,               x0, x1);
                store_split(dh + i0 + 32,          dl + i0 + 32,          y0, y1);
                store_split(dh + 8 * HD + i0,      dl + 8 * HD + i0,      x2, x3);
                store_split(dh + 8 * HD + i0 + 32, dl + 8 * HD + i0 + 32, y2, y3);
            }
        }
    }
}

// ---------------------------------------------------------------------------
// Flash attention with bf16-split mma.sync.
// CTA: 64 q-rows, 4 warps (m16 each). KV tiles of 64 keys, double-buffered.
// ---------------------------------------------------------------------------
#define A_LDSB  144
#define A_TILE  (64 * A_LDSB)
#define A_STAGE (4 * A_TILE)
#define ATTN_SMEM (2 * A_STAGE)
#define AT_KH 0
#define AT_KL A_TILE
#define AT_VH (2 * A_TILE)
#define AT_VL (3 * A_TILE)

__global__ void __launch_bounds__(128)
attn_mma_kernel()
{
    extern __shared__ char smem[];
    const uint32_t sb = smem_to_u32(smem);

    const int tid  = threadIdx.x;
    const int lane = tid & 31;
    const int wid  = tid >> 5;
    const int q0   = blockIdx.x * 64;
    const int hq   = blockIdx.y;
    const int b    = blockIdx.z;
    const int kvh  = hq >> 2;
    const int r    = lane >> 2;
    const int c2   = (lane & 3) * 2;

    const size_t qoff = ((size_t)(b * NH + hq) * SEQ + q0 + wid * 16 + r) * HD;
    const __nv_bfloat16* qh0 = g_qh + qoff;
    const __nv_bfloat16* qh1 = qh0 + 8 * HD;
    const __nv_bfloat16* ql0 = g_ql + qoff;
    const __nv_bfloat16* ql1 = ql0 + 8 * HD;
    uint32_t qfh[4][4], qfl[4][4];
#pragma unroll
    for (int ks = 0; ks < 4; ks++) {
        qfh[ks][0] = *(const uint32_t*)(qh0 + ks * 16 + c2);
        qfh[ks][1] = *(const uint32_t*)(qh1 + ks * 16 + c2);
        qfh[ks][2] = *(const uint32_t*)(qh0 + ks * 16 + c2 + 8);
        qfh[ks][3] = *(const uint32_t*)(qh1 + ks * 16 + c2 + 8);
        qfl[ks][0] = *(const uint32_t*)(ql0 + ks * 16 + c2);
        qfl[ks][1] = *(const uint32_t*)(ql1 + ks * 16 + c2);
        qfl[ks][2] = *(const uint32_t*)(ql0 + ks * 16 + c2 + 8);
        qfl[ks][3] = *(const uint32_t*)(ql1 + ks * 16 + c2 + 8);
    }

    const __nv_bfloat16* kh_g = g_kh + (size_t)(b * NKV + kvh) * SEQ * HD;
    const __nv_bfloat16* kl_g = g_kl + (size_t)(b * NKV + kvh) * SEQ * HD;
    const __nv_bfloat16* vh_g = g_vh + (size_t)(b * NKV + kvh) * SEQ * HD;
    const __nv_bfloat16* vl_g = g_vl + (size_t)(b * NKV + kvh) * SEQ * HD;

    auto load_stage = [&](int st, int kt) {
        uint32_t base = sb + st * A_STAGE;
#pragma unroll
        for (int i = 0; i < 4; i++) {
            int lin = tid + i * 128;
            int row = lin >> 3;
            int c   = lin & 7;
            uint32_t sofs = (uint32_t)(row * A_LDSB + c * 16);
            size_t gofs   = (size_t)(kt + row) * HD + c * 8;
            cp_async16(base + AT_KH + sofs, kh_g + gofs);
            cp_async16(base + AT_KL + sofs, kl_g + gofs);
            cp_async16(base + AT_VH + sofs, vh_g + gofs);
            cp_async16(base + AT_VL + sofs, vl_g + gofs);
        }
        cp_commit();
    };

    const int iters = blockIdx.x + 1;
    load_stage(0, 0);

    float o[8][4];
#pragma unroll
    for (int j = 0; j < 8; j++)
#pragma unroll
        for (int t = 0; t < 4; t++) o[j][t] = 0.f;
    float m0 = -1e30f, m1 = -1e30f, l0 = 0.f, l1 = 0.f;

    const uint32_t kcore = (uint32_t)(((lane & 7) + ((lane >> 4) << 3)) * A_LDSB
                                      + ((lane >> 3) & 1) * 16);
    const uint32_t vcore = (uint32_t)((lane & 15) * A_LDSB + ((lane >> 4) << 4));

    for (int it = 0; it < iters; ++it) {
        const int kt = it * 64;
        cp_wait0();
        __syncthreads();
        if (it + 1 < iters) load_stage((it + 1) & 1, (it + 1) * 64);

        const uint32_t base = sb + (it & 1) * A_STAGE;

        float s[8][4];
#pragma unroll
        for (int j = 0; j < 8; j++)
#pragma unroll
            for (int t = 0; t < 4; t++) s[j][t] = 0.f;

#pragma unroll
        for (int kk = 0; kk < 4; kk++) {
#pragma unroll
            for (int np = 0; np < 4; np++) {
                uint32_t addr = base + AT_KH + kcore + np * 16 * A_LDSB + kk * 32;
                uint32_t kb[4], kbl[4];
                ldsm_x4(kb[0], kb[1], kb[2], kb[3], addr);
                ldsm_x4(kbl[0], kbl[1], kbl[2], kbl[3], addr + (AT_KL - AT_KH));
                int j0 = 2 * np, j1 = 2 * np + 1;
                mma16816(s[j0][0], s[j0][1], s[j0][2], s[j0][3],
                         qfh[kk][0], qfh[kk][1], qfh[kk][2], qfh[kk][3], kb[0], kb[1]);
                mma16816(s[j1][0], s[j1][1], s[j1][2], s[j1][3],
                         qfh[kk][0], qfh[kk][1], qfh[kk][2], qfh[kk][3], kb[2], kb[3]);
                mma16816(s[j0][0], s[j0][1], s[j0][2], s[j0][3],
                         qfh[kk][0], qfh[kk][1], qfh[kk][2], qfh[kk][3], kbl[0], kbl[1]);
                mma16816(s[j1][0], s[j1][1], s[j1][2], s[j1][3],
                         qfh[kk][0], qfh[kk][1], qfh[kk][2], qfh[kk][3], kbl[2], kbl[3]);
                mma16816(s[j0][0], s[j0][1], s[j0][2], s[j0][3],
                         qfl[kk][0], qfl[kk][1], qfl[kk][2], qfl[kk][3], kb[0], kb[1]);
                mma16816(s[j1][0], s[j1][1], s[j1][2], s[j1][3],
                         qfl[kk][0], qfl[kk][1], qfl[kk][2], qfl[kk][3], kb[2], kb[3]);
            }
        }

#pragma unroll
        for (int j = 0; j < 8; j++)
#pragma unroll
            for (int t = 0; t < 4; t++) s[j][t] *= ATTN_SCALE;

        if (kt == q0) {
            int row0 = q0 + wid * 16 + r;
#pragma unroll
            for (int j = 0; j < 8; j++) {
                int col = kt + j * 8 + c2;
                if (col > row0)     s[j][0] = -1e30f;
                if (col + 1 > row0) s[j][1] = -1e30f;
                if (col > row0 + 8)     s[j][2] = -1e30f;
                if (col + 1 > row0 + 8) s[j][3] = -1e30f;
            }
        }

        float mx0 = -1e30f, mx1 = -1e30f;
#pragma unroll
        for (int j = 0; j < 8; j++) {
            mx0 = fmaxf(mx0, fmaxf(s[j][0], s[j][1]));
            mx1 = fmaxf(mx1, fmaxf(s[j][2], s[j][3]));
        }
        mx0 = fmaxf(mx0, __shfl_xor_sync(0xffffffffu, mx0, 1));
        mx0 = fmaxf(mx0, __shfl_xor_sync(0xffffffffu, mx0, 2));
        mx1 = fmaxf(mx1, __shfl_xor_sync(0xffffffffu, mx1, 1));
        mx1 = fmaxf(mx1, __shfl_xor_sync(0xffffffffu, mx1, 2));

        float mn0 = fmaxf(m0, mx0), mn1 = fmaxf(m1, mx1);
        float corr0 = __expf(m0 - mn0), corr1 = __expf(m1 - mn1);
        l0 *= corr0; l1 *= corr1;
#pragma unroll
        for (int j = 0; j < 8; j++) {
            o[j][0] *= corr0; o[j][1] *= corr0;
            o[j][2] *= corr1; o[j][3] *= corr1;
        }
#pragma unroll
        for (int j = 0; j < 8; j++) {
            float p0 = __expf(s[j][0] - mn0);
            float p1 = __expf(s[j][1] - mn0);
            float p2 = __expf(s[j][2] - mn1);
            float p3 = __expf(s[j][3] - mn1);
            l0 += p0 + p1; l1 += p2 + p3;
            s[j][0] = p0; s[j][1] = p1; s[j][2] = p2; s[j][3] = p3;
        }
        m0 = mn0; m1 = mn1;

#pragma unroll
        for (int kk = 0; kk < 4; kk++) {
            uint32_t pah[4], pal[4];
            {
                float x, y;
                __nv_bfloat16 hx, hy;
                x = s[2*kk][0]; y = s[2*kk][1];
                hx = __float2bfloat16(x); hy = __float2bfloat16(y);
                pah[0] = pack_bf16x2(__bfloat162float(hx), __bfloat162float(hy));
                pal[0] = pack_bf16x2(x - __bfloat162float(hx), y - __bfloat162float(hy));
                x = s[2*kk][2]; y = s[2*kk][3];
                hx = __float2bfloat16(x); hy = __float2bfloat16(y);
                pah[1] = pack_bf16x2(__bfloat162float(hx), __bfloat162float(hy));
                pal[1] = pack_bf16x2(x - __bfloat162float(hx), y - __bfloat162float(hy));
                x = s[2*kk+1][0]; y = s[2*kk+1][1];
                hx = __float2bfloat16(x); hy = __float2bfloat16(y);
                pah[2] = pack_bf16x2(__bfloat162float(hx), __bfloat162float(hy));
                pal[2] = pack_bf16x2(x - __bfloat162float(hx), y - __bfloat162float(hy));
                x = s[2*kk+1][2]; y = s[2*kk+1][3];
                hx = __float2bfloat16(x); hy = __float2bfloat16(y);
                pah[3] = pack_bf16x2(__bfloat162float(hx), __bfloat162float(hy));
                pal[3] = pack_bf16x2(x - __bfloat162float(hx), y - __bfloat162float(hy));
            }
#pragma unroll
            for (int np = 0; np < 4; np++) {
                uint32_t addr = base + AT_VH + vcore + kk * 16 * A_LDSB + np * 32;
                uint32_t vb[4], vbl[4];
                ldsm_x4_trans(vb[0], vb[1], vb[2], vb[3], addr);
                ldsm_x4_trans(vbl[0], vbl[1], vbl[2], vbl[3], addr + (AT_VL - AT_VH));
                int j0 = 2 * np, j1 = 2 * np + 1;
                mma16816(o[j0][0], o[j0][1], o[j0][2], o[j0][3],
                         pah[0], pah[1], pah[2], pah[3], vb[0], vb[1]);
                mma16816(o[j1][0], o[j1][1], o[j1][2], o[j1][3],
                         pah[0], pah[1], pah[2], pah[3], vb[2], vb[3]);
                mma16816(o[j0][0], o[j0][1], o[j0][2], o[j0][3],
                         pah[0], pah[1], pah[2], pah[3], vbl[0], vbl[1]);
                mma16816(o[j1][0], o[j1][1], o[j1][2], o[j1][3],
                         pah[0], pah[1], pah[2], pah[3], vbl[2], vbl[3]);
                mma16816(o[j0][0], o[j0][1], o[j0][2], o[j0][3],
                         pal[0], pal[1], pal[2], pal[3], vb[0], vb[1]);
                mma16816(o[j1][0], o[j1][1], o[j1][2], o[j1][3],
                         pal[0], pal[1], pal[2], pal[3], vb[2], vb[3]);
            }
        }
    }

    l0 += __shfl_xor_sync(0xffffffffu, l0, 1);
    l0 += __shfl_xor_sync(0xffffffffu, l0, 2);
    l1 += __shfl_xor_sync(0xffffffffu, l1, 1);
    l1 += __shfl_xor_sync(0xffffffffu, l1, 2);
    float inv0 = 1.f / l0, inv1 = 1.f / l1;

    size_t row0 = (size_t)(b * SEQ + q0 + wid * 16 + r);
    size_t row1 = row0 + 8;
#pragma unroll
    for (int j = 0; j < 8; j++) {
        int col = hq * HD + j * 8 + c2;
        store_split(&g_a_hi[row0 * QPOS + col], &g_a_lo[row0 * QPOS + col],
                    o[j][0] * inv0, o[j][1] * inv0);
        store_split(&g_a_hi[row1 * QPOS + col], &g_a_lo[row1 * QPOS + col],
                    o[j][2] * inv1, o[j][3] * inv1);
    }
}

// ---------------------------------------------------------------------------
// kernel_launch
// ---------------------------------------------------------------------------
extern "C" void kernel_launch(void* const* d_in, const int* in_sizes, int n_in,
                              void* d_out, int out_size)
{
    const float* x    = (const float*)d_in[0];
    const float* Wqkv = (const float*)d_in[1];
    const float* Wo   = (const float*)d_in[2];
    float* out        = (float*)d_out;

    __nv_bfloat16 *xh, *xl, *wqh, *wql, *woh, *wol, *ah, *al;
    cudaGetSymbolAddress((void**)&xh,  g_x_hi);
    cudaGetSymbolAddress((void**)&xl,  g_x_lo);
    cudaGetSymbolAddress((void**)&wqh, g_wq_hi);
    cudaGetSymbolAddress((void**)&wql, g_wq_lo);
    cudaGetSymbolAddress((void**)&woh, g_wo_hi);
    cudaGetSymbolAddress((void**)&wol, g_wo_lo);
    cudaGetSymbolAddress((void**)&ah,  g_a_hi);
    cudaGetSymbolAddress((void**)&al,  g_a_lo);

    cudaFuncSetAttribute(gemm_mma_split_kernel<0>,
                         cudaFuncAttributeMaxDynamicSharedMemorySize, GEMM_SMEM);
    cudaFuncSetAttribute(gemm_mma_split_kernel<1>,
                         cudaFuncAttributeMaxDynamicSharedMemorySize, GEMM_SMEM);
    cudaFuncSetAttribute(attn_mma_kernel,
                         cudaFuncAttributeMaxDynamicSharedMemorySize, ATTN_SMEM);

    // 1) Split inputs to bf16 hi/lo + rope table
    {
        int n4 = (MTOT * DMODEL) / 4;
        split_bf16_kernel<<<(n4 + 255) / 256, 256>>>(x, xh, xl, n4);
    }
    {
        int n4 = (OPS * DMODEL) / 4;
        split_bf16_kernel<<<(n4 + 255) / 256, 256>>>(Wqkv, wqh, wql, n4);
    }
    {
        int n4 = (DMODEL * DMODEL) / 4;
        split_bf16_kernel<<<(n4 + 255) / 256, 256>>>(Wo, woh, wol, n4);
    }
    {
        int n = SEQ * 32;
        rope_table_kernel<<<(n + 255) / 256, 256>>>();
    }

    // 2) QKV projection with fused rope/split/relayout epilogue
    {
        dim3 grid(OPS / 128, MTOT / 128);
        gemm_mma_split_kernel<1><<<grid, 256, GEMM_SMEM>>>(
            xh, xl, wqh, wql, nullptr, OPS, DMODEL);
    }

    // 3) Flash attention (tensor cores), writes bf16 hi/lo directly
    {
        dim3 grid(SEQ / 64, NH, BATCH);
        attn_mma_kernel<<<grid, 128, ATTN_SMEM>>>();
    }

    // 4) O-projection
    {
        dim3 grid(DMODEL / 128, MTOT / 128);
        gemm_mma_split_kernel<0><<<grid, 256, GEMM_SMEM>>>(
            ah, al, woh, wol, out, DMODEL, DMODEL);
    }
}

// round 8
// speedup vs baseline: 3.9379x; 1.0069x over previous
#include <cuda_runtime.h>
#include <cuda_bf16.h>
#include <math.h>
#include <stdint.h>

// Problem constants
#define BATCH   2
#define SEQ     2048
#define DMODEL  2048
#define NH      32
#define NKV     8
#define HD      64
#define QPOS    (NH * HD)            // 2048
#define KVPOS   (NKV * HD)           // 512
#define OPS     (QPOS + 2 * KVPOS)   // 3072
#define MTOT    (BATCH * SEQ)        // 4096
#define ATTN_SCALE 0.125f

// ---------------------------------------------------------------------------
// Scratch (device globals)
// ---------------------------------------------------------------------------
__device__ __nv_bfloat16 g_x_hi[MTOT * DMODEL];
__device__ __nv_bfloat16 g_x_lo[MTOT * DMODEL];
__device__ __nv_bfloat16 g_wq_hi[OPS * DMODEL];
__device__ __nv_bfloat16 g_wq_lo[OPS * DMODEL];
__device__ __nv_bfloat16 g_wo_hi[DMODEL * DMODEL];
__device__ __nv_bfloat16 g_wo_lo[DMODEL * DMODEL];
__device__ __nv_bfloat16 g_qh[BATCH * NH  * SEQ * HD];
__device__ __nv_bfloat16 g_ql[BATCH * NH  * SEQ * HD];
__device__ __nv_bfloat16 g_kh[BATCH * NKV * SEQ * HD];
__device__ __nv_bfloat16 g_kl[BATCH * NKV * SEQ * HD];
__device__ __nv_bfloat16 g_vh[BATCH * NKV * SEQ * HD];
__device__ __nv_bfloat16 g_vl[BATCH * NKV * SEQ * HD];
__device__ __nv_bfloat16 g_a_hi[MTOT * QPOS];
__device__ __nv_bfloat16 g_a_lo[MTOT * QPOS];
__device__ float2 g_rope[SEQ * 32];

// ---------------------------------------------------------------------------
// helpers
// ---------------------------------------------------------------------------
__device__ __forceinline__ uint32_t smem_to_u32(const void* p) {
    uint32_t a;
    asm("{ .reg .u64 t; cvta.to.shared.u64 t, %1; cvt.u32.u64 %0, t; }"
        : "=r"(a) : "l"(p));
    return a;
}

__device__ __forceinline__ void cp_async16(uint32_t smem_dst, const void* gmem_src) {
    asm volatile("cp.async.cg.shared.global [%0], [%1], 16;"
                 :: "r"(smem_dst), "l"(gmem_src) : "memory");
}
__device__ __forceinline__ void cp_commit() {
    asm volatile("cp.async.commit_group;" ::: "memory");
}
__device__ __forceinline__ void cp_wait0() {
    asm volatile("cp.async.wait_group 0;" ::: "memory");
}

__device__ __forceinline__ void ldsm_x4(uint32_t& r0, uint32_t& r1,
                                        uint32_t& r2, uint32_t& r3, uint32_t addr) {
    asm volatile("ldmatrix.sync.aligned.m8n8.x4.shared.b16 {%0,%1,%2,%3}, [%4];"
                 : "=r"(r0), "=r"(r1), "=r"(r2), "=r"(r3) : "r"(addr));
}
__device__ __forceinline__ void ldsm_x4_trans(uint32_t& r0, uint32_t& r1,
                                              uint32_t& r2, uint32_t& r3, uint32_t addr) {
    asm volatile("ldmatrix.sync.aligned.m8n8.x4.trans.shared.b16 {%0,%1,%2,%3}, [%4];"
                 : "=r"(r0), "=r"(r1), "=r"(r2), "=r"(r3) : "r"(addr));
}

__device__ __forceinline__ void mma16816(float& d0, float& d1, float& d2, float& d3,
                                         uint32_t a0, uint32_t a1, uint32_t a2, uint32_t a3,
                                         uint32_t b0, uint32_t b1) {
    asm volatile(
        "mma.sync.aligned.m16n8k16.row.col.f32.bf16.bf16.f32 "
        "{%0,%1,%2,%3}, {%4,%5,%6,%7}, {%8,%9}, {%0,%1,%2,%3};"
        : "+f"(d0), "+f"(d1), "+f"(d2), "+f"(d3)
        : "r"(a0), "r"(a1), "r"(a2), "r"(a3), "r"(b0), "r"(b1));
}

__device__ __forceinline__ uint32_t pack_bf16x2(float x, float y) {
    __nv_bfloat162 t = __floats2bfloat162_rn(x, y);
    return *(uint32_t*)&t;
}

__device__ __forceinline__ void store_split(__nv_bfloat16* ph, __nv_bfloat16* pl,
                                            float x, float y) {
    __nv_bfloat16 hx = __float2bfloat16(x);
    __nv_bfloat16 hy = __float2bfloat16(y);
    __nv_bfloat162 h2(hx, hy);
    *(uint32_t*)ph = *(uint32_t*)&h2;
    *(uint32_t*)pl = pack_bf16x2(x - __bfloat162float(hx), y - __bfloat162float(hy));
}

// ---------------------------------------------------------------------------
// Split fp32 -> bf16 hi + lo
// ---------------------------------------------------------------------------
__global__ void split_bf16_kernel(const float* __restrict__ src,
                                  __nv_bfloat16* __restrict__ hi,
                                  __nv_bfloat16* __restrict__ lo, int n4)
{
    int i = blockIdx.x * blockDim.x + threadIdx.x;
    if (i >= n4) return;
    float4 v = ((const float4*)src)[i];
    __nv_bfloat16 h0 = __float2bfloat16(v.x);
    __nv_bfloat16 h1 = __float2bfloat16(v.y);
    __nv_bfloat16 h2 = __float2bfloat16(v.z);
    __nv_bfloat16 h3 = __float2bfloat16(v.w);
    __nv_bfloat16 l0 = __float2bfloat16(v.x - __bfloat162float(h0));
    __nv_bfloat16 l1 = __float2bfloat16(v.y - __bfloat162float(h1));
    __nv_bfloat16 l2 = __float2bfloat16(v.z - __bfloat162float(h2));
    __nv_bfloat16 l3 = __float2bfloat16(v.w - __bfloat162float(h3));
    __nv_bfloat162* hp = (__nv_bfloat162*)hi;
    __nv_bfloat162* lp = (__nv_bfloat162*)lo;
    hp[2 * i]     = __nv_bfloat162(h0, h1);
    hp[2 * i + 1] = __nv_bfloat162(h2, h3);
    lp[2 * i]     = __nv_bfloat162(l0, l1);
    lp[2 * i + 1] = __nv_bfloat162(l2, l3);
}

__global__ void rope_table_kernel()
{
    int idx = blockIdx.x * blockDim.x + threadIdx.x;
    if (idx >= SEQ * 32) return;
    int l = idx >> 5, i = idx & 31;
    float ang = (float)l * powf(10000.0f, -(float)(2 * i) / (float)HD);
    float s, c;
    sincosf(ang, &s, &c);
    g_rope[idx] = make_float2(c, s);
}

// ---------------------------------------------------------------------------
// mma.sync bf16-split GEMM. CTA tile 128x128, K-chunk 32, double-buffered.
// 4 warps (2m x 2n), warp tile 64x64 (85 B ldsm traffic per HMMA).
// 128 threads, 2 CTAs/SM (reg cap 256).
// MODE 0: fp32 C.  MODE 1: fused RoPE/split/per-head scatter epilogue.
// ---------------------------------------------------------------------------
#define BKC   32
#define LDSE  40
#define LDSB  (LDSE * 2)              // 80 B row stride
#define TILE_B (128 * LDSB)           // 10240 B / operand
#define STAGE_B (4 * TILE_B)          // 40960 B / stage
#define GEMM_SMEM (2 * STAGE_B)       // 81920 B

template <int MODE>
__global__ void __launch_bounds__(128, 2)
gemm_mma_split_kernel(const __nv_bfloat16* __restrict__ Ahi,
                      const __nv_bfloat16* __restrict__ Alo,
                      const __nv_bfloat16* __restrict__ Bhi,
                      const __nv_bfloat16* __restrict__ Blo,
                      float* __restrict__ C, int N, int K)
{
    extern __shared__ char smem[];
    const uint32_t sb = smem_to_u32(smem);

    const int tid  = threadIdx.x;
    const int lane = tid & 31;
    const int wid  = tid >> 5;          // 0..3
    const int wm   = wid >> 1;          // 0..1  (m 64-row group)
    const int wn   = wid & 1;           // 0..1  (n 64-col group)
    const int bm   = blockIdx.y * 128;
    const int bn   = blockIdx.x * 128;

    const __nv_bfloat16* aH = Ahi + (size_t)bm * K;
    const __nv_bfloat16* aL = Alo + (size_t)bm * K;
    const __nv_bfloat16* bH = Bhi + (size_t)bn * K;
    const __nv_bfloat16* bL = Blo + (size_t)bn * K;

    // loader mapping: 512 16B-chunks per operand tile, 128 threads -> 4 iters
    const int r0 = tid >> 2;            // rows 0..31 (+32*i)
    const int c0 = tid & 3;

    float acc[4][8][4];
#pragma unroll
    for (int i = 0; i < 4; i++)
#pragma unroll
        for (int j = 0; j < 8; j++)
#pragma unroll
            for (int t = 0; t < 4; t++) acc[i][j][t] = 0.f;

    const int iters = K / BKC;

    const uint32_t a_ld_off =
        (uint32_t)((wm * 64 + (lane & 15)) * LDSB + (lane >> 4) * 16);
    const uint32_t b_ld_off =
        (uint32_t)((wn * 64 + (lane & 7) + ((lane >> 4) << 3)) * LDSB
                   + ((lane >> 3) & 1) * 16);

    auto load_stage = [&](int stage, int k0) {
        uint32_t base = sb + stage * STAGE_B;
#pragma unroll
        for (int i = 0; i < 4; i++) {
            int row = r0 + i * 32;
            uint32_t sofs = (uint32_t)(row * LDSB + c0 * 16);
            size_t gofs   = (size_t)row * K + k0 + c0 * 8;
            cp_async16(base + 0 * TILE_B + sofs, aH + gofs);
            cp_async16(base + 1 * TILE_B + sofs, aL + gofs);
            cp_async16(base + 2 * TILE_B + sofs, bH + gofs);
            cp_async16(base + 3 * TILE_B + sofs, bL + gofs);
        }
        cp_commit();
    };

    load_stage(0, 0);

    for (int it = 0; it < iters; ++it) {
        cp_wait0();
        __syncthreads();
        if (it + 1 < iters) load_stage((it + 1) & 1, (it + 1) * BKC);

        const uint32_t base = sb + (it & 1) * STAGE_B;
        const uint32_t sAH = base + 0 * TILE_B + a_ld_off;
        const uint32_t sAL = base + 1 * TILE_B + a_ld_off;
        const uint32_t sBH = base + 2 * TILE_B + b_ld_off;
        const uint32_t sBL = base + 3 * TILE_B + b_ld_off;

#pragma unroll
        for (int ks = 0; ks < 2; ks++) {
            const uint32_t kofs = ks * 32;
            uint32_t ah[4][4], al[4][4];
#pragma unroll
            for (int mt = 0; mt < 4; mt++) {
                ldsm_x4(ah[mt][0], ah[mt][1], ah[mt][2], ah[mt][3],
                        sAH + mt * 16 * LDSB + kofs);
                ldsm_x4(al[mt][0], al[mt][1], al[mt][2], al[mt][3],
                        sAL + mt * 16 * LDSB + kofs);
            }
#pragma unroll
            for (int np = 0; np < 4; np++) {
                uint32_t bh[4], bl[4];
                ldsm_x4(bh[0], bh[1], bh[2], bh[3], sBH + np * 16 * LDSB + kofs);
                ldsm_x4(bl[0], bl[1], bl[2], bl[3], sBL + np * 16 * LDSB + kofs);
                const int j0 = 2 * np, j1 = 2 * np + 1;
                // combo-outer: same accumulator repeats at distance 8
#pragma unroll
                for (int mt = 0; mt < 4; mt++) {
                    mma16816(acc[mt][j0][0], acc[mt][j0][1], acc[mt][j0][2], acc[mt][j0][3],
                             ah[mt][0], ah[mt][1], ah[mt][2], ah[mt][3], bh[0], bh[1]);
                    mma16816(acc[mt][j1][0], acc[mt][j1][1], acc[mt][j1][2], acc[mt][j1][3],
                             ah[mt][0], ah[mt][1], ah[mt][2], ah[mt][3], bh[2], bh[3]);
                }
#pragma unroll
                for (int mt = 0; mt < 4; mt++) {
                    mma16816(acc[mt][j0][0], acc[mt][j0][1], acc[mt][j0][2], acc[mt][j0][3],
                             ah[mt][0], ah[mt][1], ah[mt][2], ah[mt][3], bl[0], bl[1]);
                    mma16816(acc[mt][j1][0], acc[mt][j1][1], acc[mt][j1][2], acc[mt][j1][3],
                             ah[mt][0], ah[mt][1], ah[mt][2], ah[mt][3], bl[2], bl[3]);
                }
#pragma unroll
                for (int mt = 0; mt < 4; mt++) {
                    mma16816(acc[mt][j0][0], acc[mt][j0][1], acc[mt][j0][2], acc[mt][j0][3],
                             al[mt][0], al[mt][1], al[mt][2], al[mt][3], bh[0], bh[1]);
                    mma16816(acc[mt][j1][0], acc[mt][j1][1], acc[mt][j1][2], acc[mt][j1][3],
                             al[mt][0], al[mt][1], al[mt][2], al[mt][3], bh[2], bh[3]);
                }
            }
        }
        __syncthreads();
    }

    const int c2v = (lane & 3) * 2;

    if (MODE == 0) {
#pragma unroll
        for (int mt = 0; mt < 4; mt++) {
            int row = bm + wm * 64 + mt * 16 + (lane >> 2);
#pragma unroll
            for (int nt = 0; nt < 8; nt++) {
                int col = bn + wn * 64 + nt * 8 + c2v;
                *(float2*)&C[(size_t)row * N + col] =
                    make_float2(acc[mt][nt][0], acc[mt][nt][1]);
                *(float2*)&C[(size_t)(row + 8) * N + col] =
                    make_float2(acc[mt][nt][2], acc[mt][nt][3]);
            }
        }
    } else {
        // QKV epilogue: rope + split + per-head scatter (warp panel = one head)
        const int head = (bn + wn * 64) >> 6;   // 0..47
#pragma unroll
        for (int mt = 0; mt < 4; mt++) {
            int grow = bm + wm * 64 + mt * 16 + (lane >> 2);
            int b = grow >> 11;
            int l = grow & (SEQ - 1);
            __nv_bfloat16 *dh, *dl;
            bool rope;
            if (head < NH) {
                size_t o = ((size_t)(b * NH + head) * SEQ + l) * HD;
                dh = g_qh + o; dl = g_ql + o; rope = true;
            } else if (head < NH + NKV) {
                size_t o = ((size_t)(b * NKV + (head - NH)) * SEQ + l) * HD;
                dh = g_kh + o; dl = g_kl + o; rope = true;
            } else {
                size_t o = ((size_t)(b * NKV + (head - NH - NKV)) * SEQ + l) * HD;
                dh = g_vh + o; dl = g_vl + o; rope = false;
            }
#pragma unroll
            for (int nt = 0; nt < 4; nt++) {
                int i0 = nt * 8 + c2v;
                float x0 = acc[mt][nt][0],     x1 = acc[mt][nt][1];
                float y0 = acc[mt][nt + 4][0], y1 = acc[mt][nt + 4][1];
                float x2 = acc[mt][nt][2],     x3 = acc[mt][nt][3];
                float y2 = acc[mt][nt + 4][2], y3 = acc[mt][nt + 4][3];
                if (rope) {
                    float2 cs0 = g_rope[l * 32 + i0];
                    float2 cs1 = g_rope[l * 32 + i0 + 1];
                    float2 cs2 = g_rope[(l + 8) * 32 + i0];
                    float2 cs3 = g_rope[(l + 8) * 32 + i0 + 1];
                    float nx;
                    nx = x0 * cs0.x - y0 * cs0.y; y0 = y0 * cs0.x + x0 * cs0.y; x0 = nx;
                    nx = x1 * cs1.x - y1 * cs1.y; y1 = y1 * cs1.x + x1 * cs1.y; x1 = nx;
                    nx = x2 * cs2.x - y2 * cs2.y; y2 = y2 * cs2.x + x2 * cs2.y; x2 = nx;
                    nx = x3 * cs3.x - y3 * cs3.y; y3 = y3 * cs3.x + x3 * cs3.y; x3 = nx;
                }
                store_split(dh + i0,               dl + i0,               x0, x1);
                store_split(dh + i0 + 32,          dl + i0 + 32,          y0, y1);
                store_split(dh + 8 * HD + i0,      dl + 8 * HD + i0,      x2, x3);
                store_split(dh + 8 * HD + i0 + 32, dl + 8 * HD + i0 + 32, y2, y3);
            }
        }
    }
}

// ---------------------------------------------------------------------------
// Flash attention with bf16-split mma.sync (unchanged from R7).
// ---------------------------------------------------------------------------
#define A_LDSB  144
#define A_TILE  (64 * A_LDSB)
#define A_STAGE (4 * A_TILE)
#define ATTN_SMEM (2 * A_STAGE)
#define AT_KH 0
#define AT_KL A_TILE
#define AT_VH (2 * A_TILE)
#define AT_VL (3 * A_TILE)

__global__ void __launch_bounds__(128)
attn_mma_kernel()
{
    extern __shared__ char smem[];
    const uint32_t sb = smem_to_u32(smem);

    const int tid  = threadIdx.x;
    const int lane = tid & 31;
    const int wid  = tid >> 5;
    const int q0   = blockIdx.x * 64;
    const int hq   = blockIdx.y;
    const int b    = blockIdx.z;
    const int kvh  = hq >> 2;
    const int r    = lane >> 2;
    const int c2   = (lane & 3) * 2;

    const size_t qoff = ((size_t)(b * NH + hq) * SEQ + q0 + wid * 16 + r) * HD;
    const __nv_bfloat16* qh0 = g_qh + qoff;
    const __nv_bfloat16* qh1 = qh0 + 8 * HD;
    const __nv_bfloat16* ql0 = g_ql + qoff;
    const __nv_bfloat16* ql1 = ql0 + 8 * HD;
    uint32_t qfh[4][4], qfl[4][4];
#pragma unroll
    for (int ks = 0; ks < 4; ks++) {
        qfh[ks][0] = *(const uint32_t*)(qh0 + ks * 16 + c2);
        qfh[ks][1] = *(const uint32_t*)(qh1 + ks * 16 + c2);
        qfh[ks][2] = *(const uint32_t*)(qh0 + ks * 16 + c2 + 8);
        qfh[ks][3] = *(const uint32_t*)(qh1 + ks * 16 + c2 + 8);
        qfl[ks][0] = *(const uint32_t*)(ql0 + ks * 16 + c2);
        qfl[ks][1] = *(const uint32_t*)(ql1 + ks * 16 + c2);
        qfl[ks][2] = *(const uint32_t*)(ql0 + ks * 16 + c2 + 8);
        qfl[ks][3] = *(const uint32_t*)(ql1 + ks * 16 + c2 + 8);
    }

    const __nv_bfloat16* kh_g = g_kh + (size_t)(b * NKV + kvh) * SEQ * HD;
    const __nv_bfloat16* kl_g = g_kl + (size_t)(b * NKV + kvh) * SEQ * HD;
    const __nv_bfloat16* vh_g = g_vh + (size_t)(b * NKV + kvh) * SEQ * HD;
    const __nv_bfloat16* vl_g = g_vl + (size_t)(b * NKV + kvh) * SEQ * HD;

    auto load_stage = [&](int st, int kt) {
        uint32_t base = sb + st * A_STAGE;
#pragma unroll
        for (int i = 0; i < 4; i++) {
            int lin = tid + i * 128;
            int row = lin >> 3;
            int c   = lin & 7;
            uint32_t sofs = (uint32_t)(row * A_LDSB + c * 16);
            size_t gofs   = (size_t)(kt + row) * HD + c * 8;
            cp_async16(base + AT_KH + sofs, kh_g + gofs);
            cp_async16(base + AT_KL + sofs, kl_g + gofs);
            cp_async16(base + AT_VH + sofs, vh_g + gofs);
            cp_async16(base + AT_VL + sofs, vl_g + gofs);
        }
        cp_commit();
    };

    const int iters = blockIdx.x + 1;
    load_stage(0, 0);

    float o[8][4];
#pragma unroll
    for (int j = 0; j < 8; j++)
#pragma unroll
        for (int t = 0; t < 4; t++) o[j][t] = 0.f;
    float m0 = -1e30f, m1 = -1e30f, l0 = 0.f, l1 = 0.f;

    const uint32_t kcore = (uint32_t)(((lane & 7) + ((lane >> 4) << 3)) * A_LDSB
                                      + ((lane >> 3) & 1) * 16);
    const uint32_t vcore = (uint32_t)((lane & 15) * A_LDSB + ((lane >> 4) << 4));

    for (int it = 0; it < iters; ++it) {
        const int kt = it * 64;
        cp_wait0();
        __syncthreads();
        if (it + 1 < iters) load_stage((it + 1) & 1, (it + 1) * 64);

        const uint32_t base = sb + (it & 1) * A_STAGE;

        float s[8][4];
#pragma unroll
        for (int j = 0; j < 8; j++)
#pragma unroll
            for (int t = 0; t < 4; t++) s[j][t] = 0.f;

#pragma unroll
        for (int kk = 0; kk < 4; kk++) {
#pragma unroll
            for (int np = 0; np < 4; np++) {
                uint32_t addr = base + AT_KH + kcore + np * 16 * A_LDSB + kk * 32;
                uint32_t kb[4], kbl[4];
                ldsm_x4(kb[0], kb[1], kb[2], kb[3], addr);
                ldsm_x4(kbl[0], kbl[1], kbl[2], kbl[3], addr + (AT_KL - AT_KH));
                int j0 = 2 * np, j1 = 2 * np + 1;
                mma16816(s[j0][0], s[j0][1], s[j0][2], s[j0][3],
                         qfh[kk][0], qfh[kk][1], qfh[kk][2], qfh[kk][3], kb[0], kb[1]);
                mma16816(s[j1][0], s[j1][1], s[j1][2], s[j1][3],
                         qfh[kk][0], qfh[kk][1], qfh[kk][2], qfh[kk][3], kb[2], kb[3]);
                mma16816(s[j0][0], s[j0][1], s[j0][2], s[j0][3],
                         qfh[kk][0], qfh[kk][1], qfh[kk][2], qfh[kk][3], kbl[0], kbl[1]);
                mma16816(s[j1][0], s[j1][1], s[j1][2], s[j1][3],
                         qfh[kk][0], qfh[kk][1], qfh[kk][2], qfh[kk][3], kbl[2], kbl[3]);
                mma16816(s[j0][0], s[j0][1], s[j0][2], s[j0][3],
                         qfl[kk][0], qfl[kk][1], qfl[kk][2], qfl[kk][3], kb[0], kb[1]);
                mma16816(s[j1][0], s[j1][1], s[j1][2], s[j1][3],
                         qfl[kk][0], qfl[kk][1], qfl[kk][2], qfl[kk][3], kb[2], kb[3]);
            }
        }

#pragma unroll
        for (int j = 0; j < 8; j++)
#pragma unroll
            for (int t = 0; t < 4; t++) s[j][t] *= ATTN_SCALE;

        if (kt == q0) {
            int row0 = q0 + wid * 16 + r;
#pragma unroll
            for (int j = 0; j < 8; j++) {
                int col = kt + j * 8 + c2;
                if (col > row0)     s[j][0] = -1e30f;
                if (col + 1 > row0) s[j][1] = -1e30f;
                if (col > row0 + 8)     s[j][2] = -1e30f;
                if (col + 1 > row0 + 8) s[j][3] = -1e30f;
            }
        }

        float mx0 = -1e30f, mx1 = -1e30f;
#pragma unroll
        for (int j = 0; j < 8; j++) {
            mx0 = fmaxf(mx0, fmaxf(s[j][0], s[j][1]));
            mx1 = fmaxf(mx1, fmaxf(s[j][2], s[j][3]));
        }
        mx0 = fmaxf(mx0, __shfl_xor_sync(0xffffffffu, mx0, 1));
        mx0 = fmaxf(mx0, __shfl_xor_sync(0xffffffffu, mx0, 2));
        mx1 = fmaxf(mx1, __shfl_xor_sync(0xffffffffu, mx1, 1));
        mx1 = fmaxf(mx1, __shfl_xor_sync(0xffffffffu, mx1, 2));

        float mn0 = fmaxf(m0, mx0), mn1 = fmaxf(m1, mx1);
        float corr0 = __expf(m0 - mn0), corr1 = __expf(m1 - mn1);
        l0 *= corr0; l1 *= corr1;
#pragma unroll
        for (int j = 0; j < 8; j++) {
            o[j][0] *= corr0; o[j][1] *= corr0;
            o[j][2] *= corr1; o[j][3] *= corr1;
        }
#pragma unroll
        for (int j = 0; j < 8; j++) {
            float p0 = __expf(s[j][0] - mn0);
            float p1 = __expf(s[j][1] - mn0);
            float p2 = __expf(s[j][2] - mn1);
            float p3 = __expf(s[j][3] - mn1);
            l0 += p0 + p1; l1 += p2 + p3;
            s[j][0] = p0; s[j][1] = p1; s[j][2] = p2; s[j][3] = p3;
        }
        m0 = mn0; m1 = mn1;

#pragma unroll
        for (int kk = 0; kk < 4; kk++) {
            uint32_t pah[4], pal[4];
            {
                float x, y;
                __nv_bfloat16 hx, hy;
                x = s[2*kk][0]; y = s[2*kk][1];
                hx = __float2bfloat16(x); hy = __float2bfloat16(y);
                pah[0] = pack_bf16x2(__bfloat162float(hx), __bfloat162float(hy));
                pal[0] = pack_bf16x2(x - __bfloat162float(hx), y - __bfloat162float(hy));
                x = s[2*kk][2]; y = s[2*kk][3];
                hx = __float2bfloat16(x); hy = __float2bfloat16(y);
                pah[1] = pack_bf16x2(__bfloat162float(hx), __bfloat162float(hy));
                pal[1] = pack_bf16x2(x - __bfloat162float(hx), y - __bfloat162float(hy));
                x = s[2*kk+1][0]; y = s[2*kk+1][1];
                hx = __float2bfloat16(x); hy = __float2bfloat16(y);
                pah[2] = pack_bf16x2(__bfloat162float(hx), __bfloat162float(hy));
                pal[2] = pack_bf16x2(x - __bfloat162float(hx), y - __bfloat162float(hy));
                x = s[2*kk+1][2]; y = s[2*kk+1][3];
                hx = __float2bfloat16(x); hy = __float2bfloat16(y);
                pah[3] = pack_bf16x2(__bfloat162float(hx), __bfloat162float(hy));
                pal[3] = pack_bf16x2(x - __bfloat162float(hx), y - __bfloat162float(hy));
            }
#pragma unroll
            for (int np = 0; np < 4; np++) {
                uint32_t addr = base + AT_VH + vcore + kk * 16 * A_LDSB + np * 32;
                uint32_t vb[4], vbl[4];
                ldsm_x4_trans(vb[0], vb[1], vb[2], vb[3], addr);
                ldsm_x4_trans(vbl[0], vbl[1], vbl[2], vbl[3], addr + (AT_VL - AT_VH));
                int j0 = 2 * np, j1 = 2 * np + 1;
                mma16816(o[j0][0], o[j0][1], o[j0][2], o[j0][3],
                         pah[0], pah[1], pah[2], pah[3], vb[0], vb[1]);
                mma16816(o[j1][0], o[j1][1], o[j1][2], o[j1][3],
                         pah[0], pah[1], pah[2], pah[3], vb[2], vb[3]);
                mma16816(o[j0][0], o[j0][1], o[j0][2], o[j0][3],
                         pah[0], pah[1], pah[2], pah[3], vbl[0], vbl[1]);
                mma16816(o[j1][0], o[j1][1], o[j1][2], o[j1][3],
                         pah[0], pah[1], pah[2], pah[3], vbl[2], vbl[3]);
                mma16816(o[j0][0], o[j0][1], o[j0][2], o[j0][3],
                         pal[0], pal[1], pal[2], pal[3], vb[0], vb[1]);
                mma16816(o[j1][0], o[j1][1], o[j1][2], o[j1][3],
                         pal[0], pal[1], pal[2], pal[3], vb[2], vb[3]);
            }
        }
    }

    l0 += __shfl_xor_sync(0xffffffffu, l0, 1);
    l0 += __shfl_xor_sync(0xffffffffu, l0, 2);
    l1 += __shfl_xor_sync(0xffffffffu, l1, 1);
    l1 += __shfl_xor_sync(0xffffffffu, l1, 2);
    float inv0 = 1.f / l0, inv1 = 1.f / l1;

    size_t row0 = (size_t)(b * SEQ + q0 + wid * 16 + r);
    size_t row1 = row0 + 8;
#pragma unroll
    for (int j = 0; j < 8; j++) {
        int col = hq * HD + j * 8 + c2;
        store_split(&g_a_hi[row0 * QPOS + col], &g_a_lo[row0 * QPOS + col],
                    o[j][0] * inv0, o[j][1] * inv0);
        store_split(&g_a_hi[row1 * QPOS + col], &g_a_lo[row1 * QPOS + col],
                    o[j][2] * inv1, o[j][3] * inv1);
    }
}

// ---------------------------------------------------------------------------
// kernel_launch
// ---------------------------------------------------------------------------
extern "C" void kernel_launch(void* const* d_in, const int* in_sizes, int n_in,
                              void* d_out, int out_size)
{
    const float* x    = (const float*)d_in[0];
    const float* Wqkv = (const float*)d_in[1];
    const float* Wo   = (const float*)d_in[2];
    float* out        = (float*)d_out;

    __nv_bfloat16 *xh, *xl, *wqh, *wql, *woh, *wol, *ah, *al;
    cudaGetSymbolAddress((void**)&xh,  g_x_hi);
    cudaGetSymbolAddress((void**)&xl,  g_x_lo);
    cudaGetSymbolAddress((void**)&wqh, g_wq_hi);
    cudaGetSymbolAddress((void**)&wql, g_wq_lo);
    cudaGetSymbolAddress((void**)&woh, g_wo_hi);
    cudaGetSymbolAddress((void**)&wol, g_wo_lo);
    cudaGetSymbolAddress((void**)&ah,  g_a_hi);
    cudaGetSymbolAddress((void**)&al,  g_a_lo);

    cudaFuncSetAttribute(gemm_mma_split_kernel<0>,
                         cudaFuncAttributeMaxDynamicSharedMemorySize, GEMM_SMEM);
    cudaFuncSetAttribute(gemm_mma_split_kernel<1>,
                         cudaFuncAttributeMaxDynamicSharedMemorySize, GEMM_SMEM);
    cudaFuncSetAttribute(attn_mma_kernel,
                         cudaFuncAttributeMaxDynamicSharedMemorySize, ATTN_SMEM);

    // 1) Splits + rope table
    {
        int n4 = (MTOT * DMODEL) / 4;
        split_bf16_kernel<<<(n4 + 255) / 256, 256>>>(x, xh, xl, n4);
    }
    {
        int n4 = (OPS * DMODEL) / 4;
        split_bf16_kernel<<<(n4 + 255) / 256, 256>>>(Wqkv, wqh, wql, n4);
    }
    {
        int n4 = (DMODEL * DMODEL) / 4;
        split_bf16_kernel<<<(n4 + 255) / 256, 256>>>(Wo, woh, wol, n4);
    }
    {
        int n = SEQ * 32;
        rope_table_kernel<<<(n + 255) / 256, 256>>>();
    }

    // 2) QKV projection with fused rope/split/relayout epilogue
    {
        dim3 grid(OPS / 128, MTOT / 128);
        gemm_mma_split_kernel<1><<<grid, 128, GEMM_SMEM>>>(
            xh, xl, wqh, wql, nullptr, OPS, DMODEL);
    }

    // 3) Flash attention
    {
        dim3 grid(SEQ / 64, NH, BATCH);
        attn_mma_kernel<<<grid, 128, ATTN_SMEM>>>();
    }

    // 4) O-projection
    {
        dim3 grid(DMODEL / 128, MTOT / 128);
        gemm_mma_split_kernel<0><<<grid, 128, GEMM_SMEM>>>(
            ah, al, woh, wol, out, DMODEL, DMODEL);
    }
}

// round 9
// speedup vs baseline: 3.9699x; 1.0081x over previous
#include <cuda_runtime.h>
#include <cuda_bf16.h>
#include <math.h>
#include <stdint.h>

// Problem constants
#define BATCH   2
#define SEQ     2048
#define DMODEL  2048
#define NH      32
#define NKV     8
#define HD      64
#define QPOS    (NH * HD)            // 2048
#define KVPOS   (NKV * HD)           // 512
#define OPS     (QPOS + 2 * KVPOS)   // 3072
#define MTOT    (BATCH * SEQ)        // 4096
#define ATTN_SCALE 0.125f

// ---------------------------------------------------------------------------
// Scratch (device globals)
// ---------------------------------------------------------------------------
__device__ __nv_bfloat16 g_x_hi[MTOT * DMODEL];
__device__ __nv_bfloat16 g_x_lo[MTOT * DMODEL];
__device__ __nv_bfloat16 g_wq_hi[OPS * DMODEL];
__device__ __nv_bfloat16 g_wq_lo[OPS * DMODEL];
__device__ __nv_bfloat16 g_wo_hi[DMODEL * DMODEL];
__device__ __nv_bfloat16 g_wo_lo[DMODEL * DMODEL];
__device__ __nv_bfloat16 g_qh[BATCH * NH  * SEQ * HD];
__device__ __nv_bfloat16 g_ql[BATCH * NH  * SEQ * HD];
__device__ __nv_bfloat16 g_kh[BATCH * NKV * SEQ * HD];
__device__ __nv_bfloat16 g_kl[BATCH * NKV * SEQ * HD];
__device__ __nv_bfloat16 g_vh[BATCH * NKV * SEQ * HD];
__device__ __nv_bfloat16 g_vl[BATCH * NKV * SEQ * HD];
__device__ __nv_bfloat16 g_a_hi[MTOT * QPOS];
__device__ __nv_bfloat16 g_a_lo[MTOT * QPOS];
__device__ float2 g_rope[SEQ * 32];

// ---------------------------------------------------------------------------
// helpers
// ---------------------------------------------------------------------------
__device__ __forceinline__ uint32_t smem_to_u32(const void* p) {
    uint32_t a;
    asm("{ .reg .u64 t; cvta.to.shared.u64 t, %1; cvt.u32.u64 %0, t; }"
        : "=r"(a) : "l"(p));
    return a;
}

__device__ __forceinline__ void cp_async16(uint32_t smem_dst, const void* gmem_src) {
    asm volatile("cp.async.cg.shared.global [%0], [%1], 16;"
                 :: "r"(smem_dst), "l"(gmem_src) : "memory");
}
__device__ __forceinline__ void cp_commit() {
    asm volatile("cp.async.commit_group;" ::: "memory");
}
__device__ __forceinline__ void cp_wait0() {
    asm volatile("cp.async.wait_group 0;" ::: "memory");
}

__device__ __forceinline__ void ldsm_x4(uint32_t& r0, uint32_t& r1,
                                        uint32_t& r2, uint32_t& r3, uint32_t addr) {
    asm volatile("ldmatrix.sync.aligned.m8n8.x4.shared.b16 {%0,%1,%2,%3}, [%4];"
                 : "=r"(r0), "=r"(r1), "=r"(r2), "=r"(r3) : "r"(addr));
}
__device__ __forceinline__ void ldsm_x4_trans(uint32_t& r0, uint32_t& r1,
                                              uint32_t& r2, uint32_t& r3, uint32_t addr) {
    asm volatile("ldmatrix.sync.aligned.m8n8.x4.trans.shared.b16 {%0,%1,%2,%3}, [%4];"
                 : "=r"(r0), "=r"(r1), "=r"(r2), "=r"(r3) : "r"(addr));
}

__device__ __forceinline__ void mma16816(float& d0, float& d1, float& d2, float& d3,
                                         uint32_t a0, uint32_t a1, uint32_t a2, uint32_t a3,
                                         uint32_t b0, uint32_t b1) {
    asm volatile(
        "mma.sync.aligned.m16n8k16.row.col.f32.bf16.bf16.f32 "
        "{%0,%1,%2,%3}, {%4,%5,%6,%7}, {%8,%9}, {%0,%1,%2,%3};"
        : "+f"(d0), "+f"(d1), "+f"(d2), "+f"(d3)
        : "r"(a0), "r"(a1), "r"(a2), "r"(a3), "r"(b0), "r"(b1));
}

__device__ __forceinline__ uint32_t pack_bf16x2(float x, float y) {
    __nv_bfloat162 t = __floats2bfloat162_rn(x, y);
    return *(uint32_t*)&t;
}

__device__ __forceinline__ void store_split(__nv_bfloat16* ph, __nv_bfloat16* pl,
                                            float x, float y) {
    __nv_bfloat16 hx = __float2bfloat16(x);
    __nv_bfloat16 hy = __float2bfloat16(y);
    __nv_bfloat162 h2(hx, hy);
    *(uint32_t*)ph = *(uint32_t*)&h2;
    *(uint32_t*)pl = pack_bf16x2(x - __bfloat162float(hx), y - __bfloat162float(hy));
}

// ---------------------------------------------------------------------------
// Split fp32 -> bf16 hi + lo
// ---------------------------------------------------------------------------
__global__ void split_bf16_kernel(const float* __restrict__ src,
                                  __nv_bfloat16* __restrict__ hi,
                                  __nv_bfloat16* __restrict__ lo, int n4)
{
    int i = blockIdx.x * blockDim.x + threadIdx.x;
    if (i >= n4) return;
    float4 v = ((const float4*)src)[i];
    __nv_bfloat16 h0 = __float2bfloat16(v.x);
    __nv_bfloat16 h1 = __float2bfloat16(v.y);
    __nv_bfloat16 h2 = __float2bfloat16(v.z);
    __nv_bfloat16 h3 = __float2bfloat16(v.w);
    __nv_bfloat16 l0 = __float2bfloat16(v.x - __bfloat162float(h0));
    __nv_bfloat16 l1 = __float2bfloat16(v.y - __bfloat162float(h1));
    __nv_bfloat16 l2 = __float2bfloat16(v.z - __bfloat162float(h2));
    __nv_bfloat16 l3 = __float2bfloat16(v.w - __bfloat162float(h3));
    __nv_bfloat162* hp = (__nv_bfloat162*)hi;
    __nv_bfloat162* lp = (__nv_bfloat162*)lo;
    hp[2 * i]     = __nv_bfloat162(h0, h1);
    hp[2 * i + 1] = __nv_bfloat162(h2, h3);
    lp[2 * i]     = __nv_bfloat162(l0, l1);
    lp[2 * i + 1] = __nv_bfloat162(l2, l3);
}

__global__ void rope_table_kernel()
{
    int idx = blockIdx.x * blockDim.x + threadIdx.x;
    if (idx >= SEQ * 32) return;
    int l = idx >> 5, i = idx & 31;
    float ang = (float)l * powf(10000.0f, -(float)(2 * i) / (float)HD);
    float s, c;
    sincosf(ang, &s, &c);
    g_rope[idx] = make_float2(c, s);
}

// ---------------------------------------------------------------------------
// mma.sync bf16-split GEMM (R8 config: 4 warps, 64x64 warp tile, 2 CTAs/SM)
// MODE 0: fp32 C.  MODE 1: fused RoPE/split/per-head scatter epilogue.
// ---------------------------------------------------------------------------
#define BKC   32
#define LDSE  40
#define LDSB  (LDSE * 2)
#define TILE_B (128 * LDSB)
#define STAGE_B (4 * TILE_B)
#define GEMM_SMEM (2 * STAGE_B)

template <int MODE>
__global__ void __launch_bounds__(128, 2)
gemm_mma_split_kernel(const __nv_bfloat16* __restrict__ Ahi,
                      const __nv_bfloat16* __restrict__ Alo,
                      const __nv_bfloat16* __restrict__ Bhi,
                      const __nv_bfloat16* __restrict__ Blo,
                      float* __restrict__ C, int N, int K)
{
    extern __shared__ char smem[];
    const uint32_t sb = smem_to_u32(smem);

    const int tid  = threadIdx.x;
    const int lane = tid & 31;
    const int wid  = tid >> 5;
    const int wm   = wid >> 1;
    const int wn   = wid & 1;
    const int bm   = blockIdx.y * 128;
    const int bn   = blockIdx.x * 128;

    const __nv_bfloat16* aH = Ahi + (size_t)bm * K;
    const __nv_bfloat16* aL = Alo + (size_t)bm * K;
    const __nv_bfloat16* bH = Bhi + (size_t)bn * K;
    const __nv_bfloat16* bL = Blo + (size_t)bn * K;

    const int r0 = tid >> 2;
    const int c0 = tid & 3;

    float acc[4][8][4];
#pragma unroll
    for (int i = 0; i < 4; i++)
#pragma unroll
        for (int j = 0; j < 8; j++)
#pragma unroll
            for (int t = 0; t < 4; t++) acc[i][j][t] = 0.f;

    const int iters = K / BKC;

    const uint32_t a_ld_off =
        (uint32_t)((wm * 64 + (lane & 15)) * LDSB + (lane >> 4) * 16);
    const uint32_t b_ld_off =
        (uint32_t)((wn * 64 + (lane & 7) + ((lane >> 4) << 3)) * LDSB
                   + ((lane >> 3) & 1) * 16);

    auto load_stage = [&](int stage, int k0) {
        uint32_t base = sb + stage * STAGE_B;
#pragma unroll
        for (int i = 0; i < 4; i++) {
            int row = r0 + i * 32;
            uint32_t sofs = (uint32_t)(row * LDSB + c0 * 16);
            size_t gofs   = (size_t)row * K + k0 + c0 * 8;
            cp_async16(base + 0 * TILE_B + sofs, aH + gofs);
            cp_async16(base + 1 * TILE_B + sofs, aL + gofs);
            cp_async16(base + 2 * TILE_B + sofs, bH + gofs);
            cp_async16(base + 3 * TILE_B + sofs, bL + gofs);
        }
        cp_commit();
    };

    load_stage(0, 0);

    for (int it = 0; it < iters; ++it) {
        cp_wait0();
        __syncthreads();
        if (it + 1 < iters) load_stage((it + 1) & 1, (it + 1) * BKC);

        const uint32_t base = sb + (it & 1) * STAGE_B;
        const uint32_t sAH = base + 0 * TILE_B + a_ld_off;
        const uint32_t sAL = base + 1 * TILE_B + a_ld_off;
        const uint32_t sBH = base + 2 * TILE_B + b_ld_off;
        const uint32_t sBL = base + 3 * TILE_B + b_ld_off;

#pragma unroll
        for (int ks = 0; ks < 2; ks++) {
            const uint32_t kofs = ks * 32;
            uint32_t ah[4][4], al[4][4];
#pragma unroll
            for (int mt = 0; mt < 4; mt++) {
                ldsm_x4(ah[mt][0], ah[mt][1], ah[mt][2], ah[mt][3],
                        sAH + mt * 16 * LDSB + kofs);
                ldsm_x4(al[mt][0], al[mt][1], al[mt][2], al[mt][3],
                        sAL + mt * 16 * LDSB + kofs);
            }
#pragma unroll
            for (int np = 0; np < 4; np++) {
                uint32_t bh[4], bl[4];
                ldsm_x4(bh[0], bh[1], bh[2], bh[3], sBH + np * 16 * LDSB + kofs);
                ldsm_x4(bl[0], bl[1], bl[2], bl[3], sBL + np * 16 * LDSB + kofs);
                const int j0 = 2 * np, j1 = 2 * np + 1;
#pragma unroll
                for (int mt = 0; mt < 4; mt++) {
                    mma16816(acc[mt][j0][0], acc[mt][j0][1], acc[mt][j0][2], acc[mt][j0][3],
                             ah[mt][0], ah[mt][1], ah[mt][2], ah[mt][3], bh[0], bh[1]);
                    mma16816(acc[mt][j1][0], acc[mt][j1][1], acc[mt][j1][2], acc[mt][j1][3],
                             ah[mt][0], ah[mt][1], ah[mt][2], ah[mt][3], bh[2], bh[3]);
                }
#pragma unroll
                for (int mt = 0; mt < 4; mt++) {
                    mma16816(acc[mt][j0][0], acc[mt][j0][1], acc[mt][j0][2], acc[mt][j0][3],
                             ah[mt][0], ah[mt][1], ah[mt][2], ah[mt][3], bl[0], bl[1]);
                    mma16816(acc[mt][j1][0], acc[mt][j1][1], acc[mt][j1][2], acc[mt][j1][3],
                             ah[mt][0], ah[mt][1], ah[mt][2], ah[mt][3], bl[2], bl[3]);
                }
#pragma unroll
                for (int mt = 0; mt < 4; mt++) {
                    mma16816(acc[mt][j0][0], acc[mt][j0][1], acc[mt][j0][2], acc[mt][j0][3],
                             al[mt][0], al[mt][1], al[mt][2], al[mt][3], bh[0], bh[1]);
                    mma16816(acc[mt][j1][0], acc[mt][j1][1], acc[mt][j1][2], acc[mt][j1][3],
                             al[mt][0], al[mt][1], al[mt][2], al[mt][3], bh[2], bh[3]);
                }
            }
        }
        __syncthreads();
    }

    const int c2v = (lane & 3) * 2;

    if (MODE == 0) {
#pragma unroll
        for (int mt = 0; mt < 4; mt++) {
            int row = bm + wm * 64 + mt * 16 + (lane >> 2);
#pragma unroll
            for (int nt = 0; nt < 8; nt++) {
                int col = bn + wn * 64 + nt * 8 + c2v;
                *(float2*)&C[(size_t)row * N + col] =
                    make_float2(acc[mt][nt][0], acc[mt][nt][1]);
                *(float2*)&C[(size_t)(row + 8) * N + col] =
                    make_float2(acc[mt][nt][2], acc[mt][nt][3]);
            }
        }
    } else {
        const int head = (bn + wn * 64) >> 6;
#pragma unroll
        for (int mt = 0; mt < 4; mt++) {
            int grow = bm + wm * 64 + mt * 16 + (lane >> 2);
            int b = grow >> 11;
            int l = grow & (SEQ - 1);
            __nv_bfloat16 *dh, *dl;
            bool rope;
            if (head < NH) {
                size_t o = ((size_t)(b * NH + head) * SEQ + l) * HD;
                dh = g_qh + o; dl = g_ql + o; rope = true;
            } else if (head < NH + NKV) {
                size_t o = ((size_t)(b * NKV + (head - NH)) * SEQ + l) * HD;
                dh = g_kh + o; dl = g_kl + o; rope = true;
            } else {
                size_t o = ((size_t)(b * NKV + (head - NH - NKV)) * SEQ + l) * HD;
                dh = g_vh + o; dl = g_vl + o; rope = false;
            }
#pragma unroll
            for (int nt = 0; nt < 4; nt++) {
                int i0 = nt * 8 + c2v;
                float x0 = acc[mt][nt][0],     x1 = acc[mt][nt][1];
                float y0 = acc[mt][nt + 4][0], y1 = acc[mt][nt + 4][1];
                float x2 = acc[mt][nt][2],     x3 = acc[mt][nt][3];
                float y2 = acc[mt][nt + 4][2], y3 = acc[mt][nt + 4][3];
                if (rope) {
                    float2 cs0 = g_rope[l * 32 + i0];
                    float2 cs1 = g_rope[l * 32 + i0 + 1];
                    float2 cs2 = g_rope[(l + 8) * 32 + i0];
                    float2 cs3 = g_rope[(l + 8) * 32 + i0 + 1];
                    float nx;
                    nx = x0 * cs0.x - y0 * cs0.y; y0 = y0 * cs0.x + x0 * cs0.y; x0 = nx;
                    nx = x1 * cs1.x - y1 * cs1.y; y1 = y1 * cs1.x + x1 * cs1.y; x1 = nx;
                    nx = x2 * cs2.x - y2 * cs2.y; y2 = y2 * cs2.x + x2 * cs2.y; x2 = nx;
                    nx = x3 * cs3.x - y3 * cs3.y; y3 = y3 * cs3.x + x3 * cs3.y; x3 = nx;
                }
                store_split(dh + i0,               dl + i0,               x0, x1);
                store_split(dh + i0 + 32,          dl + i0 + 32,          y0, y1);
                store_split(dh + 8 * HD + i0,      dl + 8 * HD + i0,      x2, x3);
                store_split(dh + 8 * HD + i0 + 32, dl + 8 * HD + i0 + 32, y2, y3);
            }
        }
    }
}

// ---------------------------------------------------------------------------
// Flash attention, bf16-split mma.sync.
// R9: 2 CTAs/SM (__launch_bounds__(128,2)); heavy (long-iter) blocks first.
// ---------------------------------------------------------------------------
#define A_LDSB  144
#define A_TILE  (64 * A_LDSB)
#define A_STAGE (4 * A_TILE)
#define ATTN_SMEM (2 * A_STAGE)       // 73728 B; x2 CTAs = 147 KB
#define AT_KH 0
#define AT_KL A_TILE
#define AT_VH (2 * A_TILE)
#define AT_VL (3 * A_TILE)

__global__ void __launch_bounds__(128, 2)
attn_mma_kernel()
{
    extern __shared__ char smem[];
    const uint32_t sb = smem_to_u32(smem);

    const int tid  = threadIdx.x;
    const int lane = tid & 31;
    const int wid  = tid >> 5;
    // Heavy blocks (most KV iterations) first for better wave balance.
    const int bx   = (int)gridDim.x - 1 - (int)blockIdx.x;
    const int q0   = bx * 64;
    const int hq   = blockIdx.y;
    const int b    = blockIdx.z;
    const int kvh  = hq >> 2;
    const int r    = lane >> 2;
    const int c2   = (lane & 3) * 2;

    const size_t qoff = ((size_t)(b * NH + hq) * SEQ + q0 + wid * 16 + r) * HD;
    const __nv_bfloat16* qh0 = g_qh + qoff;
    const __nv_bfloat16* qh1 = qh0 + 8 * HD;
    const __nv_bfloat16* ql0 = g_ql + qoff;
    const __nv_bfloat16* ql1 = ql0 + 8 * HD;
    uint32_t qfh[4][4], qfl[4][4];
#pragma unroll
    for (int ks = 0; ks < 4; ks++) {
        qfh[ks][0] = *(const uint32_t*)(qh0 + ks * 16 + c2);
        qfh[ks][1] = *(const uint32_t*)(qh1 + ks * 16 + c2);
        qfh[ks][2] = *(const uint32_t*)(qh0 + ks * 16 + c2 + 8);
        qfh[ks][3] = *(const uint32_t*)(qh1 + ks * 16 + c2 + 8);
        qfl[ks][0] = *(const uint32_t*)(ql0 + ks * 16 + c2);
        qfl[ks][1] = *(const uint32_t*)(ql1 + ks * 16 + c2);
        qfl[ks][2] = *(const uint32_t*)(ql0 + ks * 16 + c2 + 8);
        qfl[ks][3] = *(const uint32_t*)(ql1 + ks * 16 + c2 + 8);
    }

    const __nv_bfloat16* kh_g = g_kh + (size_t)(b * NKV + kvh) * SEQ * HD;
    const __nv_bfloat16* kl_g = g_kl + (size_t)(b * NKV + kvh) * SEQ * HD;
    const __nv_bfloat16* vh_g = g_vh + (size_t)(b * NKV + kvh) * SEQ * HD;
    const __nv_bfloat16* vl_g = g_vl + (size_t)(b * NKV + kvh) * SEQ * HD;

    auto load_stage = [&](int st, int kt) {
        uint32_t base = sb + st * A_STAGE;
#pragma unroll
        for (int i = 0; i < 4; i++) {
            int lin = tid + i * 128;
            int row = lin >> 3;
            int c   = lin & 7;
            uint32_t sofs = (uint32_t)(row * A_LDSB + c * 16);
            size_t gofs   = (size_t)(kt + row) * HD + c * 8;
            cp_async16(base + AT_KH + sofs, kh_g + gofs);
            cp_async16(base + AT_KL + sofs, kl_g + gofs);
            cp_async16(base + AT_VH + sofs, vh_g + gofs);
            cp_async16(base + AT_VL + sofs, vl_g + gofs);
        }
        cp_commit();
    };

    const int iters = bx + 1;
    load_stage(0, 0);

    float o[8][4];
#pragma unroll
    for (int j = 0; j < 8; j++)
#pragma unroll
        for (int t = 0; t < 4; t++) o[j][t] = 0.f;
    float m0 = -1e30f, m1 = -1e30f, l0 = 0.f, l1 = 0.f;

    const uint32_t kcore = (uint32_t)(((lane & 7) + ((lane >> 4) << 3)) * A_LDSB
                                      + ((lane >> 3) & 1) * 16);
    const uint32_t vcore = (uint32_t)((lane & 15) * A_LDSB + ((lane >> 4) << 4));

    for (int it = 0; it < iters; ++it) {
        const int kt = it * 64;
        cp_wait0();
        __syncthreads();
        if (it + 1 < iters) load_stage((it + 1) & 1, (it + 1) * 64);

        const uint32_t base = sb + (it & 1) * A_STAGE;

        float s[8][4];
#pragma unroll
        for (int j = 0; j < 8; j++)
#pragma unroll
            for (int t = 0; t < 4; t++) s[j][t] = 0.f;

#pragma unroll
        for (int kk = 0; kk < 4; kk++) {
#pragma unroll
            for (int np = 0; np < 4; np++) {
                uint32_t addr = base + AT_KH + kcore + np * 16 * A_LDSB + kk * 32;
                uint32_t kb[4], kbl[4];
                ldsm_x4(kb[0], kb[1], kb[2], kb[3], addr);
                ldsm_x4(kbl[0], kbl[1], kbl[2], kbl[3], addr + (AT_KL - AT_KH));
                int j0 = 2 * np, j1 = 2 * np + 1;
                mma16816(s[j0][0], s[j0][1], s[j0][2], s[j0][3],
                         qfh[kk][0], qfh[kk][1], qfh[kk][2], qfh[kk][3], kb[0], kb[1]);
                mma16816(s[j1][0], s[j1][1], s[j1][2], s[j1][3],
                         qfh[kk][0], qfh[kk][1], qfh[kk][2], qfh[kk][3], kb[2], kb[3]);
                mma16816(s[j0][0], s[j0][1], s[j0][2], s[j0][3],
                         qfh[kk][0], qfh[kk][1], qfh[kk][2], qfh[kk][3], kbl[0], kbl[1]);
                mma16816(s[j1][0], s[j1][1], s[j1][2], s[j1][3],
                         qfh[kk][0], qfh[kk][1], qfh[kk][2], qfh[kk][3], kbl[2], kbl[3]);
                mma16816(s[j0][0], s[j0][1], s[j0][2], s[j0][3],
                         qfl[kk][0], qfl[kk][1], qfl[kk][2], qfl[kk][3], kb[0], kb[1]);
                mma16816(s[j1][0], s[j1][1], s[j1][2], s[j1][3],
                         qfl[kk][0], qfl[kk][1], qfl[kk][2], qfl[kk][3], kb[2], kb[3]);
            }
        }

#pragma unroll
        for (int j = 0; j < 8; j++)
#pragma unroll
            for (int t = 0; t < 4; t++) s[j][t] *= ATTN_SCALE;

        if (kt == q0) {
            int row0 = q0 + wid * 16 + r;
#pragma unroll
            for (int j = 0; j < 8; j++) {
                int col = kt + j * 8 + c2;
                if (col > row0)     s[j][0] = -1e30f;
                if (col + 1 > row0) s[j][1] = -1e30f;
                if (col > row0 + 8)     s[j][2] = -1e30f;
                if (col + 1 > row0 + 8) s[j][3] = -1e30f;
            }
        }

        float mx0 = -1e30f, mx1 = -1e30f;
#pragma unroll
        for (int j = 0; j < 8; j++) {
            mx0 = fmaxf(mx0, fmaxf(s[j][0], s[j][1]));
            mx1 = fmaxf(mx1, fmaxf(s[j][2], s[j][3]));
        }
        mx0 = fmaxf(mx0, __shfl_xor_sync(0xffffffffu, mx0, 1));
        mx0 = fmaxf(mx0, __shfl_xor_sync(0xffffffffu, mx0, 2));
        mx1 = fmaxf(mx1, __shfl_xor_sync(0xffffffffu, mx1, 1));
        mx1 = fmaxf(mx1, __shfl_xor_sync(0xffffffffu, mx1, 2));

        float mn0 = fmaxf(m0, mx0), mn1 = fmaxf(m1, mx1);
        float corr0 = __expf(m0 - mn0), corr1 = __expf(m1 - mn1);
        l0 *= corr0; l1 *= corr1;
#pragma unroll
        for (int j = 0; j < 8; j++) {
            o[j][0] *= corr0; o[j][1] *= corr0;
            o[j][2] *= corr1; o[j][3] *= corr1;
        }
#pragma unroll
        for (int j = 0; j < 8; j++) {
            float p0 = __expf(s[j][0] - mn0);
            float p1 = __expf(s[j][1] - mn0);
            float p2 = __expf(s[j][2] - mn1);
            float p3 = __expf(s[j][3] - mn1);
            l0 += p0 + p1; l1 += p2 + p3;
            s[j][0] = p0; s[j][1] = p1; s[j][2] = p2; s[j][3] = p3;
        }
        m0 = mn0; m1 = mn1;

#pragma unroll
        for (int kk = 0; kk < 4; kk++) {
            uint32_t pah[4], pal[4];
            {
                float x, y;
                __nv_bfloat16 hx, hy;
                x = s[2*kk][0]; y = s[2*kk][1];
                hx = __float2bfloat16(x); hy = __float2bfloat16(y);
                pah[0] = pack_bf16x2(__bfloat162float(hx), __bfloat162float(hy));
                pal[0] = pack_bf16x2(x - __bfloat162float(hx), y - __bfloat162float(hy));
                x = s[2*kk][2]; y = s[2*kk][3];
                hx = __float2bfloat16(x); hy = __float2bfloat16(y);
                pah[1] = pack_bf16x2(__bfloat162float(hx), __bfloat162float(hy));
                pal[1] = pack_bf16x2(x - __bfloat162float(hx), y - __bfloat162float(hy));
                x = s[2*kk+1][0]; y = s[2*kk+1][1];
                hx = __float2bfloat16(x); hy = __float2bfloat16(y);
                pah[2] = pack_bf16x2(__bfloat162float(hx), __bfloat162float(hy));
                pal[2] = pack_bf16x2(x - __bfloat162float(hx), y - __bfloat162float(hy));
                x = s[2*kk+1][2]; y = s[2*kk+1][3];
                hx = __float2bfloat16(x); hy = __float2bfloat16(y);
                pah[3] = pack_bf16x2(__bfloat162float(hx), __bfloat162float(hy));
                pal[3] = pack_bf16x2(x - __bfloat162float(hx), y - __bfloat162float(hy));
            }
#pragma unroll
            for (int np = 0; np < 4; np++) {
                uint32_t addr = base + AT_VH + vcore + kk * 16 * A_LDSB + np * 32;
                uint32_t vb[4], vbl[4];
                ldsm_x4_trans(vb[0], vb[1], vb[2], vb[3], addr);
                ldsm_x4_trans(vbl[0], vbl[1], vbl[2], vbl[3], addr + (AT_VL - AT_VH));
                int j0 = 2 * np, j1 = 2 * np + 1;
                mma16816(o[j0][0], o[j0][1], o[j0][2], o[j0][3],
                         pah[0], pah[1], pah[2], pah[3], vb[0], vb[1]);
                mma16816(o[j1][0], o[j1][1], o[j1][2], o[j1][3],
                         pah[0], pah[1], pah[2], pah[3], vb[2], vb[3]);
                mma16816(o[j0][0], o[j0][1], o[j0][2], o[j0][3],
                         pah[0], pah[1], pah[2], pah[3], vbl[0], vbl[1]);
                mma16816(o[j1][0], o[j1][1], o[j1][2], o[j1][3],
                         pah[0], pah[1], pah[2], pah[3], vbl[2], vbl[3]);
                mma16816(o[j0][0], o[j0][1], o[j0][2], o[j0][3],
                         pal[0], pal[1], pal[2], pal[3], vb[0], vb[1]);
                mma16816(o[j1][0], o[j1][1], o[j1][2], o[j1][3],
                         pal[0], pal[1], pal[2], pal[3], vb[2], vb[3]);
            }
        }
    }

    l0 += __shfl_xor_sync(0xffffffffu, l0, 1);
    l0 += __shfl_xor_sync(0xffffffffu, l0, 2);
    l1 += __shfl_xor_sync(0xffffffffu, l1, 1);
    l1 += __shfl_xor_sync(0xffffffffu, l1, 2);
    float inv0 = 1.f / l0, inv1 = 1.f / l1;

    size_t row0 = (size_t)(b * SEQ + q0 + wid * 16 + r);
    size_t row1 = row0 + 8;
#pragma unroll
    for (int j = 0; j < 8; j++) {
        int col = hq * HD + j * 8 + c2;
        store_split(&g_a_hi[row0 * QPOS + col], &g_a_lo[row0 * QPOS + col],
                    o[j][0] * inv0, o[j][1] * inv0);
        store_split(&g_a_hi[row1 * QPOS + col], &g_a_lo[row1 * QPOS + col],
                    o[j][2] * inv1, o[j][3] * inv1);
    }
}

// ---------------------------------------------------------------------------
// kernel_launch
// ---------------------------------------------------------------------------
extern "C" void kernel_launch(void* const* d_in, const int* in_sizes, int n_in,
                              void* d_out, int out_size)
{
    const float* x    = (const float*)d_in[0];
    const float* Wqkv = (const float*)d_in[1];
    const float* Wo   = (const float*)d_in[2];
    float* out        = (float*)d_out;

    __nv_bfloat16 *xh, *xl, *wqh, *wql, *woh, *wol, *ah, *al;
    cudaGetSymbolAddress((void**)&xh,  g_x_hi);
    cudaGetSymbolAddress((void**)&xl,  g_x_lo);
    cudaGetSymbolAddress((void**)&wqh, g_wq_hi);
    cudaGetSymbolAddress((void**)&wql, g_wq_lo);
    cudaGetSymbolAddress((void**)&woh, g_wo_hi);
    cudaGetSymbolAddress((void**)&wol, g_wo_lo);
    cudaGetSymbolAddress((void**)&ah,  g_a_hi);
    cudaGetSymbolAddress((void**)&al,  g_a_lo);

    cudaFuncSetAttribute(gemm_mma_split_kernel<0>,
                         cudaFuncAttributeMaxDynamicSharedMemorySize, GEMM_SMEM);
    cudaFuncSetAttribute(gemm_mma_split_kernel<1>,
                         cudaFuncAttributeMaxDynamicSharedMemorySize, GEMM_SMEM);
    cudaFuncSetAttribute(attn_mma_kernel,
                         cudaFuncAttributeMaxDynamicSharedMemorySize, ATTN_SMEM);

    // 1) Splits + rope table
    {
        int n4 = (MTOT * DMODEL) / 4;
        split_bf16_kernel<<<(n4 + 255) / 256, 256>>>(x, xh, xl, n4);
    }
    {
        int n4 = (OPS * DMODEL) / 4;
        split_bf16_kernel<<<(n4 + 255) / 256, 256>>>(Wqkv, wqh, wql, n4);
    }
    {
        int n4 = (DMODEL * DMODEL) / 4;
        split_bf16_kernel<<<(n4 + 255) / 256, 256>>>(Wo, woh, wol, n4);
    }
    {
        int n = SEQ * 32;
        rope_table_kernel<<<(n + 255) / 256, 256>>>();
    }

    // 2) QKV projection with fused rope/split/relayout epilogue
    {
        dim3 grid(OPS / 128, MTOT / 128);
        gemm_mma_split_kernel<1><<<grid, 128, GEMM_SMEM>>>(
            xh, xl, wqh, wql, nullptr, OPS, DMODEL);
    }

    // 3) Flash attention (2 CTAs/SM, heavy blocks first)
    {
        dim3 grid(SEQ / 64, NH, BATCH);
        attn_mma_kernel<<<grid, 128, ATTN_SMEM>>>();
    }

    // 4) O-projection
    {
        dim3 grid(DMODEL / 128, MTOT / 128);
        gemm_mma_split_kernel<0><<<grid, 128, GEMM_SMEM>>>(
            ah, al, woh, wol, out, DMODEL, DMODEL);
    }
}

// round 10
// speedup vs baseline: 4.0204x; 1.0127x over previous
#include <cuda_runtime.h>
#include <cuda_bf16.h>
#include <math.h>
#include <stdint.h>

// Problem constants
#define BATCH   2
#define SEQ     2048
#define DMODEL  2048
#define NH      32
#define NKV     8
#define HD      64
#define QPOS    (NH * HD)            // 2048
#define KVPOS   (NKV * HD)           // 512
#define OPS     (QPOS + 2 * KVPOS)   // 3072
#define MTOT    (BATCH * SEQ)        // 4096
#define ATTN_SCALE 0.125f

// ---------------------------------------------------------------------------
// Scratch (device globals)
// ---------------------------------------------------------------------------
__device__ __nv_bfloat16 g_x_hi[MTOT * DMODEL];
__device__ __nv_bfloat16 g_x_lo[MTOT * DMODEL];
__device__ __nv_bfloat16 g_wq_hi[OPS * DMODEL];
__device__ __nv_bfloat16 g_wq_lo[OPS * DMODEL];
__device__ __nv_bfloat16 g_wo_hi[DMODEL * DMODEL];
__device__ __nv_bfloat16 g_wo_lo[DMODEL * DMODEL];
// tf32-pre-rounded fp32 roped q/k ([b][h][seq][64]) and transposed v ([b][kvh][dim][seq])
__device__ float g_qf[BATCH * NH  * SEQ * HD];
__device__ float g_kf[BATCH * NKV * SEQ * HD];
__device__ float g_vt[BATCH * NKV * HD * SEQ];
// attention output, bf16 hi/lo (input to O-proj)
__device__ __nv_bfloat16 g_a_hi[MTOT * QPOS];
__device__ __nv_bfloat16 g_a_lo[MTOT * QPOS];
__device__ float2 g_rope[SEQ * 32];

// ---------------------------------------------------------------------------
// helpers
// ---------------------------------------------------------------------------
__device__ __forceinline__ uint32_t smem_to_u32(const void* p) {
    uint32_t a;
    asm("{ .reg .u64 t; cvta.to.shared.u64 t, %1; cvt.u32.u64 %0, t; }"
        : "=r"(a) : "l"(p));
    return a;
}

__device__ __forceinline__ void cp_async16(uint32_t smem_dst, const void* gmem_src) {
    asm volatile("cp.async.cg.shared.global [%0], [%1], 16;"
                 :: "r"(smem_dst), "l"(gmem_src) : "memory");
}
__device__ __forceinline__ void cp_commit() {
    asm volatile("cp.async.commit_group;" ::: "memory");
}
__device__ __forceinline__ void cp_wait0() {
    asm volatile("cp.async.wait_group 0;" ::: "memory");
}

__device__ __forceinline__ void ldsm_x4(uint32_t& r0, uint32_t& r1,
                                        uint32_t& r2, uint32_t& r3, uint32_t addr) {
    asm volatile("ldmatrix.sync.aligned.m8n8.x4.shared.b16 {%0,%1,%2,%3}, [%4];"
                 : "=r"(r0), "=r"(r1), "=r"(r2), "=r"(r3) : "r"(addr));
}

__device__ __forceinline__ void mma16816(float& d0, float& d1, float& d2, float& d3,
                                         uint32_t a0, uint32_t a1, uint32_t a2, uint32_t a3,
                                         uint32_t b0, uint32_t b1) {
    asm volatile(
        "mma.sync.aligned.m16n8k16.row.col.f32.bf16.bf16.f32 "
        "{%0,%1,%2,%3}, {%4,%5,%6,%7}, {%8,%9}, {%0,%1,%2,%3};"
        : "+f"(d0), "+f"(d1), "+f"(d2), "+f"(d3)
        : "r"(a0), "r"(a1), "r"(a2), "r"(a3), "r"(b0), "r"(b1));
}

// tf32 mma m16n8k8 (operands are pre-rounded fp32 bit patterns)
__device__ __forceinline__ void mma_tf32(float& d0, float& d1, float& d2, float& d3,
                                         uint32_t a0, uint32_t a1, uint32_t a2, uint32_t a3,
                                         uint32_t b0, uint32_t b1) {
    asm volatile(
        "mma.sync.aligned.m16n8k8.row.col.f32.tf32.tf32.f32 "
        "{%0,%1,%2,%3}, {%4,%5,%6,%7}, {%8,%9}, {%0,%1,%2,%3};"
        : "+f"(d0), "+f"(d1), "+f"(d2), "+f"(d3)
        : "r"(a0), "r"(a1), "r"(a2), "r"(a3), "r"(b0), "r"(b1));
}

// round-to-nearest tf32 (unbiased; truncation would bias results)
__device__ __forceinline__ float tf32r(float x) {
    float y;
    asm("cvt.rna.tf32.f32 %0, %1;" : "=f"(y) : "f"(x));
    return y;
}

__device__ __forceinline__ uint32_t pack_bf16x2(float x, float y) {
    __nv_bfloat162 t = __floats2bfloat162_rn(x, y);
    return *(uint32_t*)&t;
}

__device__ __forceinline__ void store_split(__nv_bfloat16* ph, __nv_bfloat16* pl,
                                            float x, float y) {
    __nv_bfloat16 hx = __float2bfloat16(x);
    __nv_bfloat16 hy = __float2bfloat16(y);
    __nv_bfloat162 h2(hx, hy);
    *(uint32_t*)ph = *(uint32_t*)&h2;
    *(uint32_t*)pl = pack_bf16x2(x - __bfloat162float(hx), y - __bfloat162float(hy));
}

// ---------------------------------------------------------------------------
// Split fp32 -> bf16 hi + lo
// ---------------------------------------------------------------------------
__global__ void split_bf16_kernel(const float* __restrict__ src,
                                  __nv_bfloat16* __restrict__ hi,
                                  __nv_bfloat16* __restrict__ lo, int n4)
{
    int i = blockIdx.x * blockDim.x + threadIdx.x;
    if (i >= n4) return;
    float4 v = ((const float4*)src)[i];
    __nv_bfloat16 h0 = __float2bfloat16(v.x);
    __nv_bfloat16 h1 = __float2bfloat16(v.y);
    __nv_bfloat16 h2 = __float2bfloat16(v.z);
    __nv_bfloat16 h3 = __float2bfloat16(v.w);
    __nv_bfloat16 l0 = __float2bfloat16(v.x - __bfloat162float(h0));
    __nv_bfloat16 l1 = __float2bfloat16(v.y - __bfloat162float(h1));
    __nv_bfloat16 l2 = __float2bfloat16(v.z - __bfloat162float(h2));
    __nv_bfloat16 l3 = __float2bfloat16(v.w - __bfloat162float(h3));
    __nv_bfloat162* hp = (__nv_bfloat162*)hi;
    __nv_bfloat162* lp = (__nv_bfloat162*)lo;
    hp[2 * i]     = __nv_bfloat162(h0, h1);
    hp[2 * i + 1] = __nv_bfloat162(h2, h3);
    lp[2 * i]     = __nv_bfloat162(l0, l1);
    lp[2 * i + 1] = __nv_bfloat162(l2, l3);
}

__global__ void rope_table_kernel()
{
    int idx = blockIdx.x * blockDim.x + threadIdx.x;
    if (idx >= SEQ * 32) return;
    int l = idx >> 5, i = idx & 31;
    float ang = (float)l * powf(10000.0f, -(float)(2 * i) / (float)HD);
    float s, c;
    sincosf(ang, &s, &c);
    g_rope[idx] = make_float2(c, s);
}

// ---------------------------------------------------------------------------
// mma.sync bf16-split GEMM (4 warps, 64x64 warp tile, 2 CTAs/SM)
// MODE 0: fp32 C (O-projection).
// MODE 1: QKV epilogue — RoPE, tf32-round, per-head scatter:
//         q/k -> fp32 [b][h][seq][64]; v -> fp32 transposed [b][kvh][dim][seq].
// ---------------------------------------------------------------------------
#define BKC   32
#define LDSE  40
#define LDSB  (LDSE * 2)
#define TILE_B (128 * LDSB)
#define STAGE_B (4 * TILE_B)
#define GEMM_SMEM (2 * STAGE_B)

template <int MODE>
__global__ void __launch_bounds__(128, 2)
gemm_mma_split_kernel(const __nv_bfloat16* __restrict__ Ahi,
                      const __nv_bfloat16* __restrict__ Alo,
                      const __nv_bfloat16* __restrict__ Bhi,
                      const __nv_bfloat16* __restrict__ Blo,
                      float* __restrict__ C, int N, int K)
{
    extern __shared__ char smem[];
    const uint32_t sb = smem_to_u32(smem);

    const int tid  = threadIdx.x;
    const int lane = tid & 31;
    const int wid  = tid >> 5;
    const int wm   = wid >> 1;
    const int wn   = wid & 1;
    const int bm   = blockIdx.y * 128;
    const int bn   = blockIdx.x * 128;

    const __nv_bfloat16* aH = Ahi + (size_t)bm * K;
    const __nv_bfloat16* aL = Alo + (size_t)bm * K;
    const __nv_bfloat16* bH = Bhi + (size_t)bn * K;
    const __nv_bfloat16* bL = Blo + (size_t)bn * K;

    const int r0 = tid >> 2;
    const int c0 = tid & 3;

    float acc[4][8][4];
#pragma unroll
    for (int i = 0; i < 4; i++)
#pragma unroll
        for (int j = 0; j < 8; j++)
#pragma unroll
            for (int t = 0; t < 4; t++) acc[i][j][t] = 0.f;

    const int iters = K / BKC;

    const uint32_t a_ld_off =
        (uint32_t)((wm * 64 + (lane & 15)) * LDSB + (lane >> 4) * 16);
    const uint32_t b_ld_off =
        (uint32_t)((wn * 64 + (lane & 7) + ((lane >> 4) << 3)) * LDSB
                   + ((lane >> 3) & 1) * 16);

    auto load_stage = [&](int stage, int k0) {
        uint32_t base = sb + stage * STAGE_B;
#pragma unroll
        for (int i = 0; i < 4; i++) {
            int row = r0 + i * 32;
            uint32_t sofs = (uint32_t)(row * LDSB + c0 * 16);
            size_t gofs   = (size_t)row * K + k0 + c0 * 8;
            cp_async16(base + 0 * TILE_B + sofs, aH + gofs);
            cp_async16(base + 1 * TILE_B + sofs, aL + gofs);
            cp_async16(base + 2 * TILE_B + sofs, bH + gofs);
            cp_async16(base + 3 * TILE_B + sofs, bL + gofs);
        }
        cp_commit();
    };

    load_stage(0, 0);

    for (int it = 0; it < iters; ++it) {
        cp_wait0();
        __syncthreads();
        if (it + 1 < iters) load_stage((it + 1) & 1, (it + 1) * BKC);

        const uint32_t base = sb + (it & 1) * STAGE_B;
        const uint32_t sAH = base + 0 * TILE_B + a_ld_off;
        const uint32_t sAL = base + 1 * TILE_B + a_ld_off;
        const uint32_t sBH = base + 2 * TILE_B + b_ld_off;
        const uint32_t sBL = base + 3 * TILE_B + b_ld_off;

#pragma unroll
        for (int ks = 0; ks < 2; ks++) {
            const uint32_t kofs = ks * 32;
            uint32_t ah[4][4], al[4][4];
#pragma unroll
            for (int mt = 0; mt < 4; mt++) {
                ldsm_x4(ah[mt][0], ah[mt][1], ah[mt][2], ah[mt][3],
                        sAH + mt * 16 * LDSB + kofs);
                ldsm_x4(al[mt][0], al[mt][1], al[mt][2], al[mt][3],
                        sAL + mt * 16 * LDSB + kofs);
            }
#pragma unroll
            for (int np = 0; np < 4; np++) {
                uint32_t bh[4], bl[4];
                ldsm_x4(bh[0], bh[1], bh[2], bh[3], sBH + np * 16 * LDSB + kofs);
                ldsm_x4(bl[0], bl[1], bl[2], bl[3], sBL + np * 16 * LDSB + kofs);
                const int j0 = 2 * np, j1 = 2 * np + 1;
#pragma unroll
                for (int mt = 0; mt < 4; mt++) {
                    mma16816(acc[mt][j0][0], acc[mt][j0][1], acc[mt][j0][2], acc[mt][j0][3],
                             ah[mt][0], ah[mt][1], ah[mt][2], ah[mt][3], bh[0], bh[1]);
                    mma16816(acc[mt][j1][0], acc[mt][j1][1], acc[mt][j1][2], acc[mt][j1][3],
                             ah[mt][0], ah[mt][1], ah[mt][2], ah[mt][3], bh[2], bh[3]);
                }
#pragma unroll
                for (int mt = 0; mt < 4; mt++) {
                    mma16816(acc[mt][j0][0], acc[mt][j0][1], acc[mt][j0][2], acc[mt][j0][3],
                             ah[mt][0], ah[mt][1], ah[mt][2], ah[mt][3], bl[0], bl[1]);
                    mma16816(acc[mt][j1][0], acc[mt][j1][1], acc[mt][j1][2], acc[mt][j1][3],
                             ah[mt][0], ah[mt][1], ah[mt][2], ah[mt][3], bl[2], bl[3]);
                }
#pragma unroll
                for (int mt = 0; mt < 4; mt++) {
                    mma16816(acc[mt][j0][0], acc[mt][j0][1], acc[mt][j0][2], acc[mt][j0][3],
                             al[mt][0], al[mt][1], al[mt][2], al[mt][3], bh[0], bh[1]);
                    mma16816(acc[mt][j1][0], acc[mt][j1][1], acc[mt][j1][2], acc[mt][j1][3],
                             al[mt][0], al[mt][1], al[mt][2], al[mt][3], bh[2], bh[3]);
                }
            }
        }
        __syncthreads();
    }

    const int c2v = (lane & 3) * 2;

    if (MODE == 0) {
#pragma unroll
        for (int mt = 0; mt < 4; mt++) {
            int row = bm + wm * 64 + mt * 16 + (lane >> 2);
#pragma unroll
            for (int nt = 0; nt < 8; nt++) {
                int col = bn + wn * 64 + nt * 8 + c2v;
                *(float2*)&C[(size_t)row * N + col] =
                    make_float2(acc[mt][nt][0], acc[mt][nt][1]);
                *(float2*)&C[(size_t)(row + 8) * N + col] =
                    make_float2(acc[mt][nt][2], acc[mt][nt][3]);
            }
        }
    } else {
        // QKV epilogue: rope + tf32-round + per-head scatter.
        const int head = (bn + wn * 64) >> 6;   // 0..47
#pragma unroll
        for (int mt = 0; mt < 4; mt++) {
            int grow = bm + wm * 64 + mt * 16 + (lane >> 2);
            int b = grow >> 11;
            int l = grow & (SEQ - 1);
            float* dq = nullptr;      // row-major dest (q/k)
            float* dv = nullptr;      // transposed dest base (v)
            bool rope = false;
            if (head < NH) {
                dq = g_qf + ((size_t)(b * NH + head) * SEQ + l) * HD;
                rope = true;
            } else if (head < NH + NKV) {
                dq = g_kf + ((size_t)(b * NKV + (head - NH)) * SEQ + l) * HD;
                rope = true;
            } else {
                dv = g_vt + (size_t)(b * NKV + (head - NH - NKV)) * HD * SEQ;
            }
#pragma unroll
            for (int nt = 0; nt < 4; nt++) {
                int i0 = nt * 8 + c2v;
                float x0 = acc[mt][nt][0],     x1 = acc[mt][nt][1];
                float y0 = acc[mt][nt + 4][0], y1 = acc[mt][nt + 4][1];
                float x2 = acc[mt][nt][2],     x3 = acc[mt][nt][3];
                float y2 = acc[mt][nt + 4][2], y3 = acc[mt][nt + 4][3];
                if (rope) {
                    float2 cs0 = g_rope[l * 32 + i0];
                    float2 cs1 = g_rope[l * 32 + i0 + 1];
                    float2 cs2 = g_rope[(l + 8) * 32 + i0];
                    float2 cs3 = g_rope[(l + 8) * 32 + i0 + 1];
                    float nx;
                    nx = x0 * cs0.x - y0 * cs0.y; y0 = y0 * cs0.x + x0 * cs0.y; x0 = nx;
                    nx = x1 * cs1.x - y1 * cs1.y; y1 = y1 * cs1.x + x1 * cs1.y; x1 = nx;
                    nx = x2 * cs2.x - y2 * cs2.y; y2 = y2 * cs2.x + x2 * cs2.y; x2 = nx;
                    nx = x3 * cs3.x - y3 * cs3.y; y3 = y3 * cs3.x + x3 * cs3.y; x3 = nx;
                }
                x0 = tf32r(x0); x1 = tf32r(x1); x2 = tf32r(x2); x3 = tf32r(x3);
                y0 = tf32r(y0); y1 = tf32r(y1); y2 = tf32r(y2); y3 = tf32r(y3);
                if (dq) {
                    *(float2*)(dq + i0)               = make_float2(x0, x1);
                    *(float2*)(dq + i0 + 32)          = make_float2(y0, y1);
                    *(float2*)(dq + 8 * HD + i0)      = make_float2(x2, x3);
                    *(float2*)(dq + 8 * HD + i0 + 32) = make_float2(y2, y3);
                } else {
                    dv[(size_t)(i0)      * SEQ + l]     = x0;
                    dv[(size_t)(i0 + 1)  * SEQ + l]     = x1;
                    dv[(size_t)(i0 + 32) * SEQ + l]     = y0;
                    dv[(size_t)(i0 + 33) * SEQ + l]     = y1;
                    dv[(size_t)(i0)      * SEQ + l + 8] = x2;
                    dv[(size_t)(i0 + 1)  * SEQ + l + 8] = x3;
                    dv[(size_t)(i0 + 32) * SEQ + l + 8] = y2;
                    dv[(size_t)(i0 + 33) * SEQ + l + 8] = y3;
                }
            }
        }
    }
}

// ---------------------------------------------------------------------------
// Flash attention, single-pass tf32 mma (m16n8k8), fp32 accumulate.
// CTA: 64 q-rows, 4 warps (m16 each). KV tiles of 64 keys, double-buffered.
// K in smem [key][dim] (68-float rows), V in smem TRANSPOSED [dim][key].
// ---------------------------------------------------------------------------
#define AS_LD   68                        // floats per smem row (conflict-free)
#define AS_ROW  (AS_LD * 4)               // 272 B
#define AS_TILE (64 * AS_ROW)             // 17408 B
#define AS_STAGE (2 * AS_TILE)            // K + V = 34816 B
#define ATTN_SMEM (2 * AS_STAGE)          // 69632 B; x2 CTAs = 139 KB

__global__ void __launch_bounds__(128, 2)
attn_tf32_kernel()
{
    extern __shared__ char smem[];
    const uint32_t sb = smem_to_u32(smem);

    const int tid  = threadIdx.x;
    const int lane = tid & 31;
    const int wid  = tid >> 5;
    const int bx   = (int)gridDim.x - 1 - (int)blockIdx.x;   // heavy blocks first
    const int q0   = bx * 64;
    const int hq   = blockIdx.y;
    const int b    = blockIdx.z;
    const int kvh  = hq >> 2;
    const int r    = lane >> 2;           // group id (row within m16 half)
    const int ctg  = lane & 3;            // thread in group
    const int c2   = ctg * 2;

    // Q fragments (pre-rounded tf32 fp32), m16n8k8 A layout:
    // a0=(r,c) a1=(r+8,c) a2=(r,c+4) a3=(r+8,c+4), c = ks*8 + ctg
    const float* qp = g_qf + ((size_t)(b * NH + hq) * SEQ + q0 + wid * 16 + r) * HD;
    uint32_t qa[8][4];
#pragma unroll
    for (int ks = 0; ks < 8; ks++) {
        int c = ks * 8 + ctg;
        qa[ks][0] = __float_as_uint(qp[c]);
        qa[ks][1] = __float_as_uint(qp[8 * HD + c]);
        qa[ks][2] = __float_as_uint(qp[c + 4]);
        qa[ks][3] = __float_as_uint(qp[8 * HD + c + 4]);
    }

    const float* kg = g_kf + (size_t)(b * NKV + kvh) * SEQ * HD;   // [key][dim]
    const float* vg = g_vt + (size_t)(b * NKV + kvh) * HD * SEQ;   // [dim][seq]

    auto load_stage = [&](int st, int kt) {
        uint32_t base = sb + st * AS_STAGE;
#pragma unroll
        for (int i = 0; i < 8; i++) {
            int lin = tid + i * 128;          // 0..1023
            int row = lin >> 4;               // 0..63
            int c   = lin & 15;               // 16B chunk
            cp_async16(base + (uint32_t)(row * AS_ROW + c * 16),
                       kg + (size_t)(kt + row) * HD + c * 4);
            cp_async16(base + AS_TILE + (uint32_t)(row * AS_ROW + c * 16),
                       vg + (size_t)row * SEQ + kt + c * 4);
        }
        cp_commit();
    };

    const int iters = bx + 1;
    load_stage(0, 0);

    float o[8][4];
#pragma unroll
    for (int j = 0; j < 8; j++)
#pragma unroll
        for (int t = 0; t < 4; t++) o[j][t] = 0.f;
    float m0 = -1e30f, m1 = -1e30f, l0 = 0.f, l1 = 0.f;

    // shuffle source lanes for P A-fragment construction
    const int P0 = (lane & 28) | (ctg >> 1);
    const int P2 = (lane & 28) | ((ctg >> 1) + 2);
    const bool oddl = (lane & 1);

    for (int it = 0; it < iters; ++it) {
        const int kt = it * 64;
        cp_wait0();
        __syncthreads();
        if (it + 1 < iters) load_stage((it + 1) & 1, (it + 1) * 64);

        const float* Ks = (const float*)(smem + (it & 1) * AS_STAGE);
        const float* Vt = Ks + AS_TILE / 4;

        // ---- S = Q K^T (tf32, single pass)
        float s[8][4];
#pragma unroll
        for (int j = 0; j < 8; j++)
#pragma unroll
            for (int t = 0; t < 4; t++) s[j][t] = 0.f;

#pragma unroll
        for (int ks = 0; ks < 8; ks++) {
#pragma unroll
            for (int np = 0; np < 8; np++) {
                const float* kr = Ks + (np * 8 + r) * AS_LD + ks * 8 + ctg;
                uint32_t b0 = __float_as_uint(kr[0]);
                uint32_t b1 = __float_as_uint(kr[4]);
                mma_tf32(s[np][0], s[np][1], s[np][2], s[np][3],
                         qa[ks][0], qa[ks][1], qa[ks][2], qa[ks][3], b0, b1);
            }
        }

        // ---- scale + causal mask
#pragma unroll
        for (int j = 0; j < 8; j++)
#pragma unroll
            for (int t = 0; t < 4; t++) s[j][t] *= ATTN_SCALE;

        if (kt == q0) {
            int row0 = q0 + wid * 16 + r;
#pragma unroll
            for (int j = 0; j < 8; j++) {
                int col = kt + j * 8 + c2;
                if (col > row0)     s[j][0] = -1e30f;
                if (col + 1 > row0) s[j][1] = -1e30f;
                if (col > row0 + 8)     s[j][2] = -1e30f;
                if (col + 1 > row0 + 8) s[j][3] = -1e30f;
            }
        }

        // ---- online softmax
        float mx0 = -1e30f, mx1 = -1e30f;
#pragma unroll
        for (int j = 0; j < 8; j++) {
            mx0 = fmaxf(mx0, fmaxf(s[j][0], s[j][1]));
            mx1 = fmaxf(mx1, fmaxf(s[j][2], s[j][3]));
        }
        mx0 = fmaxf(mx0, __shfl_xor_sync(0xffffffffu, mx0, 1));
        mx0 = fmaxf(mx0, __shfl_xor_sync(0xffffffffu, mx0, 2));
        mx1 = fmaxf(mx1, __shfl_xor_sync(0xffffffffu, mx1, 1));
        mx1 = fmaxf(mx1, __shfl_xor_sync(0xffffffffu, mx1, 2));

        float mn0 = fmaxf(m0, mx0), mn1 = fmaxf(m1, mx1);
        float corr0 = __expf(m0 - mn0), corr1 = __expf(m1 - mn1);
        l0 *= corr0; l1 *= corr1;
#pragma unroll
        for (int j = 0; j < 8; j++) {
            o[j][0] *= corr0; o[j][1] *= corr0;
            o[j][2] *= corr1; o[j][3] *= corr1;
        }
#pragma unroll
        for (int j = 0; j < 8; j++) {
            float p0 = __expf(s[j][0] - mn0);
            float p1 = __expf(s[j][1] - mn0);
            float p2 = __expf(s[j][2] - mn1);
            float p3 = __expf(s[j][3] - mn1);
            l0 += p0 + p1; l1 += p2 + p3;
            s[j][0] = p0; s[j][1] = p1; s[j][2] = p2; s[j][3] = p3;
        }
        m0 = mn0; m1 = mn1;

        // ---- O += P V (tf32). P A-fragments via shuffles:
        // consumer lane needs (row r, key t*8+ctg[,+4]); owner lane holds key pairs.
#pragma unroll
        for (int t = 0; t < 8; t++) {
            float s0 = s[t][0], s1 = s[t][1], s2 = s[t][2], s3 = s[t][3];
            float g00 = __shfl_sync(0xffffffffu, s0, P0);
            float g10 = __shfl_sync(0xffffffffu, s1, P0);
            float g20 = __shfl_sync(0xffffffffu, s2, P0);
            float g30 = __shfl_sync(0xffffffffu, s3, P0);
            float g01 = __shfl_sync(0xffffffffu, s0, P2);
            float g11 = __shfl_sync(0xffffffffu, s1, P2);
            float g21 = __shfl_sync(0xffffffffu, s2, P2);
            float g31 = __shfl_sync(0xffffffffu, s3, P2);
            uint32_t pa0 = __float_as_uint(tf32r(oddl ? g10 : g00));
            uint32_t pa1 = __float_as_uint(tf32r(oddl ? g30 : g20));
            uint32_t pa2 = __float_as_uint(tf32r(oddl ? g11 : g01));
            uint32_t pa3 = __float_as_uint(tf32r(oddl ? g31 : g21));
#pragma unroll
            for (int np = 0; np < 8; np++) {
                const float* vr = Vt + (np * 8 + r) * AS_LD + t * 8 + ctg;
                uint32_t b0 = __float_as_uint(vr[0]);
                uint32_t b1 = __float_as_uint(vr[4]);
                mma_tf32(o[np][0], o[np][1], o[np][2], o[np][3],
                         pa0, pa1, pa2, pa3, b0, b1);
            }
        }
    }

    l0 += __shfl_xor_sync(0xffffffffu, l0, 1);
    l0 += __shfl_xor_sync(0xffffffffu, l0, 2);
    l1 += __shfl_xor_sync(0xffffffffu, l1, 1);
    l1 += __shfl_xor_sync(0xffffffffu, l1, 2);
    float inv0 = 1.f / l0, inv1 = 1.f / l1;

    size_t row0 = (size_t)(b * SEQ + q0 + wid * 16 + r);
    size_t row1 = row0 + 8;
#pragma unroll
    for (int j = 0; j < 8; j++) {
        int col = hq * HD + j * 8 + c2;
        store_split(&g_a_hi[row0 * QPOS + col], &g_a_lo[row0 * QPOS + col],
                    o[j][0] * inv0, o[j][1] * inv0);
        store_split(&g_a_hi[row1 * QPOS + col], &g_a_lo[row1 * QPOS + col],
                    o[j][2] * inv1, o[j][3] * inv1);
    }
}

// ---------------------------------------------------------------------------
// kernel_launch
// ---------------------------------------------------------------------------
extern "C" void kernel_launch(void* const* d_in, const int* in_sizes, int n_in,
                              void* d_out, int out_size)
{
    const float* x    = (const float*)d_in[0];
    const float* Wqkv = (const float*)d_in[1];
    const float* Wo   = (const float*)d_in[2];
    float* out        = (float*)d_out;

    __nv_bfloat16 *xh, *xl, *wqh, *wql, *woh, *wol, *ah, *al;
    cudaGetSymbolAddress((void**)&xh,  g_x_hi);
    cudaGetSymbolAddress((void**)&xl,  g_x_lo);
    cudaGetSymbolAddress((void**)&wqh, g_wq_hi);
    cudaGetSymbolAddress((void**)&wql, g_wq_lo);
    cudaGetSymbolAddress((void**)&woh, g_wo_hi);
    cudaGetSymbolAddress((void**)&wol, g_wo_lo);
    cudaGetSymbolAddress((void**)&ah,  g_a_hi);
    cudaGetSymbolAddress((void**)&al,  g_a_lo);

    cudaFuncSetAttribute(gemm_mma_split_kernel<0>,
                         cudaFuncAttributeMaxDynamicSharedMemorySize, GEMM_SMEM);
    cudaFuncSetAttribute(gemm_mma_split_kernel<1>,
                         cudaFuncAttributeMaxDynamicSharedMemorySize, GEMM_SMEM);
    cudaFuncSetAttribute(attn_tf32_kernel,
                         cudaFuncAttributeMaxDynamicSharedMemorySize, ATTN_SMEM);

    // 1) Splits + rope table
    {
        int n4 = (MTOT * DMODEL) / 4;
        split_bf16_kernel<<<(n4 + 255) / 256, 256>>>(x, xh, xl, n4);
    }
    {
        int n4 = (OPS * DMODEL) / 4;
        split_bf16_kernel<<<(n4 + 255) / 256, 256>>>(Wqkv, wqh, wql, n4);
    }
    {
        int n4 = (DMODEL * DMODEL) / 4;
        split_bf16_kernel<<<(n4 + 255) / 256, 256>>>(Wo, woh, wol, n4);
    }
    {
        int n = SEQ * 32;
        rope_table_kernel<<<(n + 255) / 256, 256>>>();
    }

    // 2) QKV projection with fused rope/tf32-round/relayout epilogue
    {
        dim3 grid(OPS / 128, MTOT / 128);
        gemm_mma_split_kernel<1><<<grid, 128, GEMM_SMEM>>>(
            xh, xl, wqh, wql, nullptr, OPS, DMODEL);
    }

    // 3) Flash attention (tf32 single-pass)
    {
        dim3 grid(SEQ / 64, NH, BATCH);
        attn_tf32_kernel<<<grid, 128, ATTN_SMEM>>>();
    }

    // 4) O-projection (bf16-split, 3-combo)
    {
        dim3 grid(DMODEL / 128, MTOT / 128);
        gemm_mma_split_kernel<0><<<grid, 128, GEMM_SMEM>>>(
            ah, al, woh, wol, out, DMODEL, DMODEL);
    }
}

// round 11
// speedup vs baseline: 4.8695x; 1.2112x over previous
#include <cuda_runtime.h>
#include <cuda_bf16.h>
#include <math.h>
#include <stdint.h>

// Problem constants
#define BATCH   2
#define SEQ     2048
#define DMODEL  2048
#define NH      32
#define NKV     8
#define HD      64
#define QPOS    (NH * HD)            // 2048
#define KVPOS   (NKV * HD)           // 512
#define OPS     (QPOS + 2 * KVPOS)   // 3072
#define MTOT    (BATCH * SEQ)        // 4096
#define ATTN_SCALE 0.125f

// ---------------------------------------------------------------------------
// Scratch (device globals) — all tf32-pre-rounded fp32
// ---------------------------------------------------------------------------
__device__ float g_xr[MTOT * DMODEL];         // rounded x
__device__ float g_wqr[OPS * DMODEL];         // rounded Wqkv
__device__ float g_wor[DMODEL * DMODEL];      // rounded Wo
__device__ float g_qf[BATCH * NH  * SEQ * HD];   // roped q  [b][h][seq][64]
__device__ float g_kf[BATCH * NKV * SEQ * HD];   // roped k
__device__ float g_vt[BATCH * NKV * HD * SEQ];   // v transposed [b][kvh][dim][seq]
__device__ float g_af[MTOT * QPOS];           // attention output (rounded)
__device__ float2 g_rope[SEQ * 32];

// ---------------------------------------------------------------------------
// helpers
// ---------------------------------------------------------------------------
__device__ __forceinline__ uint32_t smem_to_u32(const void* p) {
    uint32_t a;
    asm("{ .reg .u64 t; cvta.to.shared.u64 t, %1; cvt.u32.u64 %0, t; }"
        : "=r"(a) : "l"(p));
    return a;
}

__device__ __forceinline__ void cp_async16(uint32_t smem_dst, const void* gmem_src) {
    asm volatile("cp.async.cg.shared.global [%0], [%1], 16;"
                 :: "r"(smem_dst), "l"(gmem_src) : "memory");
}
__device__ __forceinline__ void cp_commit() {
    asm volatile("cp.async.commit_group;" ::: "memory");
}
__device__ __forceinline__ void cp_wait0() {
    asm volatile("cp.async.wait_group 0;" ::: "memory");
}

// tf32 mma m16n8k8 (operands are pre-rounded fp32 bit patterns)
__device__ __forceinline__ void mma_tf32(float& d0, float& d1, float& d2, float& d3,
                                         uint32_t a0, uint32_t a1, uint32_t a2, uint32_t a3,
                                         uint32_t b0, uint32_t b1) {
    asm volatile(
        "mma.sync.aligned.m16n8k8.row.col.f32.tf32.tf32.f32 "
        "{%0,%1,%2,%3}, {%4,%5,%6,%7}, {%8,%9}, {%0,%1,%2,%3};"
        : "+f"(d0), "+f"(d1), "+f"(d2), "+f"(d3)
        : "r"(a0), "r"(a1), "r"(a2), "r"(a3), "r"(b0), "r"(b1));
}

// round-to-nearest tf32 (unbiased; truncation would bias results)
__device__ __forceinline__ float tf32r(float x) {
    float y;
    asm("cvt.rna.tf32.f32 %0, %1;" : "=f"(y) : "f"(x));
    return y;
}

// ---------------------------------------------------------------------------
// Round fp32 -> tf32-representable fp32 (rna), vectorized x4
// ---------------------------------------------------------------------------
__global__ void round_tf32_kernel(const float* __restrict__ src,
                                  float* __restrict__ dst, int n4)
{
    int i = blockIdx.x * blockDim.x + threadIdx.x;
    if (i >= n4) return;
    float4 v = ((const float4*)src)[i];
    v.x = tf32r(v.x); v.y = tf32r(v.y); v.z = tf32r(v.z); v.w = tf32r(v.w);
    ((float4*)dst)[i] = v;
}

__global__ void rope_table_kernel()
{
    int idx = blockIdx.x * blockDim.x + threadIdx.x;
    if (idx >= SEQ * 32) return;
    int l = idx >> 5, i = idx & 31;
    float ang = (float)l * powf(10000.0f, -(float)(2 * i) / (float)HD);
    float s, c;
    sincosf(ang, &s, &c);
    g_rope[idx] = make_float2(c, s);
}

// ---------------------------------------------------------------------------
// Single-pass tf32 GEMM: C[M,N] = A[M,K] * B[N,K]^T, fp32 accumulate.
// CTA tile 128x128, K-chunk 32, double-buffered cp.async.
// 4 warps (2m x 2n), warp tile 64x64. 2 CTAs/SM.
// MODE 0: fp32 C (O-projection).
// MODE 1: QKV epilogue — RoPE, tf32-round, per-head scatter.
// Operands must be tf32-pre-rounded fp32.
// ---------------------------------------------------------------------------
#define TLD   36                         // smem row stride (floats): 36 mod 32 = 4
#define TROW  (TLD * 4)                  // 144 B
#define T_TILE (128 * TROW)              // 18432 B per operand
#define T_STAGE (2 * T_TILE)             // 36864 B
#define TGEMM_SMEM (2 * T_STAGE)         // 73728 B; x2 CTAs = 147 KB

template <int MODE>
__global__ void __launch_bounds__(128, 2)
gemm_tf32_kernel(const float* __restrict__ A, const float* __restrict__ B,
                 float* __restrict__ C, int N, int K)
{
    extern __shared__ char smem[];
    const uint32_t sb = smem_to_u32(smem);

    const int tid  = threadIdx.x;
    const int lane = tid & 31;
    const int wid  = tid >> 5;
    const int wm   = wid >> 1;           // 0..1
    const int wn   = wid & 1;            // 0..1
    const int bm   = blockIdx.y * 128;
    const int bn   = blockIdx.x * 128;
    const int r    = lane >> 2;          // 0..7
    const int ctg  = lane & 3;           // 0..3

    const float* Ag = A + (size_t)bm * K;
    const float* Bg = B + (size_t)bn * K;

    float acc[4][8][4];
#pragma unroll
    for (int i = 0; i < 4; i++)
#pragma unroll
        for (int j = 0; j < 8; j++)
#pragma unroll
            for (int t = 0; t < 4; t++) acc[i][j][t] = 0.f;

    const int iters = K / 32;

    // loader: 1024 16B-chunks per operand tile, 128 threads -> 8 iters each
    auto load_stage = [&](int stage, int k0) {
        uint32_t base = sb + stage * T_STAGE;
#pragma unroll
        for (int i = 0; i < 8; i++) {
            int lin = tid + i * 128;
            int row = lin >> 3;
            int c   = lin & 7;
            uint32_t sofs = (uint32_t)(row * TROW + c * 16);
            size_t gofs   = (size_t)row * K + k0 + c * 4;
            cp_async16(base + sofs,          Ag + gofs);
            cp_async16(base + T_TILE + sofs, Bg + gofs);
        }
        cp_commit();
    };

    load_stage(0, 0);

    for (int it = 0; it < iters; ++it) {
        cp_wait0();
        __syncthreads();
        if (it + 1 < iters) load_stage((it + 1) & 1, (it + 1) * 32);

        const float* sA = (const float*)(smem + (it & 1) * T_STAGE);
        const float* sB = sA + T_TILE / 4;

#pragma unroll
        for (int ks = 0; ks < 4; ks++) {
            // A-fragments (m16n8k8): a0=(r,c) a1=(r+8,c) a2=(r,c+4) a3=(r+8,c+4)
            uint32_t af[4][4];
#pragma unroll
            for (int mt = 0; mt < 4; mt++) {
                const float* ap = sA + (wm * 64 + mt * 16 + r) * TLD + ks * 8 + ctg;
                af[mt][0] = __float_as_uint(ap[0]);
                af[mt][1] = __float_as_uint(ap[8 * TLD]);
                af[mt][2] = __float_as_uint(ap[4]);
                af[mt][3] = __float_as_uint(ap[8 * TLD + 4]);
            }
#pragma unroll
            for (int np = 0; np < 8; np++) {
                const float* bp = sB + (wn * 64 + np * 8 + r) * TLD + ks * 8 + ctg;
                uint32_t b0 = __float_as_uint(bp[0]);
                uint32_t b1 = __float_as_uint(bp[4]);
#pragma unroll
                for (int mt = 0; mt < 4; mt++) {
                    mma_tf32(acc[mt][np][0], acc[mt][np][1], acc[mt][np][2], acc[mt][np][3],
                             af[mt][0], af[mt][1], af[mt][2], af[mt][3], b0, b1);
                }
            }
        }
        __syncthreads();
    }

    const int c2v = ctg * 2;

    if (MODE == 0) {
#pragma unroll
        for (int mt = 0; mt < 4; mt++) {
            int row = bm + wm * 64 + mt * 16 + r;
#pragma unroll
            for (int nt = 0; nt < 8; nt++) {
                int col = bn + wn * 64 + nt * 8 + c2v;
                *(float2*)&C[(size_t)row * N + col] =
                    make_float2(acc[mt][nt][0], acc[mt][nt][1]);
                *(float2*)&C[(size_t)(row + 8) * N + col] =
                    make_float2(acc[mt][nt][2], acc[mt][nt][3]);
            }
        }
    } else {
        // QKV epilogue: rope + tf32-round + per-head scatter.
        const int head = (bn + wn * 64) >> 6;   // 0..47
#pragma unroll
        for (int mt = 0; mt < 4; mt++) {
            int grow = bm + wm * 64 + mt * 16 + r;
            int b = grow >> 11;
            int l = grow & (SEQ - 1);
            float* dq = nullptr;
            float* dv = nullptr;
            bool rope = false;
            if (head < NH) {
                dq = g_qf + ((size_t)(b * NH + head) * SEQ + l) * HD;
                rope = true;
            } else if (head < NH + NKV) {
                dq = g_kf + ((size_t)(b * NKV + (head - NH)) * SEQ + l) * HD;
                rope = true;
            } else {
                dv = g_vt + (size_t)(b * NKV + (head - NH - NKV)) * HD * SEQ;
            }
#pragma unroll
            for (int nt = 0; nt < 4; nt++) {
                int i0 = nt * 8 + c2v;
                float x0 = acc[mt][nt][0],     x1 = acc[mt][nt][1];
                float y0 = acc[mt][nt + 4][0], y1 = acc[mt][nt + 4][1];
                float x2 = acc[mt][nt][2],     x3 = acc[mt][nt][3];
                float y2 = acc[mt][nt + 4][2], y3 = acc[mt][nt + 4][3];
                if (rope) {
                    float2 cs0 = g_rope[l * 32 + i0];
                    float2 cs1 = g_rope[l * 32 + i0 + 1];
                    float2 cs2 = g_rope[(l + 8) * 32 + i0];
                    float2 cs3 = g_rope[(l + 8) * 32 + i0 + 1];
                    float nx;
                    nx = x0 * cs0.x - y0 * cs0.y; y0 = y0 * cs0.x + x0 * cs0.y; x0 = nx;
                    nx = x1 * cs1.x - y1 * cs1.y; y1 = y1 * cs1.x + x1 * cs1.y; x1 = nx;
                    nx = x2 * cs2.x - y2 * cs2.y; y2 = y2 * cs2.x + x2 * cs2.y; x2 = nx;
                    nx = x3 * cs3.x - y3 * cs3.y; y3 = y3 * cs3.x + x3 * cs3.y; x3 = nx;
                }
                x0 = tf32r(x0); x1 = tf32r(x1); x2 = tf32r(x2); x3 = tf32r(x3);
                y0 = tf32r(y0); y1 = tf32r(y1); y2 = tf32r(y2); y3 = tf32r(y3);
                if (dq) {
                    *(float2*)(dq + i0)               = make_float2(x0, x1);
                    *(float2*)(dq + i0 + 32)          = make_float2(y0, y1);
                    *(float2*)(dq + 8 * HD + i0)      = make_float2(x2, x3);
                    *(float2*)(dq + 8 * HD + i0 + 32) = make_float2(y2, y3);
                } else {
                    dv[(size_t)(i0)      * SEQ + l]     = x0;
                    dv[(size_t)(i0 + 1)  * SEQ + l]     = x1;
                    dv[(size_t)(i0 + 32) * SEQ + l]     = y0;
                    dv[(size_t)(i0 + 33) * SEQ + l]     = y1;
                    dv[(size_t)(i0)      * SEQ + l + 8] = x2;
                    dv[(size_t)(i0 + 1)  * SEQ + l + 8] = x3;
                    dv[(size_t)(i0 + 32) * SEQ + l + 8] = y2;
                    dv[(size_t)(i0 + 33) * SEQ + l + 8] = y3;
                }
            }
        }
    }
}

// ---------------------------------------------------------------------------
// Flash attention, single-pass tf32 mma (m16n8k8), fp32 accumulate.
// CTA: 64 q-rows, 4 warps. KV tiles of 64 keys, double-buffered, 2 CTAs/SM.
// K in smem [key][dim] (68-float rows), V in smem TRANSPOSED [dim][key].
// Epilogue writes tf32-rounded fp32 to g_af (O-proj A operand).
// ---------------------------------------------------------------------------
#define AS_LD   68
#define AS_ROW  (AS_LD * 4)
#define AS_TILE (64 * AS_ROW)
#define AS_STAGE (2 * AS_TILE)
#define ATTN_SMEM (2 * AS_STAGE)          // 69632 B; x2 CTAs = 139 KB

__global__ void __launch_bounds__(128, 2)
attn_tf32_kernel()
{
    extern __shared__ char smem[];
    const uint32_t sb = smem_to_u32(smem);

    const int tid  = threadIdx.x;
    const int lane = tid & 31;
    const int wid  = tid >> 5;
    const int bx   = (int)gridDim.x - 1 - (int)blockIdx.x;   // heavy blocks first
    const int q0   = bx * 64;
    const int hq   = blockIdx.y;
    const int b    = blockIdx.z;
    const int kvh  = hq >> 2;
    const int r    = lane >> 2;
    const int ctg  = lane & 3;
    const int c2   = ctg * 2;

    const float* qp = g_qf + ((size_t)(b * NH + hq) * SEQ + q0 + wid * 16 + r) * HD;
    uint32_t qa[8][4];
#pragma unroll
    for (int ks = 0; ks < 8; ks++) {
        int c = ks * 8 + ctg;
        qa[ks][0] = __float_as_uint(qp[c]);
        qa[ks][1] = __float_as_uint(qp[8 * HD + c]);
        qa[ks][2] = __float_as_uint(qp[c + 4]);
        qa[ks][3] = __float_as_uint(qp[8 * HD + c + 4]);
    }

    const float* kg = g_kf + (size_t)(b * NKV + kvh) * SEQ * HD;   // [key][dim]
    const float* vg = g_vt + (size_t)(b * NKV + kvh) * HD * SEQ;   // [dim][seq]

    auto load_stage = [&](int st, int kt) {
        uint32_t base = sb + st * AS_STAGE;
#pragma unroll
        for (int i = 0; i < 8; i++) {
            int lin = tid + i * 128;
            int row = lin >> 4;
            int c   = lin & 15;
            cp_async16(base + (uint32_t)(row * AS_ROW + c * 16),
                       kg + (size_t)(kt + row) * HD + c * 4);
            cp_async16(base + AS_TILE + (uint32_t)(row * AS_ROW + c * 16),
                       vg + (size_t)row * SEQ + kt + c * 4);
        }
        cp_commit();
    };

    const int iters = bx + 1;
    load_stage(0, 0);

    float o[8][4];
#pragma unroll
    for (int j = 0; j < 8; j++)
#pragma unroll
        for (int t = 0; t < 4; t++) o[j][t] = 0.f;
    float m0 = -1e30f, m1 = -1e30f, l0 = 0.f, l1 = 0.f;

    const int P0 = (lane & 28) | (ctg >> 1);
    const int P2 = (lane & 28) | ((ctg >> 1) + 2);
    const bool oddl = (lane & 1);

    for (int it = 0; it < iters; ++it) {
        const int kt = it * 64;
        cp_wait0();
        __syncthreads();
        if (it + 1 < iters) load_stage((it + 1) & 1, (it + 1) * 64);

        const float* Ks = (const float*)(smem + (it & 1) * AS_STAGE);
        const float* Vt = Ks + AS_TILE / 4;

        float s[8][4];
#pragma unroll
        for (int j = 0; j < 8; j++)
#pragma unroll
            for (int t = 0; t < 4; t++) s[j][t] = 0.f;

#pragma unroll
        for (int ks = 0; ks < 8; ks++) {
#pragma unroll
            for (int np = 0; np < 8; np++) {
                const float* kr = Ks + (np * 8 + r) * AS_LD + ks * 8 + ctg;
                uint32_t b0 = __float_as_uint(kr[0]);
                uint32_t b1 = __float_as_uint(kr[4]);
                mma_tf32(s[np][0], s[np][1], s[np][2], s[np][3],
                         qa[ks][0], qa[ks][1], qa[ks][2], qa[ks][3], b0, b1);
            }
        }

#pragma unroll
        for (int j = 0; j < 8; j++)
#pragma unroll
            for (int t = 0; t < 4; t++) s[j][t] *= ATTN_SCALE;

        if (kt == q0) {
            int row0 = q0 + wid * 16 + r;
#pragma unroll
            for (int j = 0; j < 8; j++) {
                int col = kt + j * 8 + c2;
                if (col > row0)     s[j][0] = -1e30f;
                if (col + 1 > row0) s[j][1] = -1e30f;
                if (col > row0 + 8)     s[j][2] = -1e30f;
                if (col + 1 > row0 + 8) s[j][3] = -1e30f;
            }
        }

        float mx0 = -1e30f, mx1 = -1e30f;
#pragma unroll
        for (int j = 0; j < 8; j++) {
            mx0 = fmaxf(mx0, fmaxf(s[j][0], s[j][1]));
            mx1 = fmaxf(mx1, fmaxf(s[j][2], s[j][3]));
        }
        mx0 = fmaxf(mx0, __shfl_xor_sync(0xffffffffu, mx0, 1));
        mx0 = fmaxf(mx0, __shfl_xor_sync(0xffffffffu, mx0, 2));
        mx1 = fmaxf(mx1, __shfl_xor_sync(0xffffffffu, mx1, 1));
        mx1 = fmaxf(mx1, __shfl_xor_sync(0xffffffffu, mx1, 2));

        float mn0 = fmaxf(m0, mx0), mn1 = fmaxf(m1, mx1);
        float corr0 = __expf(m0 - mn0), corr1 = __expf(m1 - mn1);
        l0 *= corr0; l1 *= corr1;
#pragma unroll
        for (int j = 0; j < 8; j++) {
            o[j][0] *= corr0; o[j][1] *= corr0;
            o[j][2] *= corr1; o[j][3] *= corr1;
        }
#pragma unroll
        for (int j = 0; j < 8; j++) {
            float p0 = __expf(s[j][0] - mn0);
            float p1 = __expf(s[j][1] - mn0);
            float p2 = __expf(s[j][2] - mn1);
            float p3 = __expf(s[j][3] - mn1);
            l0 += p0 + p1; l1 += p2 + p3;
            s[j][0] = p0; s[j][1] = p1; s[j][2] = p2; s[j][3] = p3;
        }
        m0 = mn0; m1 = mn1;

#pragma unroll
        for (int t = 0; t < 8; t++) {
            float s0 = s[t][0], s1 = s[t][1], s2 = s[t][2], s3 = s[t][3];
            float g00 = __shfl_sync(0xffffffffu, s0, P0);
            float g10 = __shfl_sync(0xffffffffu, s1, P0);
            float g20 = __shfl_sync(0xffffffffu, s2, P0);
            float g30 = __shfl_sync(0xffffffffu, s3, P0);
            float g01 = __shfl_sync(0xffffffffu, s0, P2);
            float g11 = __shfl_sync(0xffffffffu, s1, P2);
            float g21 = __shfl_sync(0xffffffffu, s2, P2);
            float g31 = __shfl_sync(0xffffffffu, s3, P2);
            uint32_t pa0 = __float_as_uint(tf32r(oddl ? g10 : g00));
            uint32_t pa1 = __float_as_uint(tf32r(oddl ? g30 : g20));
            uint32_t pa2 = __float_as_uint(tf32r(oddl ? g11 : g01));
            uint32_t pa3 = __float_as_uint(tf32r(oddl ? g31 : g21));
#pragma unroll
            for (int np = 0; np < 8; np++) {
                const float* vr = Vt + (np * 8 + r) * AS_LD + t * 8 + ctg;
                uint32_t b0 = __float_as_uint(vr[0]);
                uint32_t b1 = __float_as_uint(vr[4]);
                mma_tf32(o[np][0], o[np][1], o[np][2], o[np][3],
                         pa0, pa1, pa2, pa3, b0, b1);
            }
        }
    }

    l0 += __shfl_xor_sync(0xffffffffu, l0, 1);
    l0 += __shfl_xor_sync(0xffffffffu, l0, 2);
    l1 += __shfl_xor_sync(0xffffffffu, l1, 1);
    l1 += __shfl_xor_sync(0xffffffffu, l1, 2);
    float inv0 = 1.f / l0, inv1 = 1.f / l1;

    size_t row0 = (size_t)(b * SEQ + q0 + wid * 16 + r);
    size_t row1 = row0 + 8;
#pragma unroll
    for (int j = 0; j < 8; j++) {
        int col = hq * HD + j * 8 + c2;
        *(float2*)&g_af[row0 * QPOS + col] =
            make_float2(tf32r(o[j][0] * inv0), tf32r(o[j][1] * inv0));
        *(float2*)&g_af[row1 * QPOS + col] =
            make_float2(tf32r(o[j][2] * inv1), tf32r(o[j][3] * inv1));
    }
}

// ---------------------------------------------------------------------------
// kernel_launch
// ---------------------------------------------------------------------------
extern "C" void kernel_launch(void* const* d_in, const int* in_sizes, int n_in,
                              void* d_out, int out_size)
{
    const float* x    = (const float*)d_in[0];
    const float* Wqkv = (const float*)d_in[1];
    const float* Wo   = (const float*)d_in[2];
    float* out        = (float*)d_out;

    float *xr, *wqr, *wor, *af;
    cudaGetSymbolAddress((void**)&xr,  g_xr);
    cudaGetSymbolAddress((void**)&wqr, g_wqr);
    cudaGetSymbolAddress((void**)&wor, g_wor);
    cudaGetSymbolAddress((void**)&af,  g_af);

    cudaFuncSetAttribute(gemm_tf32_kernel<0>,
                         cudaFuncAttributeMaxDynamicSharedMemorySize, TGEMM_SMEM);
    cudaFuncSetAttribute(gemm_tf32_kernel<1>,
                         cudaFuncAttributeMaxDynamicSharedMemorySize, TGEMM_SMEM);
    cudaFuncSetAttribute(attn_tf32_kernel,
                         cudaFuncAttributeMaxDynamicSharedMemorySize, ATTN_SMEM);

    // 1) tf32-round inputs + rope table
    {
        int n4 = (MTOT * DMODEL) / 4;
        round_tf32_kernel<<<(n4 + 255) / 256, 256>>>(x, xr, n4);
    }
    {
        int n4 = (OPS * DMODEL) / 4;
        round_tf32_kernel<<<(n4 + 255) / 256, 256>>>(Wqkv, wqr, n4);
    }
    {
        int n4 = (DMODEL * DMODEL) / 4;
        round_tf32_kernel<<<(n4 + 255) / 256, 256>>>(Wo, wor, n4);
    }
    {
        int n = SEQ * 32;
        rope_table_kernel<<<(n + 255) / 256, 256>>>();
    }

    // 2) QKV projection (tf32 single-pass) with fused rope/round/relayout
    {
        dim3 grid(OPS / 128, MTOT / 128);
        gemm_tf32_kernel<1><<<grid, 128, TGEMM_SMEM>>>(xr, wqr, nullptr, OPS, DMODEL);
    }

    // 3) Flash attention (tf32 single-pass)
    {
        dim3 grid(SEQ / 64, NH, BATCH);
        attn_tf32_kernel<<<grid, 128, ATTN_SMEM>>>();
    }

    // 4) O-projection (tf32 single-pass)
    {
        dim3 grid(DMODEL / 128, MTOT / 128);
        gemm_tf32_kernel<0><<<grid, 128, TGEMM_SMEM>>>(af, wor, out, DMODEL, DMODEL);
    }
}

// round 12
// speedup vs baseline: 10.0929x; 2.0727x over previous
#include <cuda_runtime.h>
#include <cuda_fp16.h>
#include <math.h>
#include <stdint.h>

// Problem constants
#define BATCH   2
#define SEQ     2048
#define DMODEL  2048
#define NH      32
#define NKV     8
#define HD      64
#define QPOS    (NH * HD)            // 2048
#define KVPOS   (NKV * HD)           // 512
#define OPS     (QPOS + 2 * KVPOS)   // 3072
#define MTOT    (BATCH * SEQ)        // 4096
#define ATTN_SCALE 0.125f

// ---------------------------------------------------------------------------
// Scratch (device globals) — fp16 operands everywhere, fp32 accumulate
// ---------------------------------------------------------------------------
__device__ __half g_x [MTOT * DMODEL];
__device__ __half g_wq[OPS * DMODEL];
__device__ __half g_wo[DMODEL * DMODEL];
// per-head-contiguous roped q/k and v: [b][h][seq][64]
__device__ __half g_qh[BATCH * NH  * SEQ * HD];
__device__ __half g_kh[BATCH * NKV * SEQ * HD];
__device__ __half g_vh[BATCH * NKV * SEQ * HD];
// attention output [row][2048] (O-proj A operand)
__device__ __half g_ah[MTOT * QPOS];
__device__ float2 g_rope[SEQ * 32];

// ---------------------------------------------------------------------------
// helpers
// ---------------------------------------------------------------------------
__device__ __forceinline__ uint32_t smem_to_u32(const void* p) {
    uint32_t a;
    asm("{ .reg .u64 t; cvta.to.shared.u64 t, %1; cvt.u32.u64 %0, t; }"
        : "=r"(a) : "l"(p));
    return a;
}

__device__ __forceinline__ void cp_async16(uint32_t smem_dst, const void* gmem_src) {
    asm volatile("cp.async.cg.shared.global [%0], [%1], 16;"
                 :: "r"(smem_dst), "l"(gmem_src) : "memory");
}
__device__ __forceinline__ void cp_commit() {
    asm volatile("cp.async.commit_group;" ::: "memory");
}
__device__ __forceinline__ void cp_wait0() {
    asm volatile("cp.async.wait_group 0;" ::: "memory");
}

__device__ __forceinline__ void ldsm_x4(uint32_t& r0, uint32_t& r1,
                                        uint32_t& r2, uint32_t& r3, uint32_t addr) {
    asm volatile("ldmatrix.sync.aligned.m8n8.x4.shared.b16 {%0,%1,%2,%3}, [%4];"
                 : "=r"(r0), "=r"(r1), "=r"(r2), "=r"(r3) : "r"(addr));
}
__device__ __forceinline__ void ldsm_x4_trans(uint32_t& r0, uint32_t& r1,
                                              uint32_t& r2, uint32_t& r3, uint32_t addr) {
    asm volatile("ldmatrix.sync.aligned.m8n8.x4.trans.shared.b16 {%0,%1,%2,%3}, [%4];"
                 : "=r"(r0), "=r"(r1), "=r"(r2), "=r"(r3) : "r"(addr));
}

// fp16 mma m16n8k16, fp32 accumulate
__device__ __forceinline__ void mma_f16(float& d0, float& d1, float& d2, float& d3,
                                        uint32_t a0, uint32_t a1, uint32_t a2, uint32_t a3,
                                        uint32_t b0, uint32_t b1) {
    asm volatile(
        "mma.sync.aligned.m16n8k16.row.col.f32.f16.f16.f32 "
        "{%0,%1,%2,%3}, {%4,%5,%6,%7}, {%8,%9}, {%0,%1,%2,%3};"
        : "+f"(d0), "+f"(d1), "+f"(d2), "+f"(d3)
        : "r"(a0), "r"(a1), "r"(a2), "r"(a3), "r"(b0), "r"(b1));
}

__device__ __forceinline__ uint32_t pack_h2(float x, float y) {
    __half2 t = __floats2half2_rn(x, y);
    return *(uint32_t*)&t;
}

// ---------------------------------------------------------------------------
// fp32 -> fp16 (rn), vectorized
// ---------------------------------------------------------------------------
__global__ void to_half_kernel(const float* __restrict__ src,
                               __half* __restrict__ dst, int n4)
{
    int i = blockIdx.x * blockDim.x + threadIdx.x;
    if (i >= n4) return;
    float4 v = ((const float4*)src)[i];
    uint32_t* dp = (uint32_t*)dst;
    dp[2 * i]     = pack_h2(v.x, v.y);
    dp[2 * i + 1] = pack_h2(v.z, v.w);
}

__global__ void rope_table_kernel()
{
    int idx = blockIdx.x * blockDim.x + threadIdx.x;
    if (idx >= SEQ * 32) return;
    int l = idx >> 5, i = idx & 31;
    float ang = (float)l * powf(10000.0f, -(float)(2 * i) / (float)HD);
    float s, c;
    sincosf(ang, &s, &c);
    g_rope[idx] = make_float2(c, s);
}

// ---------------------------------------------------------------------------
// Single-pass fp16 GEMM: C[M,N] = A[M,K] * B[N,K]^T, fp32 accumulate.
// CTA tile 128x128, K-chunk 32, double-buffered cp.async.
// 4 warps (2m x 2n), warp tile 64x64. 2 CTAs/SM.
// MODE 0: fp32 C (O-projection).
// MODE 1: QKV epilogue — RoPE, fp16-round, per-head scatter to g_qh/g_kh/g_vh.
// ---------------------------------------------------------------------------
#define LDSE  40                         // halves per smem row (80 B, conflict-free)
#define LDSB  (LDSE * 2)
#define TILE_B (128 * LDSB)              // 10240 B per operand
#define STAGE_B (2 * TILE_B)             // 20480 B per stage
#define GEMM_SMEM (2 * STAGE_B)          // 40960 B

template <int MODE>
__global__ void __launch_bounds__(128, 2)
gemm_f16_kernel(const __half* __restrict__ A, const __half* __restrict__ B,
                float* __restrict__ C, int N, int K)
{
    extern __shared__ char smem[];
    const uint32_t sb = smem_to_u32(smem);

    const int tid  = threadIdx.x;
    const int lane = tid & 31;
    const int wid  = tid >> 5;
    const int wm   = wid >> 1;           // 0..1
    const int wn   = wid & 1;            // 0..1
    const int bm   = blockIdx.y * 128;
    const int bn   = blockIdx.x * 128;

    const __half* Ag = A + (size_t)bm * K;
    const __half* Bg = B + (size_t)bn * K;

    // loader: per operand tile 128 rows x 64 B = 512 chunks; 4 per thread
    const int r0 = tid >> 2;             // rows 0..31 (+32*i)
    const int c0 = tid & 3;

    float acc[4][8][4];
#pragma unroll
    for (int i = 0; i < 4; i++)
#pragma unroll
        for (int j = 0; j < 8; j++)
#pragma unroll
            for (int t = 0; t < 4; t++) acc[i][j][t] = 0.f;

    const int iters = K / 32;

    const uint32_t a_ld_off =
        (uint32_t)((wm * 64 + (lane & 15)) * LDSB + (lane >> 4) * 16);
    const uint32_t b_ld_off =
        (uint32_t)((wn * 64 + (lane & 7) + ((lane >> 4) << 3)) * LDSB
                   + ((lane >> 3) & 1) * 16);

    auto load_stage = [&](int stage, int k0) {
        uint32_t base = sb + stage * STAGE_B;
#pragma unroll
        for (int i = 0; i < 4; i++) {
            int row = r0 + i * 32;
            uint32_t sofs = (uint32_t)(row * LDSB + c0 * 16);
            size_t gofs   = (size_t)row * K + k0 + c0 * 8;
            cp_async16(base + sofs,          Ag + gofs);
            cp_async16(base + TILE_B + sofs, Bg + gofs);
        }
        cp_commit();
    };

    load_stage(0, 0);

    for (int it = 0; it < iters; ++it) {
        cp_wait0();
        __syncthreads();
        if (it + 1 < iters) load_stage((it + 1) & 1, (it + 1) * 32);

        const uint32_t base = sb + (it & 1) * STAGE_B;
        const uint32_t sA = base + a_ld_off;
        const uint32_t sB = base + TILE_B + b_ld_off;

#pragma unroll
        for (int ks = 0; ks < 2; ks++) {
            const uint32_t kofs = ks * 32;       // 16 halves = 32 B
            uint32_t af[4][4];
#pragma unroll
            for (int mt = 0; mt < 4; mt++)
                ldsm_x4(af[mt][0], af[mt][1], af[mt][2], af[mt][3],
                        sA + mt * 16 * LDSB + kofs);
#pragma unroll
            for (int np = 0; np < 4; np++) {
                uint32_t bf[4];
                ldsm_x4(bf[0], bf[1], bf[2], bf[3], sB + np * 16 * LDSB + kofs);
                const int j0 = 2 * np, j1 = 2 * np + 1;
#pragma unroll
                for (int mt = 0; mt < 4; mt++) {
                    mma_f16(acc[mt][j0][0], acc[mt][j0][1], acc[mt][j0][2], acc[mt][j0][3],
                            af[mt][0], af[mt][1], af[mt][2], af[mt][3], bf[0], bf[1]);
                    mma_f16(acc[mt][j1][0], acc[mt][j1][1], acc[mt][j1][2], acc[mt][j1][3],
                            af[mt][0], af[mt][1], af[mt][2], af[mt][3], bf[2], bf[3]);
                }
            }
        }
        __syncthreads();
    }

    const int c2v = (lane & 3) * 2;

    if (MODE == 0) {
#pragma unroll
        for (int mt = 0; mt < 4; mt++) {
            int row = bm + wm * 64 + mt * 16 + (lane >> 2);
#pragma unroll
            for (int nt = 0; nt < 8; nt++) {
                int col = bn + wn * 64 + nt * 8 + c2v;
                *(float2*)&C[(size_t)row * N + col] =
                    make_float2(acc[mt][nt][0], acc[mt][nt][1]);
                *(float2*)&C[(size_t)(row + 8) * N + col] =
                    make_float2(acc[mt][nt][2], acc[mt][nt][3]);
            }
        }
    } else {
        // QKV epilogue: rope + fp16-round + per-head scatter (warp panel = 1 head)
        const int head = (bn + wn * 64) >> 6;   // 0..47
#pragma unroll
        for (int mt = 0; mt < 4; mt++) {
            int grow = bm + wm * 64 + mt * 16 + (lane >> 2);
            int b = grow >> 11;
            int l = grow & (SEQ - 1);
            __half* dh;
            bool rope;
            if (head < NH) {
                dh = g_qh + ((size_t)(b * NH + head) * SEQ + l) * HD;
                rope = true;
            } else if (head < NH + NKV) {
                dh = g_kh + ((size_t)(b * NKV + (head - NH)) * SEQ + l) * HD;
                rope = true;
            } else {
                dh = g_vh + ((size_t)(b * NKV + (head - NH - NKV)) * SEQ + l) * HD;
                rope = false;
            }
#pragma unroll
            for (int nt = 0; nt < 4; nt++) {
                int i0 = nt * 8 + c2v;
                float x0 = acc[mt][nt][0],     x1 = acc[mt][nt][1];
                float y0 = acc[mt][nt + 4][0], y1 = acc[mt][nt + 4][1];
                float x2 = acc[mt][nt][2],     x3 = acc[mt][nt][3];
                float y2 = acc[mt][nt + 4][2], y3 = acc[mt][nt + 4][3];
                if (rope) {
                    float2 cs0 = g_rope[l * 32 + i0];
                    float2 cs1 = g_rope[l * 32 + i0 + 1];
                    float2 cs2 = g_rope[(l + 8) * 32 + i0];
                    float2 cs3 = g_rope[(l + 8) * 32 + i0 + 1];
                    float nx;
                    nx = x0 * cs0.x - y0 * cs0.y; y0 = y0 * cs0.x + x0 * cs0.y; x0 = nx;
                    nx = x1 * cs1.x - y1 * cs1.y; y1 = y1 * cs1.x + x1 * cs1.y; x1 = nx;
                    nx = x2 * cs2.x - y2 * cs2.y; y2 = y2 * cs2.x + x2 * cs2.y; x2 = nx;
                    nx = x3 * cs3.x - y3 * cs3.y; y3 = y3 * cs3.x + x3 * cs3.y; x3 = nx;
                }
                *(uint32_t*)(dh + i0)               = pack_h2(x0, x1);
                *(uint32_t*)(dh + i0 + 32)          = pack_h2(y0, y1);
                *(uint32_t*)(dh + 8 * HD + i0)      = pack_h2(x2, x3);
                *(uint32_t*)(dh + 8 * HD + i0 + 32) = pack_h2(y2, y3);
            }
        }
    }
}

// ---------------------------------------------------------------------------
// Flash attention, single-pass fp16 mma, fp32 accumulate + fp32 softmax.
// CTA: 64 q-rows, 4 warps (m16 each). KV tiles of 64 keys, double-buffered.
// 3 CTAs/SM. Heavy (long) blocks launch first.
// ---------------------------------------------------------------------------
#define A_LDSB  144                      // 72 halves per row
#define A_TILE  (64 * A_LDSB)            // 9216 B
#define A_STAGE (2 * A_TILE)             // K + V = 18432 B
#define ATTN_SMEM (2 * A_STAGE)          // 36864 B; x3 CTAs = 110 KB
#define AT_KH 0
#define AT_VH A_TILE

__global__ void __launch_bounds__(128, 3)
attn_f16_kernel()
{
    extern __shared__ char smem[];
    const uint32_t sb = smem_to_u32(smem);

    const int tid  = threadIdx.x;
    const int lane = tid & 31;
    const int wid  = tid >> 5;
    const int bx   = (int)gridDim.x - 1 - (int)blockIdx.x;   // heavy first
    const int q0   = bx * 64;
    const int hq   = blockIdx.y;
    const int b    = blockIdx.z;
    const int kvh  = hq >> 2;
    const int r    = lane >> 2;
    const int c2   = (lane & 3) * 2;

    // Q fragments (m16n8k16 A layout), direct from gmem
    const size_t qoff = ((size_t)(b * NH + hq) * SEQ + q0 + wid * 16 + r) * HD;
    const __half* qh0 = g_qh + qoff;
    const __half* qh1 = qh0 + 8 * HD;
    uint32_t qf[4][4];
#pragma unroll
    for (int ks = 0; ks < 4; ks++) {
        qf[ks][0] = *(const uint32_t*)(qh0 + ks * 16 + c2);
        qf[ks][1] = *(const uint32_t*)(qh1 + ks * 16 + c2);
        qf[ks][2] = *(const uint32_t*)(qh0 + ks * 16 + c2 + 8);
        qf[ks][3] = *(const uint32_t*)(qh1 + ks * 16 + c2 + 8);
    }

    const __half* kg = g_kh + (size_t)(b * NKV + kvh) * SEQ * HD;
    const __half* vg = g_vh + (size_t)(b * NKV + kvh) * SEQ * HD;

    auto load_stage = [&](int st, int kt) {
        uint32_t base = sb + st * A_STAGE;
#pragma unroll
        for (int i = 0; i < 4; i++) {
            int lin = tid + i * 128;
            int row = lin >> 3;
            int c   = lin & 7;
            uint32_t sofs = (uint32_t)(row * A_LDSB + c * 16);
            size_t gofs   = (size_t)(kt + row) * HD + c * 8;
            cp_async16(base + AT_KH + sofs, kg + gofs);
            cp_async16(base + AT_VH + sofs, vg + gofs);
        }
        cp_commit();
    };

    const int iters = bx + 1;
    load_stage(0, 0);

    float o[8][4];
#pragma unroll
    for (int j = 0; j < 8; j++)
#pragma unroll
        for (int t = 0; t < 4; t++) o[j][t] = 0.f;
    float m0 = -1e30f, m1 = -1e30f, l0 = 0.f, l1 = 0.f;

    const uint32_t kcore = (uint32_t)(((lane & 7) + ((lane >> 4) << 3)) * A_LDSB
                                      + ((lane >> 3) & 1) * 16);
    const uint32_t vcore = (uint32_t)((lane & 15) * A_LDSB + ((lane >> 4) << 4));

    for (int it = 0; it < iters; ++it) {
        const int kt = it * 64;
        cp_wait0();
        __syncthreads();
        if (it + 1 < iters) load_stage((it + 1) & 1, (it + 1) * 64);

        const uint32_t base = sb + (it & 1) * A_STAGE;

        // ---- S = Q K^T (single fp16 pass)
        float s[8][4];
#pragma unroll
        for (int j = 0; j < 8; j++)
#pragma unroll
            for (int t = 0; t < 4; t++) s[j][t] = 0.f;

#pragma unroll
        for (int kk = 0; kk < 4; kk++) {
#pragma unroll
            for (int np = 0; np < 4; np++) {
                uint32_t kb[4];
                ldsm_x4(kb[0], kb[1], kb[2], kb[3],
                        base + AT_KH + kcore + np * 16 * A_LDSB + kk * 32);
                int j0 = 2 * np, j1 = 2 * np + 1;
                mma_f16(s[j0][0], s[j0][1], s[j0][2], s[j0][3],
                        qf[kk][0], qf[kk][1], qf[kk][2], qf[kk][3], kb[0], kb[1]);
                mma_f16(s[j1][0], s[j1][1], s[j1][2], s[j1][3],
                        qf[kk][0], qf[kk][1], qf[kk][2], qf[kk][3], kb[2], kb[3]);
            }
        }

#pragma unroll
        for (int j = 0; j < 8; j++)
#pragma unroll
            for (int t = 0; t < 4; t++) s[j][t] *= ATTN_SCALE;

        if (kt == q0) {
            int row0 = q0 + wid * 16 + r;
#pragma unroll
            for (int j = 0; j < 8; j++) {
                int col = kt + j * 8 + c2;
                if (col > row0)     s[j][0] = -1e30f;
                if (col + 1 > row0) s[j][1] = -1e30f;
                if (col > row0 + 8)     s[j][2] = -1e30f;
                if (col + 1 > row0 + 8) s[j][3] = -1e30f;
            }
        }

        // ---- online softmax
        float mx0 = -1e30f, mx1 = -1e30f;
#pragma unroll
        for (int j = 0; j < 8; j++) {
            mx0 = fmaxf(mx0, fmaxf(s[j][0], s[j][1]));
            mx1 = fmaxf(mx1, fmaxf(s[j][2], s[j][3]));
        }
        mx0 = fmaxf(mx0, __shfl_xor_sync(0xffffffffu, mx0, 1));
        mx0 = fmaxf(mx0, __shfl_xor_sync(0xffffffffu, mx0, 2));
        mx1 = fmaxf(mx1, __shfl_xor_sync(0xffffffffu, mx1, 1));
        mx1 = fmaxf(mx1, __shfl_xor_sync(0xffffffffu, mx1, 2));

        float mn0 = fmaxf(m0, mx0), mn1 = fmaxf(m1, mx1);
        float corr0 = __expf(m0 - mn0), corr1 = __expf(m1 - mn1);
        l0 *= corr0; l1 *= corr1;
#pragma unroll
        for (int j = 0; j < 8; j++) {
            o[j][0] *= corr0; o[j][1] *= corr0;
            o[j][2] *= corr1; o[j][3] *= corr1;
        }
#pragma unroll
        for (int j = 0; j < 8; j++) {
            float p0 = __expf(s[j][0] - mn0);
            float p1 = __expf(s[j][1] - mn0);
            float p2 = __expf(s[j][2] - mn1);
            float p3 = __expf(s[j][3] - mn1);
            l0 += p0 + p1; l1 += p2 + p3;
            s[j][0] = p0; s[j][1] = p1; s[j][2] = p2; s[j][3] = p3;
        }
        m0 = mn0; m1 = mn1;

        // ---- O += P V (fp16). P A-fragments from S registers (FA2 identity)
#pragma unroll
        for (int kk = 0; kk < 4; kk++) {
            uint32_t pa[4];
            pa[0] = pack_h2(s[2*kk][0],   s[2*kk][1]);
            pa[1] = pack_h2(s[2*kk][2],   s[2*kk][3]);
            pa[2] = pack_h2(s[2*kk+1][0], s[2*kk+1][1]);
            pa[3] = pack_h2(s[2*kk+1][2], s[2*kk+1][3]);
#pragma unroll
            for (int np = 0; np < 4; np++) {
                uint32_t vb[4];
                ldsm_x4_trans(vb[0], vb[1], vb[2], vb[3],
                              base + AT_VH + vcore + kk * 16 * A_LDSB + np * 32);
                int j0 = 2 * np, j1 = 2 * np + 1;
                mma_f16(o[j0][0], o[j0][1], o[j0][2], o[j0][3],
                        pa[0], pa[1], pa[2], pa[3], vb[0], vb[1]);
                mma_f16(o[j1][0], o[j1][1], o[j1][2], o[j1][3],
                        pa[0], pa[1], pa[2], pa[3], vb[2], vb[3]);
            }
        }
    }

    l0 += __shfl_xor_sync(0xffffffffu, l0, 1);
    l0 += __shfl_xor_sync(0xffffffffu, l0, 2);
    l1 += __shfl_xor_sync(0xffffffffu, l1, 1);
    l1 += __shfl_xor_sync(0xffffffffu, l1, 2);
    float inv0 = 1.f / l0, inv1 = 1.f / l1;

    size_t row0 = (size_t)(b * SEQ + q0 + wid * 16 + r);
    size_t row1 = row0 + 8;
#pragma unroll
    for (int j = 0; j < 8; j++) {
        int col = hq * HD + j * 8 + c2;
        *(uint32_t*)&g_ah[row0 * QPOS + col] = pack_h2(o[j][0] * inv0, o[j][1] * inv0);
        *(uint32_t*)&g_ah[row1 * QPOS + col] = pack_h2(o[j][2] * inv1, o[j][3] * inv1);
    }
}

// ---------------------------------------------------------------------------
// kernel_launch
// ---------------------------------------------------------------------------
extern "C" void kernel_launch(void* const* d_in, const int* in_sizes, int n_in,
                              void* d_out, int out_size)
{
    const float* x    = (const float*)d_in[0];
    const float* Wqkv = (const float*)d_in[1];
    const float* Wo   = (const float*)d_in[2];
    float* out        = (float*)d_out;

    __half *xh, *wqh, *woh, *ah;
    cudaGetSymbolAddress((void**)&xh,  g_x);
    cudaGetSymbolAddress((void**)&wqh, g_wq);
    cudaGetSymbolAddress((void**)&woh, g_wo);
    cudaGetSymbolAddress((void**)&ah,  g_ah);

    cudaFuncSetAttribute(gemm_f16_kernel<0>,
                         cudaFuncAttributeMaxDynamicSharedMemorySize, GEMM_SMEM);
    cudaFuncSetAttribute(gemm_f16_kernel<1>,
                         cudaFuncAttributeMaxDynamicSharedMemorySize, GEMM_SMEM);
    cudaFuncSetAttribute(attn_f16_kernel,
                         cudaFuncAttributeMaxDynamicSharedMemorySize, ATTN_SMEM);

    // 1) fp16 conversion + rope table
    {
        int n4 = (MTOT * DMODEL) / 4;
        to_half_kernel<<<(n4 + 255) / 256, 256>>>(x, xh, n4);
    }
    {
        int n4 = (OPS * DMODEL) / 4;
        to_half_kernel<<<(n4 + 255) / 256, 256>>>(Wqkv, wqh, n4);
    }
    {
        int n4 = (DMODEL * DMODEL) / 4;
        to_half_kernel<<<(n4 + 255) / 256, 256>>>(Wo, woh, n4);
    }
    {
        int n = SEQ * 32;
        rope_table_kernel<<<(n + 255) / 256, 256>>>();
    }

    // 2) QKV projection (fp16 single-pass) with fused rope/round/relayout
    {
        dim3 grid(OPS / 128, MTOT / 128);
        gemm_f16_kernel<1><<<grid, 128, GEMM_SMEM>>>(xh, wqh, nullptr, OPS, DMODEL);
    }

    // 3) Flash attention (fp16 single-pass)
    {
        dim3 grid(SEQ / 64, NH, BATCH);
        attn_f16_kernel<<<grid, 128, ATTN_SMEM>>>();
    }

    // 4) O-projection (fp16 single-pass)
    {
        dim3 grid(DMODEL / 128, MTOT / 128);
        gemm_f16_kernel<0><<<grid, 128, GEMM_SMEM>>>(ah, woh, out, DMODEL, DMODEL);
    }
}